// round 1
// baseline (speedup 1.0000x reference)
#include <cuda_runtime.h>
#include <math.h>

// ---------------------------------------------------------------------------
// Problem constants
// ---------------------------------------------------------------------------
#define BATCH   2
#define SEQ     2048
#define DMODEL  1024
#define NHEADS  16
#define HEADDIM 64
#define DFF     4096
#define TOKENS  (BATCH * SEQ)          // 4096

// ---------------------------------------------------------------------------
// Scratch (static device allocations; no cudaMalloc allowed)
// ---------------------------------------------------------------------------
__device__ float g_q[TOKENS * DMODEL];
__device__ float g_k[TOKENS * DMODEL];
__device__ float g_v[TOKENS * DMODEL];
__device__ float g_logits[(size_t)BATCH * NHEADS * SEQ * SEQ]; // 512 MB
__device__ float g_ctx[TOKENS * DMODEL];
__device__ float g_attnout[TOKENS * DMODEL];
__device__ float g_h1[TOKENS * DMODEL];
__device__ float g_ff1[TOKENS * DFF];
__device__ float g_ff2[TOKENS * DMODEL];

// ---------------------------------------------------------------------------
// Generic register-blocked SGEMM.
// C[M,N] = alpha * A @ B (+bias) (optional B transposed: B is [N,K]),
// optional exact GELU epilogue. Batched with two-level batch index:
// z -> (zo = z / Hmod, zi = z % Hmod); base += zo*s?_o + zi*s?_i.
// 256 threads (16x16), thread computes TM x TN outputs.
// Assumes M%BM==0, N%BN==0, K%BK==0, BK%4==0, lda/ldb/ldc %4==0.
// ---------------------------------------------------------------------------
template<int BM, int BN, int BK, int TM, int TN, bool TRANSB, bool GELU>
__global__ __launch_bounds__(256)
void sgemm_kernel(int M, int N, int K,
                  const float* __restrict__ A, int lda,
                  const float* __restrict__ B, int ldb,
                  float* __restrict__ C, int ldc,
                  const float* __restrict__ bias,
                  float alpha,
                  int Hmod,
                  long long sA_o, long long sA_i,
                  long long sB_o, long long sB_i,
                  long long sC_o, long long sC_i)
{
    const int z  = blockIdx.z;
    const int zo = z / Hmod;
    const int zi = z % Hmod;
    A += (size_t)zo * sA_o + (size_t)zi * sA_i;
    B += (size_t)zo * sB_o + (size_t)zi * sB_i;
    C += (size_t)zo * sC_o + (size_t)zi * sC_i;

    const int tid = threadIdx.x;
    const int tx  = tid % 16;
    const int ty  = tid / 16;

    __shared__ float As[BM * BK];
    __shared__ float Bs[BK * BN];

    const int m0 = blockIdx.y * BM;
    const int n0 = blockIdx.x * BN;

    float acc[TM][TN];
#pragma unroll
    for (int i = 0; i < TM; i++)
#pragma unroll
        for (int j = 0; j < TN; j++) acc[i][j] = 0.0f;

    constexpr int A_LD4 = (BM * BK) / (256 * 4);
    constexpr int B_LD4 = (BK * BN) / (256 * 4);
    static_assert(A_LD4 >= 1 && B_LD4 >= 1, "tile too small");

    for (int k0 = 0; k0 < K; k0 += BK) {
        // --- load A tile (row-major [M,K]) ---
#pragma unroll
        for (int l = 0; l < A_LD4; l++) {
            int flat = (tid + l * 256) * 4;
            int m  = flat / BK;
            int kk = flat % BK;
            float4 v4 = *(const float4*)(A + (size_t)(m0 + m) * lda + k0 + kk);
            *(float4*)(As + m * BK + kk) = v4;
        }
        // --- load B tile ---
        if (!TRANSB) {
#pragma unroll
            for (int l = 0; l < B_LD4; l++) {
                int flat = (tid + l * 256) * 4;
                int kk = flat / BN;
                int n  = flat % BN;
                float4 v4 = *(const float4*)(B + (size_t)(k0 + kk) * ldb + n0 + n);
                *(float4*)(Bs + kk * BN + n) = v4;
            }
        } else {
#pragma unroll
            for (int l = 0; l < B_LD4; l++) {
                int flat = (tid + l * 256) * 4;
                int n  = flat / BK;
                int kk = flat % BK;
                float4 v4 = *(const float4*)(B + (size_t)(n0 + n) * ldb + k0 + kk);
                Bs[(kk + 0) * BN + n] = v4.x;
                Bs[(kk + 1) * BN + n] = v4.y;
                Bs[(kk + 2) * BN + n] = v4.z;
                Bs[(kk + 3) * BN + n] = v4.w;
            }
        }
        __syncthreads();

#pragma unroll
        for (int kk = 0; kk < BK; kk++) {
            float af[TM], bf[TN];
#pragma unroll
            for (int i = 0; i < TM; i++) af[i] = As[(ty * TM + i) * BK + kk];
#pragma unroll
            for (int j = 0; j < TN; j += 4) {
                float4 b4 = *(const float4*)(Bs + kk * BN + tx * TN + j);
                bf[j + 0] = b4.x; bf[j + 1] = b4.y; bf[j + 2] = b4.z; bf[j + 3] = b4.w;
            }
#pragma unroll
            for (int i = 0; i < TM; i++)
#pragma unroll
                for (int j = 0; j < TN; j++)
                    acc[i][j] = fmaf(af[i], bf[j], acc[i][j]);
        }
        __syncthreads();
    }

    // --- epilogue ---
#pragma unroll
    for (int i = 0; i < TM; i++) {
        size_t row = (size_t)(m0 + ty * TM + i) * ldc + n0 + tx * TN;
#pragma unroll
        for (int j = 0; j < TN; j += 4) {
            float4 o;
            float* op = &o.x;
#pragma unroll
            for (int e = 0; e < 4; e++) {
                float v = acc[i][j + e] * alpha;
                if (bias) v += bias[n0 + tx * TN + j + e];
                if (GELU) v = 0.5f * v * (1.0f + erff(v * 0.7071067811865475f));
                op[e] = v;
            }
            *(float4*)(C + row + j) = o;
        }
    }
}

// ---------------------------------------------------------------------------
// RoPE (interleaved pairs), in place on x laid out [B,S,H,HD]
// ---------------------------------------------------------------------------
__global__ void rope_kernel(float* __restrict__ x, const float* __restrict__ tau,
                            int n_pairs)
{
    int idx = blockIdx.x * 256 + threadIdx.x;
    if (idx >= n_pairs) return;
    int bs = idx >> 9;          // / (DMODEL/2)
    int r  = idx & 511;
    int j  = r & 31;            // freq index within head
    int h  = r >> 5;
    size_t off = ((size_t)bs << 10) + h * HEADDIM + 2 * j;
    float t   = tau[bs];
    float inv = expf(-0.28782313662425572f * (float)j); // ln(10000)/32
    float s, c;
    sincosf(t * inv, &s, &c);
    float x0 = x[off], x1 = x[off + 1];
    x[off]     = x0 * c - x1 * s;
    x[off + 1] = x1 * c + x0 * s;
}

// ---------------------------------------------------------------------------
// Row softmax over `cols` contiguous elements, in place.  one block per row.
// ---------------------------------------------------------------------------
__global__ __launch_bounds__(256)
void softmax_kernel(float* __restrict__ x, int cols)
{
    size_t row = blockIdx.x;
    float* p = x + row * (size_t)cols;
    int tid = threadIdx.x;
    __shared__ float red[256];

    float lm = -INFINITY;
    for (int c = tid; c < cols; c += 256) lm = fmaxf(lm, p[c]);
    red[tid] = lm;
    __syncthreads();
    for (int s = 128; s > 0; s >>= 1) {
        if (tid < s) red[tid] = fmaxf(red[tid], red[tid + s]);
        __syncthreads();
    }
    float m = red[0];
    __syncthreads();

    float ls = 0.0f;
    for (int c = tid; c < cols; c += 256) {
        float e = expf(p[c] - m);
        p[c] = e;
        ls += e;
    }
    red[tid] = ls;
    __syncthreads();
    for (int s = 128; s > 0; s >>= 1) {
        if (tid < s) red[tid] += red[tid + s];
        __syncthreads();
    }
    float inv = 1.0f / red[0];
    for (int c = tid; c < cols; c += 256) p[c] *= inv;
}

// ---------------------------------------------------------------------------
// Fused residual + LayerNorm: out = LN(a + b) * g + be.  D = 1024 fixed.
// one block (256 thr) per row; 4 elems/thread.
// ---------------------------------------------------------------------------
__global__ __launch_bounds__(256)
void ln_kernel(const float* __restrict__ a, const float* __restrict__ b,
               const float* __restrict__ g, const float* __restrict__ be,
               float* __restrict__ out)
{
    const int D = DMODEL;
    size_t row = blockIdx.x;
    const float* pa = a + row * D;
    const float* pb = b + row * D;
    int tid = threadIdx.x;
    __shared__ float red[256];

    float x[4];
    float s = 0.0f;
#pragma unroll
    for (int i = 0; i < 4; i++) {
        int c = tid + i * 256;
        x[i] = pa[c] + pb[c];
        s += x[i];
    }
    red[tid] = s;
    __syncthreads();
    for (int t = 128; t > 0; t >>= 1) {
        if (tid < t) red[tid] += red[tid + t];
        __syncthreads();
    }
    float mu = red[0] * (1.0f / D);
    __syncthreads();

    float v = 0.0f;
#pragma unroll
    for (int i = 0; i < 4; i++) {
        float d = x[i] - mu;
        v += d * d;
    }
    red[tid] = v;
    __syncthreads();
    for (int t = 128; t > 0; t >>= 1) {
        if (tid < t) red[tid] += red[tid + t];
        __syncthreads();
    }
    float var = red[0] * (1.0f / D);
    float r = rsqrtf(var + 1e-5f);
#pragma unroll
    for (int i = 0; i < 4; i++) {
        int c = tid + i * 256;
        out[row * D + c] = (x[i] - mu) * r * g[c] + be[c];
    }
}

// ---------------------------------------------------------------------------
// Host-side launch
// ---------------------------------------------------------------------------
static float* symptr(const void* sym)
{
    void* p = nullptr;
    cudaGetSymbolAddress(&p, sym);
    return (float*)p;
}

extern "C" void kernel_launch(void* const* d_in, const int* in_sizes, int n_in,
                              void* d_out, int out_size)
{
    const float* src = (const float*)d_in[0];
    const float* tau = (const float*)d_in[1];
    const float* Wq  = (const float*)d_in[2];
    const float* bq  = (const float*)d_in[3];
    const float* Wk  = (const float*)d_in[4];
    const float* bk  = (const float*)d_in[5];
    const float* Wv  = (const float*)d_in[6];
    const float* bv  = (const float*)d_in[7];
    const float* Wo  = (const float*)d_in[8];
    const float* bo  = (const float*)d_in[9];
    const float* W1  = (const float*)d_in[10];
    const float* b1  = (const float*)d_in[11];
    const float* W2  = (const float*)d_in[12];
    const float* b2  = (const float*)d_in[13];
    const float* g1  = (const float*)d_in[14];
    const float* be1 = (const float*)d_in[15];
    const float* g2  = (const float*)d_in[16];
    const float* be2 = (const float*)d_in[17];
    float* out = (float*)d_out;

    float* q   = symptr(g_q);
    float* k   = symptr(g_k);
    float* v   = symptr(g_v);
    float* lg  = symptr(g_logits);
    float* ctx = symptr(g_ctx);
    float* ao  = symptr(g_attnout);
    float* h1  = symptr(g_h1);
    float* f1  = symptr(g_ff1);
    float* f2  = symptr(g_ff2);

    // ---- QKV projections: [4096,1024] @ [1024,1024] ----
    {
        dim3 grid(DMODEL / 128, TOKENS / 128, 1);
        sgemm_kernel<128,128,8,8,8,false,false><<<grid, 256>>>(
            TOKENS, DMODEL, DMODEL, src, DMODEL, Wq, DMODEL, q, DMODEL,
            bq, 1.0f, 1, 0,0, 0,0, 0,0);
        sgemm_kernel<128,128,8,8,8,false,false><<<grid, 256>>>(
            TOKENS, DMODEL, DMODEL, src, DMODEL, Wk, DMODEL, k, DMODEL,
            bk, 1.0f, 1, 0,0, 0,0, 0,0);
        sgemm_kernel<128,128,8,8,8,false,false><<<grid, 256>>>(
            TOKENS, DMODEL, DMODEL, src, DMODEL, Wv, DMODEL, v, DMODEL,
            bv, 1.0f, 1, 0,0, 0,0, 0,0);
    }

    // ---- RoPE on q and k ----
    {
        int n_pairs = TOKENS * DMODEL / 2;  // 2,097,152
        int blocks = (n_pairs + 255) / 256;
        rope_kernel<<<blocks, 256>>>(q, tau, n_pairs);
        rope_kernel<<<blocks, 256>>>(k, tau, n_pairs);
    }

    // ---- logits = q @ k^T / sqrt(64)  (batched over B*H = 32) ----
    {
        dim3 grid(SEQ / 128, SEQ / 128, BATCH * NHEADS);
        long long sSD = (long long)SEQ * DMODEL;
        long long sSS = (long long)SEQ * SEQ;
        sgemm_kernel<128,128,8,8,8,true,false><<<grid, 256>>>(
            SEQ, SEQ, HEADDIM,
            q, DMODEL, k, DMODEL, lg, SEQ,
            nullptr, 0.125f,
            NHEADS, sSD, HEADDIM, sSD, HEADDIM, NHEADS * sSS, sSS);
    }

    // ---- softmax rows ----
    softmax_kernel<<<BATCH * NHEADS * SEQ, 256>>>(lg, SEQ);

    // ---- ctx = attn @ v  (batched, N=64) ----
    {
        dim3 grid(1, SEQ / 128, BATCH * NHEADS);
        long long sSD = (long long)SEQ * DMODEL;
        long long sSS = (long long)SEQ * SEQ;
        sgemm_kernel<128,64,16,8,4,false,false><<<grid, 256>>>(
            SEQ, HEADDIM, SEQ,
            lg, SEQ, v, DMODEL, ctx, DMODEL,
            nullptr, 1.0f,
            NHEADS, NHEADS * sSS, sSS, sSD, HEADDIM, sSD, HEADDIM);
    }

    // ---- output projection ----
    {
        dim3 grid(DMODEL / 128, TOKENS / 128, 1);
        sgemm_kernel<128,128,8,8,8,false,false><<<grid, 256>>>(
            TOKENS, DMODEL, DMODEL, ctx, DMODEL, Wo, DMODEL, ao, DMODEL,
            bo, 1.0f, 1, 0,0, 0,0, 0,0);
    }

    // ---- LN1: h1 = LN(src + attnout) ----
    ln_kernel<<<TOKENS, 256>>>(src, ao, g1, be1, h1);

    // ---- FFN: f1 = gelu(h1 @ W1 + b1) ----
    {
        dim3 grid(DFF / 128, TOKENS / 128, 1);
        sgemm_kernel<128,128,8,8,8,false,true><<<grid, 256>>>(
            TOKENS, DFF, DMODEL, h1, DMODEL, W1, DFF, f1, DFF,
            b1, 1.0f, 1, 0,0, 0,0, 0,0);
    }
    // ---- f2 = f1 @ W2 + b2 ----
    {
        dim3 grid(DMODEL / 128, TOKENS / 128, 1);
        sgemm_kernel<128,128,8,8,8,false,false><<<grid, 256>>>(
            TOKENS, DMODEL, DFF, f1, DFF, W2, DMODEL, f2, DMODEL,
            b2, 1.0f, 1, 0,0, 0,0, 0,0);
    }

    // ---- LN2 -> out ----
    ln_kernel<<<TOKENS, 256>>>(h1, f2, g2, be2, out);

    (void)in_sizes; (void)n_in; (void)out_size;
}

// round 2
// speedup vs baseline: 2.5714x; 2.5714x over previous
#include <cuda_runtime.h>
#include <math.h>
#include <cstdint>

// ---------------------------------------------------------------------------
// Problem constants
// ---------------------------------------------------------------------------
#define BATCH   2
#define SEQ     2048
#define DMODEL  1024
#define NHEADS  16
#define HEADDIM 64
#define DFF     4096
#define TOKENS  (BATCH * SEQ)          // 4096

// ---------------------------------------------------------------------------
// Scratch (static device allocations; no cudaMalloc allowed)
// ---------------------------------------------------------------------------
__device__ float g_q[TOKENS * DMODEL];
__device__ float g_k[TOKENS * DMODEL];
__device__ float g_v[TOKENS * DMODEL];
__device__ float g_logits[(size_t)BATCH * NHEADS * SEQ * SEQ]; // 512 MB
__device__ float g_ctx[TOKENS * DMODEL];
__device__ float g_attnout[TOKENS * DMODEL];
__device__ float g_h1[TOKENS * DMODEL];
__device__ float g_ff1[TOKENS * DFF];
__device__ float g_ff2[TOKENS * DMODEL];

// ---------------------------------------------------------------------------
// PTX helpers
// ---------------------------------------------------------------------------
__device__ __forceinline__ uint32_t smem_u32(const void* p) {
    return (uint32_t)__cvta_generic_to_shared(p);
}
__device__ __forceinline__ void cp16(uint32_t s, const void* g) {
    asm volatile("cp.async.cg.shared.global [%0], [%1], 16;" :: "r"(s), "l"(g));
}
__device__ __forceinline__ void cp_commit() {
    asm volatile("cp.async.commit_group;");
}
__device__ __forceinline__ void cp_wait0() {
    asm volatile("cp.async.wait_group 0;");
}
__device__ __forceinline__ uint32_t f2tf32(float x) {
    uint32_t r;
    asm("cvt.rna.tf32.f32 %0, %1;" : "=r"(r) : "f"(x));
    return r;
}
__device__ __forceinline__ void mma_tf32(float* c, const uint32_t* a, const uint32_t* b) {
    asm volatile(
        "mma.sync.aligned.m16n8k8.row.col.f32.tf32.tf32.f32 "
        "{%0,%1,%2,%3}, {%4,%5,%6,%7}, {%8,%9}, {%0,%1,%2,%3};"
        : "+f"(c[0]), "+f"(c[1]), "+f"(c[2]), "+f"(c[3])
        : "r"(a[0]), "r"(a[1]), "r"(a[2]), "r"(a[3]), "r"(b[0]), "r"(b[1]));
}

// ---------------------------------------------------------------------------
// TF32 tensor-core GEMM.
// C[M,N] = alpha * A @ B (+bias) (TRANSB: B is [N,K]), optional exact GELU.
// Batched: z -> (zo = z/Hmod, zi = z%Hmod); base += zo*s?_o + zi*s?_i.
// 256 threads, 8 warps. BK = 16, double-buffered cp.async.
// Requires M%BM==0, N%BN==0, K%16==0, lda/ldb/ldc%4==0, 16B-aligned bases.
// ---------------------------------------------------------------------------
template<int BM, int BN, int WARPS_M, int WARPS_N, bool TRANSB, bool GELU>
__global__ __launch_bounds__(256)
void mm_tf32_kernel(int M, int N, int K,
                    const float* __restrict__ A, int lda,
                    const float* __restrict__ B, int ldb,
                    float* __restrict__ C, int ldc,
                    const float* __restrict__ bias,
                    float alpha,
                    int Hmod,
                    long long sA_o, long long sA_i,
                    long long sB_o, long long sB_i,
                    long long sC_o, long long sC_i)
{
    constexpr int BK = 16;
    constexpr int WM = BM / WARPS_M;         // warp tile M
    constexpr int WN = BN / WARPS_N;         // warp tile N
    constexpr int MT = WM / 16;              // mma tiles in M per warp
    constexpr int NT = WN / 8;               // mma tiles in N per warp
    constexpr int AS_STRIDE = BK + 4;        // 20 -> conflict-free frag loads
    constexpr int BS_STRIDE = TRANSB ? (BK + 4) : (BN + 8);
    constexpr int AS_ELEMS  = BM * AS_STRIDE;
    constexpr int BS_ELEMS  = TRANSB ? BN * BS_STRIDE : BK * BS_STRIDE;

    __shared__ float As[2][AS_ELEMS];
    __shared__ float Bs[2][BS_ELEMS];

    const int z  = blockIdx.z;
    const int zo = z / Hmod;
    const int zi = z % Hmod;
    A += (size_t)zo * sA_o + (size_t)zi * sA_i;
    B += (size_t)zo * sB_o + (size_t)zi * sB_i;
    C += (size_t)zo * sC_o + (size_t)zi * sC_i;

    const int tid  = threadIdx.x;
    const int lane = tid & 31;
    const int warp = tid >> 5;
    const int grp  = lane >> 2;   // 0..7
    const int tig  = lane & 3;    // 0..3
    const int wm0  = (warp / WARPS_N) * WM;
    const int wn0  = (warp % WARPS_N) * WN;

    const int m0 = blockIdx.y * BM;
    const int n0 = blockIdx.x * BN;

    float acc[MT][NT][4];
#pragma unroll
    for (int mi = 0; mi < MT; mi++)
#pragma unroll
        for (int ni = 0; ni < NT; ni++)
#pragma unroll
            for (int e = 0; e < 4; e++) acc[mi][ni][e] = 0.0f;

    // ---- stage loaders (all direct row copies, 16B chunks) ----
    auto load_stage = [&](int k0, int buf) {
        // A tile: BM rows x 16 floats
#pragma unroll 2
        for (int c = tid; c < BM * 4; c += 256) {
            int m = c >> 2, kq = c & 3;
            cp16(smem_u32(&As[buf][m * AS_STRIDE + kq * 4]),
                 A + (size_t)(m0 + m) * lda + k0 + kq * 4);
        }
        if (TRANSB) {
            // B tile: BN rows x 16 floats (row-direct, [n][k])
#pragma unroll 2
            for (int c = tid; c < BN * 4; c += 256) {
                int n = c >> 2, kq = c & 3;
                cp16(smem_u32(&Bs[buf][n * BS_STRIDE + kq * 4]),
                     B + (size_t)(n0 + n) * ldb + k0 + kq * 4);
            }
        } else {
            // B tile: 16 rows x BN floats ([k][n])
#pragma unroll 2
            for (int c = tid; c < BK * (BN / 4); c += 256) {
                int kk = c / (BN / 4), nq = c % (BN / 4);
                cp16(smem_u32(&Bs[buf][kk * BS_STRIDE + nq * 4]),
                     B + (size_t)(k0 + kk) * ldb + n0 + nq * 4);
            }
        }
        cp_commit();
    };

    auto compute_stage = [&](int buf) {
        const float* as = As[buf];
        const float* bs = Bs[buf];
#pragma unroll
        for (int kk = 0; kk < BK; kk += 8) {
            uint32_t af[MT][4], bf[NT][2];
#pragma unroll
            for (int mi = 0; mi < MT; mi++) {
                int r = wm0 + mi * 16 + grp;
                int c = kk + tig;
                af[mi][0] = f2tf32(as[(r    ) * AS_STRIDE + c    ]);
                af[mi][1] = f2tf32(as[(r + 8) * AS_STRIDE + c    ]);
                af[mi][2] = f2tf32(as[(r    ) * AS_STRIDE + c + 4]);
                af[mi][3] = f2tf32(as[(r + 8) * AS_STRIDE + c + 4]);
            }
#pragma unroll
            for (int ni = 0; ni < NT; ni++) {
                int n = wn0 + ni * 8 + grp;
                if (TRANSB) {
                    bf[ni][0] = f2tf32(bs[n * BS_STRIDE + kk + tig    ]);
                    bf[ni][1] = f2tf32(bs[n * BS_STRIDE + kk + tig + 4]);
                } else {
                    bf[ni][0] = f2tf32(bs[(kk + tig    ) * BS_STRIDE + n]);
                    bf[ni][1] = f2tf32(bs[(kk + tig + 4) * BS_STRIDE + n]);
                }
            }
#pragma unroll
            for (int mi = 0; mi < MT; mi++)
#pragma unroll
                for (int ni = 0; ni < NT; ni++)
                    mma_tf32(acc[mi][ni], af[mi], bf[ni]);
        }
    };

    // ---- pipelined main loop ----
    const int nstages = K / BK;
    load_stage(0, 0);
    for (int s = 0; s < nstages; s++) {
        cp_wait0();
        __syncthreads();
        if (s + 1 < nstages) load_stage((s + 1) * BK, (s + 1) & 1);
        compute_stage(s & 1);
        __syncthreads();
    }

    // ---- epilogue ----
#pragma unroll
    for (int mi = 0; mi < MT; mi++) {
#pragma unroll
        for (int ni = 0; ni < NT; ni++) {
#pragma unroll
            for (int h = 0; h < 2; h++) {
                int row = m0 + wm0 + mi * 16 + grp + h * 8;
                int col = n0 + wn0 + ni * 8 + 2 * tig;
                float v0 = acc[mi][ni][h * 2 + 0] * alpha;
                float v1 = acc[mi][ni][h * 2 + 1] * alpha;
                if (bias) { v0 += bias[col]; v1 += bias[col + 1]; }
                if (GELU) {
                    v0 = 0.5f * v0 * (1.0f + erff(v0 * 0.7071067811865475f));
                    v1 = 0.5f * v1 * (1.0f + erff(v1 * 0.7071067811865475f));
                }
                float2 o = make_float2(v0, v1);
                *(float2*)(C + (size_t)row * ldc + col) = o;
            }
        }
    }
}

// ---------------------------------------------------------------------------
// RoPE (interleaved pairs), in place on x laid out [B,S,H,HD]
// ---------------------------------------------------------------------------
__global__ void rope_kernel(float* __restrict__ x, const float* __restrict__ tau,
                            int n_pairs)
{
    int idx = blockIdx.x * 256 + threadIdx.x;
    if (idx >= n_pairs) return;
    int bs = idx >> 9;          // / (DMODEL/2)
    int r  = idx & 511;
    int j  = r & 31;            // freq index within head
    int h  = r >> 5;
    size_t off = ((size_t)bs << 10) + h * HEADDIM + 2 * j;
    float t   = tau[bs];
    float inv = expf(-0.28782313662425572f * (float)j); // ln(10000)/32
    float s, c;
    sincosf(t * inv, &s, &c);
    float x0 = x[off], x1 = x[off + 1];
    x[off]     = x0 * c - x1 * s;
    x[off + 1] = x1 * c + x0 * s;
}

// ---------------------------------------------------------------------------
// Row softmax over 2048 cols, in place; row cached in registers (2 passes
// over HBM instead of 5). one block (256 thr) per row.
// ---------------------------------------------------------------------------
__global__ __launch_bounds__(256)
void softmax_kernel(float* __restrict__ x)
{
    float* p = x + (size_t)blockIdx.x * SEQ;
    int tid = threadIdx.x;
    __shared__ float red[256];

    float v[8];
    float lm = -INFINITY;
#pragma unroll
    for (int i = 0; i < 8; i++) {
        v[i] = p[tid + i * 256];
        lm = fmaxf(lm, v[i]);
    }
    red[tid] = lm;
    __syncthreads();
    for (int s = 128; s > 0; s >>= 1) {
        if (tid < s) red[tid] = fmaxf(red[tid], red[tid + s]);
        __syncthreads();
    }
    float m = red[0];
    __syncthreads();

    float ls = 0.0f;
#pragma unroll
    for (int i = 0; i < 8; i++) {
        v[i] = __expf(v[i] - m);
        ls += v[i];
    }
    red[tid] = ls;
    __syncthreads();
    for (int s = 128; s > 0; s >>= 1) {
        if (tid < s) red[tid] += red[tid + s];
        __syncthreads();
    }
    float inv = 1.0f / red[0];
#pragma unroll
    for (int i = 0; i < 8; i++) p[tid + i * 256] = v[i] * inv;
}

// ---------------------------------------------------------------------------
// Fused residual + LayerNorm: out = LN(a + b) * g + be.  D = 1024 fixed.
// ---------------------------------------------------------------------------
__global__ __launch_bounds__(256)
void ln_kernel(const float* __restrict__ a, const float* __restrict__ b,
               const float* __restrict__ g, const float* __restrict__ be,
               float* __restrict__ out)
{
    const int D = DMODEL;
    size_t row = blockIdx.x;
    const float* pa = a + row * D;
    const float* pb = b + row * D;
    int tid = threadIdx.x;
    __shared__ float red[256];

    float x[4];
    float s = 0.0f;
#pragma unroll
    for (int i = 0; i < 4; i++) {
        int c = tid + i * 256;
        x[i] = pa[c] + pb[c];
        s += x[i];
    }
    red[tid] = s;
    __syncthreads();
    for (int t = 128; t > 0; t >>= 1) {
        if (tid < t) red[tid] += red[tid + t];
        __syncthreads();
    }
    float mu = red[0] * (1.0f / D);
    __syncthreads();

    float v = 0.0f;
#pragma unroll
    for (int i = 0; i < 4; i++) {
        float d = x[i] - mu;
        v += d * d;
    }
    red[tid] = v;
    __syncthreads();
    for (int t = 128; t > 0; t >>= 1) {
        if (tid < t) red[tid] += red[tid + t];
        __syncthreads();
    }
    float var = red[0] * (1.0f / D);
    float r = rsqrtf(var + 1e-5f);
#pragma unroll
    for (int i = 0; i < 4; i++) {
        int c = tid + i * 256;
        out[row * D + c] = (x[i] - mu) * r * g[c] + be[c];
    }
}

// ---------------------------------------------------------------------------
// Host-side launch
// ---------------------------------------------------------------------------
static float* symptr(const void* sym)
{
    void* p = nullptr;
    cudaGetSymbolAddress(&p, sym);
    return (float*)p;
}

extern "C" void kernel_launch(void* const* d_in, const int* in_sizes, int n_in,
                              void* d_out, int out_size)
{
    const float* src = (const float*)d_in[0];
    const float* tau = (const float*)d_in[1];
    const float* Wq  = (const float*)d_in[2];
    const float* bq  = (const float*)d_in[3];
    const float* Wk  = (const float*)d_in[4];
    const float* bk  = (const float*)d_in[5];
    const float* Wv  = (const float*)d_in[6];
    const float* bv  = (const float*)d_in[7];
    const float* Wo  = (const float*)d_in[8];
    const float* bo  = (const float*)d_in[9];
    const float* W1  = (const float*)d_in[10];
    const float* b1  = (const float*)d_in[11];
    const float* W2  = (const float*)d_in[12];
    const float* b2  = (const float*)d_in[13];
    const float* g1  = (const float*)d_in[14];
    const float* be1 = (const float*)d_in[15];
    const float* g2  = (const float*)d_in[16];
    const float* be2 = (const float*)d_in[17];
    float* out = (float*)d_out;

    float* q   = symptr(g_q);
    float* k   = symptr(g_k);
    float* v   = symptr(g_v);
    float* lg  = symptr(g_logits);
    float* ctx = symptr(g_ctx);
    float* ao  = symptr(g_attnout);
    float* h1  = symptr(g_h1);
    float* f1  = symptr(g_ff1);
    float* f2  = symptr(g_ff2);

    // ---- QKV projections: [4096,1024] @ [1024,1024] ----
    {
        dim3 grid(DMODEL / 128, TOKENS / 128, 1);
        mm_tf32_kernel<128,128,2,4,false,false><<<grid, 256>>>(
            TOKENS, DMODEL, DMODEL, src, DMODEL, Wq, DMODEL, q, DMODEL,
            bq, 1.0f, 1, 0,0, 0,0, 0,0);
        mm_tf32_kernel<128,128,2,4,false,false><<<grid, 256>>>(
            TOKENS, DMODEL, DMODEL, src, DMODEL, Wk, DMODEL, k, DMODEL,
            bk, 1.0f, 1, 0,0, 0,0, 0,0);
        mm_tf32_kernel<128,128,2,4,false,false><<<grid, 256>>>(
            TOKENS, DMODEL, DMODEL, src, DMODEL, Wv, DMODEL, v, DMODEL,
            bv, 1.0f, 1, 0,0, 0,0, 0,0);
    }

    // ---- RoPE on q and k ----
    {
        int n_pairs = TOKENS * DMODEL / 2;
        int blocks = (n_pairs + 255) / 256;
        rope_kernel<<<blocks, 256>>>(q, tau, n_pairs);
        rope_kernel<<<blocks, 256>>>(k, tau, n_pairs);
    }

    // ---- logits = q @ k^T / sqrt(64)  (batched over B*H = 32, TRANSB) ----
    {
        dim3 grid(SEQ / 128, SEQ / 128, BATCH * NHEADS);
        long long sSD = (long long)SEQ * DMODEL;
        long long sSS = (long long)SEQ * SEQ;
        mm_tf32_kernel<128,128,2,4,true,false><<<grid, 256>>>(
            SEQ, SEQ, HEADDIM,
            q, DMODEL, k, DMODEL, lg, SEQ,
            nullptr, 0.125f,
            NHEADS, sSD, HEADDIM, sSD, HEADDIM, NHEADS * sSS, sSS);
    }

    // ---- softmax rows ----
    softmax_kernel<<<BATCH * NHEADS * SEQ, 256>>>(lg);

    // ---- ctx = attn @ v  (batched, N=64) ----
    {
        dim3 grid(1, SEQ / 128, BATCH * NHEADS);
        long long sSD = (long long)SEQ * DMODEL;
        long long sSS = (long long)SEQ * SEQ;
        mm_tf32_kernel<128,64,4,2,false,false><<<grid, 256>>>(
            SEQ, HEADDIM, SEQ,
            lg, SEQ, v, DMODEL, ctx, DMODEL,
            nullptr, 1.0f,
            NHEADS, NHEADS * sSS, sSS, sSD, HEADDIM, sSD, HEADDIM);
    }

    // ---- output projection ----
    {
        dim3 grid(DMODEL / 128, TOKENS / 128, 1);
        mm_tf32_kernel<128,128,2,4,false,false><<<grid, 256>>>(
            TOKENS, DMODEL, DMODEL, ctx, DMODEL, Wo, DMODEL, ao, DMODEL,
            bo, 1.0f, 1, 0,0, 0,0, 0,0);
    }

    // ---- LN1: h1 = LN(src + attnout) ----
    ln_kernel<<<TOKENS, 256>>>(src, ao, g1, be1, h1);

    // ---- FFN: f1 = gelu(h1 @ W1 + b1) ----
    {
        dim3 grid(DFF / 128, TOKENS / 128, 1);
        mm_tf32_kernel<128,128,2,4,false,true><<<grid, 256>>>(
            TOKENS, DFF, DMODEL, h1, DMODEL, W1, DFF, f1, DFF,
            b1, 1.0f, 1, 0,0, 0,0, 0,0);
    }
    // ---- f2 = f1 @ W2 + b2 ----
    {
        dim3 grid(DMODEL / 128, TOKENS / 128, 1);
        mm_tf32_kernel<128,128,2,4,false,false><<<grid, 256>>>(
            TOKENS, DMODEL, DFF, f1, DFF, W2, DMODEL, f2, DMODEL,
            b2, 1.0f, 1, 0,0, 0,0, 0,0);
    }

    // ---- LN2 -> out ----
    ln_kernel<<<TOKENS, 256>>>(h1, f2, g2, be2, out);

    (void)in_sizes; (void)n_in; (void)out_size;
}

// round 3
// speedup vs baseline: 3.2433x; 1.2613x over previous
#include <cuda_runtime.h>
#include <math.h>
#include <cstdint>

// ---------------------------------------------------------------------------
// Problem constants
// ---------------------------------------------------------------------------
#define BATCH   2
#define SEQ     2048
#define DMODEL  1024
#define NHEADS  16
#define HEADDIM 64
#define DFF     4096
#define TOKENS  (BATCH * SEQ)          // 4096

// ---------------------------------------------------------------------------
// Scratch (static device allocations; no cudaMalloc allowed)
// ---------------------------------------------------------------------------
__device__ float g_q[TOKENS * DMODEL];
__device__ float g_k[TOKENS * DMODEL];
__device__ float g_v[TOKENS * DMODEL];
__device__ float g_ctx[TOKENS * DMODEL];
__device__ float g_attnout[TOKENS * DMODEL];
__device__ float g_h1[TOKENS * DMODEL];
__device__ float g_ff1[TOKENS * DFF];
__device__ float g_ff2[TOKENS * DMODEL];

// ---------------------------------------------------------------------------
// PTX helpers
// ---------------------------------------------------------------------------
__device__ __forceinline__ uint32_t smem_u32(const void* p) {
    return (uint32_t)__cvta_generic_to_shared(p);
}
__device__ __forceinline__ void cp16(uint32_t s, const void* g) {
    asm volatile("cp.async.cg.shared.global [%0], [%1], 16;" :: "r"(s), "l"(g));
}
__device__ __forceinline__ void cp_commit() {
    asm volatile("cp.async.commit_group;");
}
__device__ __forceinline__ void cp_wait0() {
    asm volatile("cp.async.wait_group 0;");
}
__device__ __forceinline__ uint32_t f2tf32(float x) {
    uint32_t r;
    asm("cvt.rna.tf32.f32 %0, %1;" : "=r"(r) : "f"(x));
    return r;
}
__device__ __forceinline__ void mma_tf32(float* c, const uint32_t* a, const uint32_t* b) {
    asm volatile(
        "mma.sync.aligned.m16n8k8.row.col.f32.tf32.tf32.f32 "
        "{%0,%1,%2,%3}, {%4,%5,%6,%7}, {%8,%9}, {%0,%1,%2,%3};"
        : "+f"(c[0]), "+f"(c[1]), "+f"(c[2]), "+f"(c[3])
        : "r"(a[0]), "r"(a[1]), "r"(a[2]), "r"(a[3]), "r"(b[0]), "r"(b[1]));
}

// ---------------------------------------------------------------------------
// TF32 tensor-core GEMM (unchanged from R2).
// ---------------------------------------------------------------------------
template<int BM, int BN, int WARPS_M, int WARPS_N, bool TRANSB, bool GELU>
__global__ __launch_bounds__(256)
void mm_tf32_kernel(int M, int N, int K,
                    const float* __restrict__ A, int lda,
                    const float* __restrict__ B, int ldb,
                    float* __restrict__ C, int ldc,
                    const float* __restrict__ bias,
                    float alpha)
{
    constexpr int BK = 16;
    constexpr int WM = BM / WARPS_M;
    constexpr int WN = BN / WARPS_N;
    constexpr int MT = WM / 16;
    constexpr int NT = WN / 8;
    constexpr int AS_STRIDE = BK + 4;
    constexpr int BS_STRIDE = TRANSB ? (BK + 4) : (BN + 8);
    constexpr int AS_ELEMS  = BM * AS_STRIDE;
    constexpr int BS_ELEMS  = TRANSB ? BN * BS_STRIDE : BK * BS_STRIDE;

    __shared__ float As[2][AS_ELEMS];
    __shared__ float Bs[2][BS_ELEMS];

    const int tid  = threadIdx.x;
    const int lane = tid & 31;
    const int warp = tid >> 5;
    const int grp  = lane >> 2;
    const int tig  = lane & 3;
    const int wm0  = (warp / WARPS_N) * WM;
    const int wn0  = (warp % WARPS_N) * WN;

    const int m0 = blockIdx.y * BM;
    const int n0 = blockIdx.x * BN;

    float acc[MT][NT][4];
#pragma unroll
    for (int mi = 0; mi < MT; mi++)
#pragma unroll
        for (int ni = 0; ni < NT; ni++)
#pragma unroll
            for (int e = 0; e < 4; e++) acc[mi][ni][e] = 0.0f;

    auto load_stage = [&](int k0, int buf) {
#pragma unroll 2
        for (int c = tid; c < BM * 4; c += 256) {
            int m = c >> 2, kq = c & 3;
            cp16(smem_u32(&As[buf][m * AS_STRIDE + kq * 4]),
                 A + (size_t)(m0 + m) * lda + k0 + kq * 4);
        }
        if (TRANSB) {
#pragma unroll 2
            for (int c = tid; c < BN * 4; c += 256) {
                int n = c >> 2, kq = c & 3;
                cp16(smem_u32(&Bs[buf][n * BS_STRIDE + kq * 4]),
                     B + (size_t)(n0 + n) * ldb + k0 + kq * 4);
            }
        } else {
#pragma unroll 2
            for (int c = tid; c < BK * (BN / 4); c += 256) {
                int kk = c / (BN / 4), nq = c % (BN / 4);
                cp16(smem_u32(&Bs[buf][kk * BS_STRIDE + nq * 4]),
                     B + (size_t)(k0 + kk) * ldb + n0 + nq * 4);
            }
        }
        cp_commit();
    };

    auto compute_stage = [&](int buf) {
        const float* as = As[buf];
        const float* bs = Bs[buf];
#pragma unroll
        for (int kk = 0; kk < BK; kk += 8) {
            uint32_t af[MT][4], bf[NT][2];
#pragma unroll
            for (int mi = 0; mi < MT; mi++) {
                int r = wm0 + mi * 16 + grp;
                int c = kk + tig;
                af[mi][0] = f2tf32(as[(r    ) * AS_STRIDE + c    ]);
                af[mi][1] = f2tf32(as[(r + 8) * AS_STRIDE + c    ]);
                af[mi][2] = f2tf32(as[(r    ) * AS_STRIDE + c + 4]);
                af[mi][3] = f2tf32(as[(r + 8) * AS_STRIDE + c + 4]);
            }
#pragma unroll
            for (int ni = 0; ni < NT; ni++) {
                int n = wn0 + ni * 8 + grp;
                if (TRANSB) {
                    bf[ni][0] = f2tf32(bs[n * BS_STRIDE + kk + tig    ]);
                    bf[ni][1] = f2tf32(bs[n * BS_STRIDE + kk + tig + 4]);
                } else {
                    bf[ni][0] = f2tf32(bs[(kk + tig    ) * BS_STRIDE + n]);
                    bf[ni][1] = f2tf32(bs[(kk + tig + 4) * BS_STRIDE + n]);
                }
            }
#pragma unroll
            for (int mi = 0; mi < MT; mi++)
#pragma unroll
                for (int ni = 0; ni < NT; ni++)
                    mma_tf32(acc[mi][ni], af[mi], bf[ni]);
        }
    };

    const int nstages = K / BK;
    load_stage(0, 0);
    for (int s = 0; s < nstages; s++) {
        cp_wait0();
        __syncthreads();
        if (s + 1 < nstages) load_stage((s + 1) * BK, (s + 1) & 1);
        compute_stage(s & 1);
        __syncthreads();
    }

#pragma unroll
    for (int mi = 0; mi < MT; mi++) {
#pragma unroll
        for (int ni = 0; ni < NT; ni++) {
#pragma unroll
            for (int h = 0; h < 2; h++) {
                int row = m0 + wm0 + mi * 16 + grp + h * 8;
                int col = n0 + wn0 + ni * 8 + 2 * tig;
                float v0 = acc[mi][ni][h * 2 + 0] * alpha;
                float v1 = acc[mi][ni][h * 2 + 1] * alpha;
                if (bias) { v0 += bias[col]; v1 += bias[col + 1]; }
                if (GELU) {
                    v0 = 0.5f * v0 * (1.0f + erff(v0 * 0.7071067811865475f));
                    v1 = 0.5f * v1 * (1.0f + erff(v1 * 0.7071067811865475f));
                }
                float2 o = make_float2(v0, v1);
                *(float2*)(C + (size_t)row * ldc + col) = o;
            }
        }
    }
}

// ---------------------------------------------------------------------------
// Flash attention: ctx = softmax(Q K^T / 8) V per (b,h), fully fused.
// Block: 128 q-rows, 8 warps (16 rows/warp). KV tiles of 128 keys.
// Q frags in registers (TF32, pre-scaled). K double-buffered cp.async.
// V fetched to regs at loop top, stored transposed+TF32 to smem for PV.
// ---------------------------------------------------------------------------
#define FA_KS_STRIDE 68
#define FA_VT_STRIDE 132
#define FA_PS_STRIDE 132
#define FA_KS_BUF    (128 * FA_KS_STRIDE)          // 8704 floats per buffer
#define FA_SMEM_FLOATS (2 * FA_KS_BUF + 64 * FA_VT_STRIDE + 8 * 16 * FA_PS_STRIDE)
#define FA_SMEM_BYTES  (FA_SMEM_FLOATS * 4)        // 171008 B

__global__ __launch_bounds__(256)
void flash_kernel(const float* __restrict__ q, const float* __restrict__ k,
                  const float* __restrict__ v, float* __restrict__ ctx)
{
    extern __shared__ float sm[];
    float* Ks = sm;                         // [2][128][68]
    float* Vt = sm + 2 * FA_KS_BUF;         // [64][132] (tf32 bits)
    float* Ps = Vt + 64 * FA_VT_STRIDE;     // [8 warps][16][132] (tf32 bits)

    const int tid  = threadIdx.x;
    const int lane = tid & 31;
    const int warp = tid >> 5;
    const int grp  = lane >> 2;
    const int tig  = lane & 3;

    const int m0 = blockIdx.x * 128;
    const int bh = blockIdx.y;
    const int b  = bh >> 4;
    const int h  = bh & 15;

    const float* qb = q + ((size_t)b * SEQ) * DMODEL + h * HEADDIM;
    const float* kb = k + ((size_t)b * SEQ) * DMODEL + h * HEADDIM;
    const float* vb = v + ((size_t)b * SEQ) * DMODEL + h * HEADDIM;

    // ---- stage Q tile through Ks[0], convert to register fragments ----
    for (int c = tid; c < 128 * 16; c += 256) {
        int r = c >> 4, ch = c & 15;
        cp16(smem_u32(&Ks[r * FA_KS_STRIDE + ch * 4]),
             qb + (size_t)(m0 + r) * DMODEL + ch * 4);
    }
    cp_commit(); cp_wait0(); __syncthreads();

    uint32_t aq[8][4];
    {
        const float* qs = Ks + (warp * 16) * FA_KS_STRIDE;
#pragma unroll
        for (int kc = 0; kc < 8; kc++) {
            aq[kc][0] = f2tf32(0.125f * qs[(grp    ) * FA_KS_STRIDE + kc * 8 + tig    ]);
            aq[kc][1] = f2tf32(0.125f * qs[(grp + 8) * FA_KS_STRIDE + kc * 8 + tig    ]);
            aq[kc][2] = f2tf32(0.125f * qs[(grp    ) * FA_KS_STRIDE + kc * 8 + tig + 4]);
            aq[kc][3] = f2tf32(0.125f * qs[(grp + 8) * FA_KS_STRIDE + kc * 8 + tig + 4]);
        }
    }
    __syncthreads();   // all warps done reading Q before K overwrites Ks[0]

    float o[8][4];
#pragma unroll
    for (int ni = 0; ni < 8; ni++)
#pragma unroll
        for (int e = 0; e < 4; e++) o[ni][e] = 0.0f;
    float mrun0 = -1e30f, mrun1 = -1e30f, lrun0 = 0.0f, lrun1 = 0.0f;

    // preload K tile 0 into buffer 0
    for (int c = tid; c < 2048; c += 256) {
        int r = c >> 4, ch = c & 15;
        cp16(smem_u32(&Ks[r * FA_KS_STRIDE + ch * 4]),
             kb + (size_t)r * DMODEL + ch * 4);
    }
    cp_commit();

    const int NTILE = SEQ / 128;  // 16
    for (int t = 0; t < NTILE; t++) {
        // issue V loads for this tile early (consumed after S compute)
        float vr[32];
#pragma unroll
        for (int i = 0; i < 32; i++) {
            int c = tid + i * 256;
            int d = c & 63, kk = c >> 6;
            vr[i] = vb[(size_t)(t * 128 + kk) * DMODEL + d];
        }

        cp_wait0();
        __syncthreads();   // K tile t ready; prev PV done (Vt/Ps reusable)

        // prefetch next K tile into the other buffer
        if (t + 1 < NTILE) {
            float* kd = Ks + ((t + 1) & 1) * FA_KS_BUF;
            for (int c = tid; c < 2048; c += 256) {
                int r = c >> 4, ch = c & 15;
                cp16(smem_u32(&kd[r * FA_KS_STRIDE + ch * 4]),
                     kb + (size_t)((t + 1) * 128 + r) * DMODEL + ch * 4);
            }
            cp_commit();
        }

        // ---- S = (Q/8) @ K^T, 16 q-rows x 128 keys per warp ----
        const float* kcur = Ks + (t & 1) * FA_KS_BUF;
        float sacc[16][4];
#pragma unroll
        for (int ni = 0; ni < 16; ni++)
#pragma unroll
            for (int e = 0; e < 4; e++) sacc[ni][e] = 0.0f;

#pragma unroll
        for (int ni = 0; ni < 16; ni++) {
            const float* kr = kcur + (ni * 8 + grp) * FA_KS_STRIDE;
#pragma unroll
            for (int kc = 0; kc < 8; kc++) {
                uint32_t bf[2];
                bf[0] = f2tf32(kr[kc * 8 + tig    ]);
                bf[1] = f2tf32(kr[kc * 8 + tig + 4]);
                mma_tf32(sacc[ni], aq[kc], bf);
            }
        }

        // ---- online softmax update ----
        float tmax0 = -1e30f, tmax1 = -1e30f;
#pragma unroll
        for (int ni = 0; ni < 16; ni++) {
            tmax0 = fmaxf(tmax0, fmaxf(sacc[ni][0], sacc[ni][1]));
            tmax1 = fmaxf(tmax1, fmaxf(sacc[ni][2], sacc[ni][3]));
        }
        tmax0 = fmaxf(tmax0, __shfl_xor_sync(0xffffffffu, tmax0, 1));
        tmax0 = fmaxf(tmax0, __shfl_xor_sync(0xffffffffu, tmax0, 2));
        tmax1 = fmaxf(tmax1, __shfl_xor_sync(0xffffffffu, tmax1, 1));
        tmax1 = fmaxf(tmax1, __shfl_xor_sync(0xffffffffu, tmax1, 2));

        float nm0 = fmaxf(mrun0, tmax0);
        float nm1 = fmaxf(mrun1, tmax1);
        float sc0 = __expf(mrun0 - nm0);
        float sc1 = __expf(mrun1 - nm1);
        mrun0 = nm0; mrun1 = nm1;

        float* pw = Ps + warp * (16 * FA_PS_STRIDE);
        float sum0 = 0.0f, sum1 = 0.0f;
#pragma unroll
        for (int ni = 0; ni < 16; ni++) {
            float p00 = __expf(sacc[ni][0] - nm0);
            float p01 = __expf(sacc[ni][1] - nm0);
            float p10 = __expf(sacc[ni][2] - nm1);
            float p11 = __expf(sacc[ni][3] - nm1);
            sum0 += p00 + p01;
            sum1 += p10 + p11;
            int col = ni * 8 + 2 * tig;
            pw[(grp    ) * FA_PS_STRIDE + col    ] = __uint_as_float(f2tf32(p00));
            pw[(grp    ) * FA_PS_STRIDE + col + 1] = __uint_as_float(f2tf32(p01));
            pw[(grp + 8) * FA_PS_STRIDE + col    ] = __uint_as_float(f2tf32(p10));
            pw[(grp + 8) * FA_PS_STRIDE + col + 1] = __uint_as_float(f2tf32(p11));
        }
        sum0 += __shfl_xor_sync(0xffffffffu, sum0, 1);
        sum0 += __shfl_xor_sync(0xffffffffu, sum0, 2);
        sum1 += __shfl_xor_sync(0xffffffffu, sum1, 1);
        sum1 += __shfl_xor_sync(0xffffffffu, sum1, 2);
        lrun0 = lrun0 * sc0 + sum0;
        lrun1 = lrun1 * sc1 + sum1;

#pragma unroll
        for (int ni = 0; ni < 8; ni++) {
            o[ni][0] *= sc0; o[ni][1] *= sc0;
            o[ni][2] *= sc1; o[ni][3] *= sc1;
        }

        // ---- store V transposed (tf32 bits) ----
#pragma unroll
        for (int i = 0; i < 32; i++) {
            int c = tid + i * 256;
            int d = c & 63, kk = c >> 6;
            Vt[d * FA_VT_STRIDE + kk] = __uint_as_float(f2tf32(vr[i]));
        }
        __syncthreads();   // Vt + all warps' Ps visible

        // ---- O += P @ V ----
#pragma unroll
        for (int kc = 0; kc < 16; kc++) {
            uint32_t a[4];
            a[0] = __float_as_uint(pw[(grp    ) * FA_PS_STRIDE + kc * 8 + tig    ]);
            a[1] = __float_as_uint(pw[(grp + 8) * FA_PS_STRIDE + kc * 8 + tig    ]);
            a[2] = __float_as_uint(pw[(grp    ) * FA_PS_STRIDE + kc * 8 + tig + 4]);
            a[3] = __float_as_uint(pw[(grp + 8) * FA_PS_STRIDE + kc * 8 + tig + 4]);
#pragma unroll
            for (int ni = 0; ni < 8; ni++) {
                uint32_t bb[2];
                bb[0] = __float_as_uint(Vt[(ni * 8 + grp) * FA_VT_STRIDE + kc * 8 + tig    ]);
                bb[1] = __float_as_uint(Vt[(ni * 8 + grp) * FA_VT_STRIDE + kc * 8 + tig + 4]);
                mma_tf32(o[ni], a, bb);
            }
        }
    }

    // ---- normalize and write ctx ----
    float inv0 = 1.0f / lrun0;
    float inv1 = 1.0f / lrun1;
    int r0 = m0 + warp * 16 + grp;
    float* cb = ctx + ((size_t)b * SEQ) * DMODEL + h * HEADDIM;
#pragma unroll
    for (int ni = 0; ni < 8; ni++) {
        int col = ni * 8 + 2 * tig;
        *(float2*)(cb + (size_t)(r0    ) * DMODEL + col) =
            make_float2(o[ni][0] * inv0, o[ni][1] * inv0);
        *(float2*)(cb + (size_t)(r0 + 8) * DMODEL + col) =
            make_float2(o[ni][2] * inv1, o[ni][3] * inv1);
    }
}

// ---------------------------------------------------------------------------
// RoPE on q and k together (sincos computed once per pair position)
// ---------------------------------------------------------------------------
__global__ void rope2_kernel(float* __restrict__ xq, float* __restrict__ xk,
                             const float* __restrict__ tau, int n_pairs)
{
    int idx = blockIdx.x * 256 + threadIdx.x;
    if (idx >= n_pairs) return;
    int bs = idx >> 9;
    int r  = idx & 511;
    int j  = r & 31;
    int h  = r >> 5;
    size_t off = ((size_t)bs << 10) + h * HEADDIM + 2 * j;
    float t   = tau[bs];
    float inv = expf(-0.28782313662425572f * (float)j); // ln(10000)/32
    float s, c;
    sincosf(t * inv, &s, &c);
    float q0 = xq[off], q1 = xq[off + 1];
    xq[off]     = q0 * c - q1 * s;
    xq[off + 1] = q1 * c + q0 * s;
    float k0 = xk[off], k1 = xk[off + 1];
    xk[off]     = k0 * c - k1 * s;
    xk[off + 1] = k1 * c + k0 * s;
}

// ---------------------------------------------------------------------------
// Fused residual + LayerNorm: out = LN(a + b) * g + be.  D = 1024 fixed.
// ---------------------------------------------------------------------------
__global__ __launch_bounds__(256)
void ln_kernel(const float* __restrict__ a, const float* __restrict__ b,
               const float* __restrict__ g, const float* __restrict__ be,
               float* __restrict__ out)
{
    const int D = DMODEL;
    size_t row = blockIdx.x;
    const float* pa = a + row * D;
    const float* pb = b + row * D;
    int tid = threadIdx.x;
    __shared__ float red[256];

    float x[4];
    float s = 0.0f;
#pragma unroll
    for (int i = 0; i < 4; i++) {
        int c = tid + i * 256;
        x[i] = pa[c] + pb[c];
        s += x[i];
    }
    red[tid] = s;
    __syncthreads();
    for (int t = 128; t > 0; t >>= 1) {
        if (tid < t) red[tid] += red[tid + t];
        __syncthreads();
    }
    float mu = red[0] * (1.0f / D);
    __syncthreads();

    float v = 0.0f;
#pragma unroll
    for (int i = 0; i < 4; i++) {
        float d = x[i] - mu;
        v += d * d;
    }
    red[tid] = v;
    __syncthreads();
    for (int t = 128; t > 0; t >>= 1) {
        if (tid < t) red[tid] += red[tid + t];
        __syncthreads();
    }
    float var = red[0] * (1.0f / D);
    float r = rsqrtf(var + 1e-5f);
#pragma unroll
    for (int i = 0; i < 4; i++) {
        int c = tid + i * 256;
        out[row * D + c] = (x[i] - mu) * r * g[c] + be[c];
    }
}

// ---------------------------------------------------------------------------
// Host-side launch
// ---------------------------------------------------------------------------
static float* symptr(const void* sym)
{
    void* p = nullptr;
    cudaGetSymbolAddress(&p, sym);
    return (float*)p;
}

extern "C" void kernel_launch(void* const* d_in, const int* in_sizes, int n_in,
                              void* d_out, int out_size)
{
    const float* src = (const float*)d_in[0];
    const float* tau = (const float*)d_in[1];
    const float* Wq  = (const float*)d_in[2];
    const float* bq  = (const float*)d_in[3];
    const float* Wk  = (const float*)d_in[4];
    const float* bk  = (const float*)d_in[5];
    const float* Wv  = (const float*)d_in[6];
    const float* bv  = (const float*)d_in[7];
    const float* Wo  = (const float*)d_in[8];
    const float* bo  = (const float*)d_in[9];
    const float* W1  = (const float*)d_in[10];
    const float* b1  = (const float*)d_in[11];
    const float* W2  = (const float*)d_in[12];
    const float* b2  = (const float*)d_in[13];
    const float* g1  = (const float*)d_in[14];
    const float* be1 = (const float*)d_in[15];
    const float* g2  = (const float*)d_in[16];
    const float* be2 = (const float*)d_in[17];
    float* out = (float*)d_out;

    float* q   = symptr(g_q);
    float* k   = symptr(g_k);
    float* v   = symptr(g_v);
    float* ctx = symptr(g_ctx);
    float* ao  = symptr(g_attnout);
    float* h1  = symptr(g_h1);
    float* f1  = symptr(g_ff1);
    float* f2  = symptr(g_ff2);

    cudaFuncSetAttribute(flash_kernel,
                         cudaFuncAttributeMaxDynamicSharedMemorySize,
                         FA_SMEM_BYTES);

    // ---- QKV projections ----
    {
        dim3 grid(DMODEL / 128, TOKENS / 128, 1);
        mm_tf32_kernel<128,128,2,4,false,false><<<grid, 256>>>(
            TOKENS, DMODEL, DMODEL, src, DMODEL, Wq, DMODEL, q, DMODEL, bq, 1.0f);
        mm_tf32_kernel<128,128,2,4,false,false><<<grid, 256>>>(
            TOKENS, DMODEL, DMODEL, src, DMODEL, Wk, DMODEL, k, DMODEL, bk, 1.0f);
        mm_tf32_kernel<128,128,2,4,false,false><<<grid, 256>>>(
            TOKENS, DMODEL, DMODEL, src, DMODEL, Wv, DMODEL, v, DMODEL, bv, 1.0f);
    }

    // ---- RoPE on q and k (fused) ----
    {
        int n_pairs = TOKENS * DMODEL / 2;
        rope2_kernel<<<(n_pairs + 255) / 256, 256>>>(q, k, tau, n_pairs);
    }

    // ---- fused flash attention -> ctx ----
    flash_kernel<<<dim3(SEQ / 128, BATCH * NHEADS), 256, FA_SMEM_BYTES>>>(
        q, k, v, ctx);

    // ---- output projection ----
    {
        dim3 grid(DMODEL / 128, TOKENS / 128, 1);
        mm_tf32_kernel<128,128,2,4,false,false><<<grid, 256>>>(
            TOKENS, DMODEL, DMODEL, ctx, DMODEL, Wo, DMODEL, ao, DMODEL, bo, 1.0f);
    }

    // ---- LN1 ----
    ln_kernel<<<TOKENS, 256>>>(src, ao, g1, be1, h1);

    // ---- FFN ----
    {
        dim3 grid(DFF / 128, TOKENS / 128, 1);
        mm_tf32_kernel<128,128,2,4,false,true><<<grid, 256>>>(
            TOKENS, DFF, DMODEL, h1, DMODEL, W1, DFF, f1, DFF, b1, 1.0f);
    }
    {
        dim3 grid(DMODEL / 128, TOKENS / 128, 1);
        mm_tf32_kernel<128,128,2,4,false,false><<<grid, 256>>>(
            TOKENS, DMODEL, DFF, f1, DFF, W2, DMODEL, f2, DMODEL, b2, 1.0f);
    }

    // ---- LN2 -> out ----
    ln_kernel<<<TOKENS, 256>>>(h1, f2, g2, be2, out);

    (void)in_sizes; (void)n_in; (void)out_size;
}

// round 4
// speedup vs baseline: 3.3635x; 1.0371x over previous
#include <cuda_runtime.h>
#include <math.h>
#include <cstdint>

// ---------------------------------------------------------------------------
// Problem constants
// ---------------------------------------------------------------------------
#define BATCH   2
#define SEQ     2048
#define DMODEL  1024
#define NHEADS  16
#define HEADDIM 64
#define DFF     4096
#define TOKENS  (BATCH * SEQ)          // 4096

// ---------------------------------------------------------------------------
// Scratch (static device allocations; no cudaMalloc allowed)
// ---------------------------------------------------------------------------
__device__ float g_q[TOKENS * DMODEL];
__device__ float g_k[TOKENS * DMODEL];
__device__ float g_v[TOKENS * DMODEL];
__device__ float g_ctx[TOKENS * DMODEL];
__device__ float g_attnout[TOKENS * DMODEL];
__device__ float g_h1[TOKENS * DMODEL];
__device__ float g_ff1[TOKENS * DFF];
__device__ float g_ff2[TOKENS * DMODEL];

// ---------------------------------------------------------------------------
// PTX helpers
// ---------------------------------------------------------------------------
__device__ __forceinline__ uint32_t smem_u32(const void* p) {
    return (uint32_t)__cvta_generic_to_shared(p);
}
__device__ __forceinline__ void cp16(uint32_t s, const void* g) {
    asm volatile("cp.async.cg.shared.global [%0], [%1], 16;" :: "r"(s), "l"(g));
}
__device__ __forceinline__ void cp_commit() {
    asm volatile("cp.async.commit_group;");
}
__device__ __forceinline__ void cp_wait0() {
    asm volatile("cp.async.wait_group 0;");
}
__device__ __forceinline__ uint32_t f2tf32(float x) {
    uint32_t r;
    asm("cvt.rna.tf32.f32 %0, %1;" : "=r"(r) : "f"(x));
    return r;
}
// mma with raw fp32 bits in a/b: HW consumes the tf32 subset (truncation).
__device__ __forceinline__ void mma_tf32(float* c, const uint32_t* a, const uint32_t* b) {
    asm volatile(
        "mma.sync.aligned.m16n8k8.row.col.f32.tf32.tf32.f32 "
        "{%0,%1,%2,%3}, {%4,%5,%6,%7}, {%8,%9}, {%0,%1,%2,%3};"
        : "+f"(c[0]), "+f"(c[1]), "+f"(c[2]), "+f"(c[3])
        : "r"(a[0]), "r"(a[1]), "r"(a[2]), "r"(a[3]), "r"(b[0]), "r"(b[1]));
}

// ---------------------------------------------------------------------------
// TF32 GEMM v2: BM=128, BN=256, BK=16, 8 warps (2x4), warp tile 64x64.
// No inner-loop cvt (raw fp32 bits to mma). Optional fused QKV (grid.z
// selects weight/bias/output; RoPE applied in epilogue for z<2) and GELU.
// Requires M%128==0, N%256==0, K%16==0.
// ---------------------------------------------------------------------------
#define MM2_AS_STRIDE 20
#define MM2_BS_STRIDE 264
#define MM2_AS_ELEMS  (128 * MM2_AS_STRIDE)   // 2560
#define MM2_BS_ELEMS  (16 * MM2_BS_STRIDE)    // 4224
#define MM2_SMEM_BYTES ((2 * (MM2_AS_ELEMS + MM2_BS_ELEMS)) * 4)  // 54272

template<bool QKV, bool GELU>
__global__ __launch_bounds__(256)
void mm2_kernel(int M, int N, int K,
                const float* __restrict__ A, int lda,
                const float* __restrict__ B0, const float* __restrict__ B1,
                const float* __restrict__ B2, int ldb,
                float* __restrict__ C0, float* __restrict__ C1,
                float* __restrict__ C2, int ldc,
                const float* __restrict__ bias0, const float* __restrict__ bias1,
                const float* __restrict__ bias2,
                const float* __restrict__ tau)
{
    constexpr int BM = 128, BN = 256, BK = 16;
    constexpr int MT = 4, NT = 8;             // warp tile 64x64

    extern __shared__ float sm[];
    float* As[2] = { sm, sm + MM2_AS_ELEMS };
    float* Bs[2] = { sm + 2 * MM2_AS_ELEMS, sm + 2 * MM2_AS_ELEMS + MM2_BS_ELEMS };

    const float* B    = B0;
    float*       C    = C0;
    const float* bias = bias0;
    bool rope = false;
    if (QKV) {
        int z = blockIdx.z;
        if (z == 1)      { B = B1; C = C1; bias = bias1; }
        else if (z == 2) { B = B2; C = C2; bias = bias2; }
        rope = (z < 2);
    }

    const int tid  = threadIdx.x;
    const int lane = tid & 31;
    const int warp = tid >> 5;
    const int grp  = lane >> 2;
    const int tig  = lane & 3;
    const int wm0  = (warp >> 2) * 64;    // warp / 4 -> 0,1
    const int wn0  = (warp & 3) * 64;     // warp % 4 -> 0..3

    const int m0 = blockIdx.y * BM;
    const int n0 = blockIdx.x * BN;

    float acc[MT][NT][4];
#pragma unroll
    for (int mi = 0; mi < MT; mi++)
#pragma unroll
        for (int ni = 0; ni < NT; ni++)
#pragma unroll
            for (int e = 0; e < 4; e++) acc[mi][ni][e] = 0.0f;

    auto load_stage = [&](int k0, int buf) {
        // A: 128 rows x 16 floats -> 512 16B-chunks, 2 per thread
#pragma unroll
        for (int l = 0; l < 2; l++) {
            int c = tid + l * 256;
            int m = c >> 2, kq = c & 3;
            cp16(smem_u32(&As[buf][m * MM2_AS_STRIDE + kq * 4]),
                 A + (size_t)(m0 + m) * lda + k0 + kq * 4);
        }
        // B: 16 rows x 256 floats -> 1024 16B-chunks, 4 per thread
#pragma unroll
        for (int l = 0; l < 4; l++) {
            int c = tid + l * 256;
            int kk = c >> 6, nq = c & 63;
            cp16(smem_u32(&Bs[buf][kk * MM2_BS_STRIDE + nq * 4]),
                 B + (size_t)(k0 + kk) * ldb + n0 + nq * 4);
        }
        cp_commit();
    };

    auto compute_stage = [&](int buf) {
        const float* as = As[buf];
        const float* bs = Bs[buf];
#pragma unroll
        for (int kk = 0; kk < BK; kk += 8) {
            uint32_t af[MT][4], bf[NT][2];
#pragma unroll
            for (int mi = 0; mi < MT; mi++) {
                int r = wm0 + mi * 16 + grp;
                int c = kk + tig;
                af[mi][0] = __float_as_uint(as[(r    ) * MM2_AS_STRIDE + c    ]);
                af[mi][1] = __float_as_uint(as[(r + 8) * MM2_AS_STRIDE + c    ]);
                af[mi][2] = __float_as_uint(as[(r    ) * MM2_AS_STRIDE + c + 4]);
                af[mi][3] = __float_as_uint(as[(r + 8) * MM2_AS_STRIDE + c + 4]);
            }
#pragma unroll
            for (int ni = 0; ni < NT; ni++) {
                int n = wn0 + ni * 8 + grp;
                bf[ni][0] = __float_as_uint(bs[(kk + tig    ) * MM2_BS_STRIDE + n]);
                bf[ni][1] = __float_as_uint(bs[(kk + tig + 4) * MM2_BS_STRIDE + n]);
            }
#pragma unroll
            for (int mi = 0; mi < MT; mi++)
#pragma unroll
                for (int ni = 0; ni < NT; ni++)
                    mma_tf32(acc[mi][ni], af[mi], bf[ni]);
        }
    };

    const int nstages = K / BK;
    load_stage(0, 0);
    for (int s = 0; s < nstages; s++) {
        cp_wait0();
        __syncthreads();
        if (s + 1 < nstages) load_stage((s + 1) * BK, (s + 1) & 1);
        compute_stage(s & 1);
        __syncthreads();
    }

    // ---- epilogue ----
#pragma unroll
    for (int mi = 0; mi < MT; mi++) {
#pragma unroll
        for (int h = 0; h < 2; h++) {
            int row = m0 + wm0 + mi * 16 + grp + h * 8;
            float t = 0.0f;
            if (QKV) t = tau[row];   // harmless load for z==2
#pragma unroll
            for (int ni = 0; ni < NT; ni++) {
                int col = wn0 + ni * 8 + 2 * tig;   // within BN tile; even
                int gcol = n0 + col;
                float v0 = acc[mi][ni][h * 2 + 0];
                float v1 = acc[mi][ni][h * 2 + 1];
                if (bias) { v0 += bias[gcol]; v1 += bias[gcol + 1]; }
                if (GELU) {
                    v0 = 0.5f * v0 * (1.0f + erff(v0 * 0.7071067811865475f));
                    v1 = 0.5f * v1 * (1.0f + erff(v1 * 0.7071067811865475f));
                }
                if (QKV && rope) {
                    int j = (gcol & 63) >> 1;
                    float inv = __expf(-0.28782313662425572f * (float)j);
                    float s, c;
                    sincosf(t * inv, &s, &c);
                    float r0 = v0 * c - v1 * s;
                    float r1 = v1 * c + v0 * s;
                    v0 = r0; v1 = r1;
                }
                *(float2*)(C + (size_t)row * ldc + gcol) = make_float2(v0, v1);
            }
        }
    }
}

// ---------------------------------------------------------------------------
// Flash attention: ctx = softmax(Q K^T / 8) V per (b,h), fully fused.
// Raw-bit tf32 operands everywhere except the one-time Q convert.
// ---------------------------------------------------------------------------
#define FA_KS_STRIDE 68
#define FA_VT_STRIDE 132
#define FA_PS_STRIDE 132
#define FA_KS_BUF    (128 * FA_KS_STRIDE)
#define FA_SMEM_FLOATS (2 * FA_KS_BUF + 64 * FA_VT_STRIDE + 8 * 16 * FA_PS_STRIDE)
#define FA_SMEM_BYTES  (FA_SMEM_FLOATS * 4)

__global__ __launch_bounds__(256)
void flash_kernel(const float* __restrict__ q, const float* __restrict__ k,
                  const float* __restrict__ v, float* __restrict__ ctx)
{
    extern __shared__ float sm[];
    float* Ks = sm;
    float* Vt = sm + 2 * FA_KS_BUF;
    float* Ps = Vt + 64 * FA_VT_STRIDE;

    const int tid  = threadIdx.x;
    const int lane = tid & 31;
    const int warp = tid >> 5;
    const int grp  = lane >> 2;
    const int tig  = lane & 3;

    const int m0 = blockIdx.x * 128;
    const int bh = blockIdx.y;
    const int b  = bh >> 4;
    const int h  = bh & 15;

    const float* qb = q + ((size_t)b * SEQ) * DMODEL + h * HEADDIM;
    const float* kb = k + ((size_t)b * SEQ) * DMODEL + h * HEADDIM;
    const float* vb = v + ((size_t)b * SEQ) * DMODEL + h * HEADDIM;

    // stage Q tile through Ks[0]
    for (int c = tid; c < 128 * 16; c += 256) {
        int r = c >> 4, ch = c & 15;
        cp16(smem_u32(&Ks[r * FA_KS_STRIDE + ch * 4]),
             qb + (size_t)(m0 + r) * DMODEL + ch * 4);
    }
    cp_commit(); cp_wait0(); __syncthreads();

    uint32_t aq[8][4];
    {
        const float* qs = Ks + (warp * 16) * FA_KS_STRIDE;
#pragma unroll
        for (int kc = 0; kc < 8; kc++) {
            aq[kc][0] = f2tf32(0.125f * qs[(grp    ) * FA_KS_STRIDE + kc * 8 + tig    ]);
            aq[kc][1] = f2tf32(0.125f * qs[(grp + 8) * FA_KS_STRIDE + kc * 8 + tig    ]);
            aq[kc][2] = f2tf32(0.125f * qs[(grp    ) * FA_KS_STRIDE + kc * 8 + tig + 4]);
            aq[kc][3] = f2tf32(0.125f * qs[(grp + 8) * FA_KS_STRIDE + kc * 8 + tig + 4]);
        }
    }
    __syncthreads();

    float o[8][4];
#pragma unroll
    for (int ni = 0; ni < 8; ni++)
#pragma unroll
        for (int e = 0; e < 4; e++) o[ni][e] = 0.0f;
    float mrun0 = -1e30f, mrun1 = -1e30f, lrun0 = 0.0f, lrun1 = 0.0f;

    for (int c = tid; c < 2048; c += 256) {
        int r = c >> 4, ch = c & 15;
        cp16(smem_u32(&Ks[r * FA_KS_STRIDE + ch * 4]),
             kb + (size_t)r * DMODEL + ch * 4);
    }
    cp_commit();

    const int NTILE = SEQ / 128;
    for (int t = 0; t < NTILE; t++) {
        float vr[32];
#pragma unroll
        for (int i = 0; i < 32; i++) {
            int c = tid + i * 256;
            int d = c & 63, kk = c >> 6;
            vr[i] = vb[(size_t)(t * 128 + kk) * DMODEL + d];
        }

        cp_wait0();
        __syncthreads();

        if (t + 1 < NTILE) {
            float* kd = Ks + ((t + 1) & 1) * FA_KS_BUF;
            for (int c = tid; c < 2048; c += 256) {
                int r = c >> 4, ch = c & 15;
                cp16(smem_u32(&kd[r * FA_KS_STRIDE + ch * 4]),
                     kb + (size_t)((t + 1) * 128 + r) * DMODEL + ch * 4);
            }
            cp_commit();
        }

        const float* kcur = Ks + (t & 1) * FA_KS_BUF;
        float sacc[16][4];
#pragma unroll
        for (int ni = 0; ni < 16; ni++)
#pragma unroll
            for (int e = 0; e < 4; e++) sacc[ni][e] = 0.0f;

#pragma unroll
        for (int ni = 0; ni < 16; ni++) {
            const float* kr = kcur + (ni * 8 + grp) * FA_KS_STRIDE;
#pragma unroll
            for (int kc = 0; kc < 8; kc++) {
                uint32_t bf[2];
                bf[0] = __float_as_uint(kr[kc * 8 + tig    ]);
                bf[1] = __float_as_uint(kr[kc * 8 + tig + 4]);
                mma_tf32(sacc[ni], aq[kc], bf);
            }
        }

        float tmax0 = -1e30f, tmax1 = -1e30f;
#pragma unroll
        for (int ni = 0; ni < 16; ni++) {
            tmax0 = fmaxf(tmax0, fmaxf(sacc[ni][0], sacc[ni][1]));
            tmax1 = fmaxf(tmax1, fmaxf(sacc[ni][2], sacc[ni][3]));
        }
        tmax0 = fmaxf(tmax0, __shfl_xor_sync(0xffffffffu, tmax0, 1));
        tmax0 = fmaxf(tmax0, __shfl_xor_sync(0xffffffffu, tmax0, 2));
        tmax1 = fmaxf(tmax1, __shfl_xor_sync(0xffffffffu, tmax1, 1));
        tmax1 = fmaxf(tmax1, __shfl_xor_sync(0xffffffffu, tmax1, 2));

        float nm0 = fmaxf(mrun0, tmax0);
        float nm1 = fmaxf(mrun1, tmax1);
        float sc0 = __expf(mrun0 - nm0);
        float sc1 = __expf(mrun1 - nm1);
        mrun0 = nm0; mrun1 = nm1;

        float* pw = Ps + warp * (16 * FA_PS_STRIDE);
        float sum0 = 0.0f, sum1 = 0.0f;
#pragma unroll
        for (int ni = 0; ni < 16; ni++) {
            float p00 = __expf(sacc[ni][0] - nm0);
            float p01 = __expf(sacc[ni][1] - nm0);
            float p10 = __expf(sacc[ni][2] - nm1);
            float p11 = __expf(sacc[ni][3] - nm1);
            sum0 += p00 + p01;
            sum1 += p10 + p11;
            int col = ni * 8 + 2 * tig;
            pw[(grp    ) * FA_PS_STRIDE + col    ] = p00;
            pw[(grp    ) * FA_PS_STRIDE + col + 1] = p01;
            pw[(grp + 8) * FA_PS_STRIDE + col    ] = p10;
            pw[(grp + 8) * FA_PS_STRIDE + col + 1] = p11;
        }
        sum0 += __shfl_xor_sync(0xffffffffu, sum0, 1);
        sum0 += __shfl_xor_sync(0xffffffffu, sum0, 2);
        sum1 += __shfl_xor_sync(0xffffffffu, sum1, 1);
        sum1 += __shfl_xor_sync(0xffffffffu, sum1, 2);
        lrun0 = lrun0 * sc0 + sum0;
        lrun1 = lrun1 * sc1 + sum1;

#pragma unroll
        for (int ni = 0; ni < 8; ni++) {
            o[ni][0] *= sc0; o[ni][1] *= sc0;
            o[ni][2] *= sc1; o[ni][3] *= sc1;
        }

#pragma unroll
        for (int i = 0; i < 32; i++) {
            int c = tid + i * 256;
            int d = c & 63, kk = c >> 6;
            Vt[d * FA_VT_STRIDE + kk] = vr[i];
        }
        __syncthreads();

#pragma unroll
        for (int kc = 0; kc < 16; kc++) {
            uint32_t a[4];
            a[0] = __float_as_uint(pw[(grp    ) * FA_PS_STRIDE + kc * 8 + tig    ]);
            a[1] = __float_as_uint(pw[(grp + 8) * FA_PS_STRIDE + kc * 8 + tig    ]);
            a[2] = __float_as_uint(pw[(grp    ) * FA_PS_STRIDE + kc * 8 + tig + 4]);
            a[3] = __float_as_uint(pw[(grp + 8) * FA_PS_STRIDE + kc * 8 + tig + 4]);
#pragma unroll
            for (int ni = 0; ni < 8; ni++) {
                uint32_t bb[2];
                bb[0] = __float_as_uint(Vt[(ni * 8 + grp) * FA_VT_STRIDE + kc * 8 + tig    ]);
                bb[1] = __float_as_uint(Vt[(ni * 8 + grp) * FA_VT_STRIDE + kc * 8 + tig + 4]);
                mma_tf32(o[ni], a, bb);
            }
        }
    }

    float inv0 = 1.0f / lrun0;
    float inv1 = 1.0f / lrun1;
    int r0 = m0 + warp * 16 + grp;
    float* cb = ctx + ((size_t)b * SEQ) * DMODEL + h * HEADDIM;
#pragma unroll
    for (int ni = 0; ni < 8; ni++) {
        int col = ni * 8 + 2 * tig;
        *(float2*)(cb + (size_t)(r0    ) * DMODEL + col) =
            make_float2(o[ni][0] * inv0, o[ni][1] * inv0);
        *(float2*)(cb + (size_t)(r0 + 8) * DMODEL + col) =
            make_float2(o[ni][2] * inv1, o[ni][3] * inv1);
    }
}

// ---------------------------------------------------------------------------
// Fused residual + LayerNorm: out = LN(a + b) * g + be.  D = 1024 fixed.
// ---------------------------------------------------------------------------
__global__ __launch_bounds__(256)
void ln_kernel(const float* __restrict__ a, const float* __restrict__ b,
               const float* __restrict__ g, const float* __restrict__ be,
               float* __restrict__ out)
{
    const int D = DMODEL;
    size_t row = blockIdx.x;
    const float* pa = a + row * D;
    const float* pb = b + row * D;
    int tid = threadIdx.x;
    __shared__ float red[256];

    float x[4];
    float s = 0.0f;
#pragma unroll
    for (int i = 0; i < 4; i++) {
        int c = tid + i * 256;
        x[i] = pa[c] + pb[c];
        s += x[i];
    }
    red[tid] = s;
    __syncthreads();
    for (int t = 128; t > 0; t >>= 1) {
        if (tid < t) red[tid] += red[tid + t];
        __syncthreads();
    }
    float mu = red[0] * (1.0f / D);
    __syncthreads();

    float v = 0.0f;
#pragma unroll
    for (int i = 0; i < 4; i++) {
        float d = x[i] - mu;
        v += d * d;
    }
    red[tid] = v;
    __syncthreads();
    for (int t = 128; t > 0; t >>= 1) {
        if (tid < t) red[tid] += red[tid + t];
        __syncthreads();
    }
    float var = red[0] * (1.0f / D);
    float r = rsqrtf(var + 1e-5f);
#pragma unroll
    for (int i = 0; i < 4; i++) {
        int c = tid + i * 256;
        out[row * D + c] = (x[i] - mu) * r * g[c] + be[c];
    }
}

// ---------------------------------------------------------------------------
// Host-side launch
// ---------------------------------------------------------------------------
static float* symptr(const void* sym)
{
    void* p = nullptr;
    cudaGetSymbolAddress(&p, sym);
    return (float*)p;
}

extern "C" void kernel_launch(void* const* d_in, const int* in_sizes, int n_in,
                              void* d_out, int out_size)
{
    const float* src = (const float*)d_in[0];
    const float* tau = (const float*)d_in[1];
    const float* Wq  = (const float*)d_in[2];
    const float* bq  = (const float*)d_in[3];
    const float* Wk  = (const float*)d_in[4];
    const float* bk  = (const float*)d_in[5];
    const float* Wv  = (const float*)d_in[6];
    const float* bv  = (const float*)d_in[7];
    const float* Wo  = (const float*)d_in[8];
    const float* bo  = (const float*)d_in[9];
    const float* W1  = (const float*)d_in[10];
    const float* b1  = (const float*)d_in[11];
    const float* W2  = (const float*)d_in[12];
    const float* b2  = (const float*)d_in[13];
    const float* g1  = (const float*)d_in[14];
    const float* be1 = (const float*)d_in[15];
    const float* g2  = (const float*)d_in[16];
    const float* be2 = (const float*)d_in[17];
    float* out = (float*)d_out;

    float* q   = symptr(g_q);
    float* k   = symptr(g_k);
    float* v   = symptr(g_v);
    float* ctx = symptr(g_ctx);
    float* ao  = symptr(g_attnout);
    float* h1  = symptr(g_h1);
    float* f1  = symptr(g_ff1);
    float* f2  = symptr(g_ff2);

    static bool attr_done = false;
    if (!attr_done) {
        cudaFuncSetAttribute(flash_kernel,
                             cudaFuncAttributeMaxDynamicSharedMemorySize, FA_SMEM_BYTES);
        cudaFuncSetAttribute(mm2_kernel<true,  false>,
                             cudaFuncAttributeMaxDynamicSharedMemorySize, MM2_SMEM_BYTES);
        cudaFuncSetAttribute(mm2_kernel<false, false>,
                             cudaFuncAttributeMaxDynamicSharedMemorySize, MM2_SMEM_BYTES);
        cudaFuncSetAttribute(mm2_kernel<false, true>,
                             cudaFuncAttributeMaxDynamicSharedMemorySize, MM2_SMEM_BYTES);
        attr_done = true;
    }

    // ---- fused QKV projections + RoPE epilogue (z = 0:q, 1:k, 2:v) ----
    mm2_kernel<true, false><<<dim3(DMODEL / 256, TOKENS / 128, 3), 256, MM2_SMEM_BYTES>>>(
        TOKENS, DMODEL, DMODEL, src, DMODEL,
        Wq, Wk, Wv, DMODEL, q, k, v, DMODEL, bq, bk, bv, tau);

    // ---- fused flash attention -> ctx ----
    flash_kernel<<<dim3(SEQ / 128, BATCH * NHEADS), 256, FA_SMEM_BYTES>>>(
        q, k, v, ctx);

    // ---- output projection ----
    mm2_kernel<false, false><<<dim3(DMODEL / 256, TOKENS / 128, 1), 256, MM2_SMEM_BYTES>>>(
        TOKENS, DMODEL, DMODEL, ctx, DMODEL,
        Wo, nullptr, nullptr, DMODEL, ao, nullptr, nullptr, DMODEL,
        bo, nullptr, nullptr, nullptr);

    // ---- LN1 ----
    ln_kernel<<<TOKENS, 256>>>(src, ao, g1, be1, h1);

    // ---- FFN ----
    mm2_kernel<false, true><<<dim3(DFF / 256, TOKENS / 128, 1), 256, MM2_SMEM_BYTES>>>(
        TOKENS, DFF, DMODEL, h1, DMODEL,
        W1, nullptr, nullptr, DFF, f1, nullptr, nullptr, DFF,
        b1, nullptr, nullptr, nullptr);
    mm2_kernel<false, false><<<dim3(DMODEL / 256, TOKENS / 128, 1), 256, MM2_SMEM_BYTES>>>(
        TOKENS, DMODEL, DFF, f1, DFF,
        W2, nullptr, nullptr, DMODEL, f2, nullptr, nullptr, DMODEL,
        b2, nullptr, nullptr, nullptr);

    // ---- LN2 -> out ----
    ln_kernel<<<TOKENS, 256>>>(h1, f2, g2, be2, out);

    (void)in_sizes; (void)n_in; (void)out_size;
}

// round 6
// speedup vs baseline: 4.9509x; 1.4719x over previous
#include <cuda_runtime.h>
#include <cuda_fp16.h>
#include <math.h>
#include <cstdint>

// ---------------------------------------------------------------------------
// Problem constants
// ---------------------------------------------------------------------------
#define BATCH   2
#define SEQ     2048
#define DMODEL  1024
#define NHEADS  16
#define HEADDIM 64
#define DFF     4096
#define TOKENS  (BATCH * SEQ)          // 4096

// ---------------------------------------------------------------------------
// Scratch (static device allocations)
// ---------------------------------------------------------------------------
__device__ __half g_srch[TOKENS * DMODEL];
__device__ __half g_qh  [TOKENS * DMODEL];
__device__ __half g_kh  [TOKENS * DMODEL];
__device__ __half g_vh  [TOKENS * DMODEL];
__device__ __half g_ctxh[TOKENS * DMODEL];
__device__ __half g_h1h [TOKENS * DMODEL];
__device__ __half g_f1h [(size_t)TOKENS * DFF];
__device__ float  g_ao  [TOKENS * DMODEL];
__device__ float  g_h1f [TOKENS * DMODEL];
__device__ float  g_f2  [TOKENS * DMODEL];
// transposed half weights, [N][K]
__device__ __half g_wqT[DMODEL * DMODEL];
__device__ __half g_wkT[DMODEL * DMODEL];
__device__ __half g_wvT[DMODEL * DMODEL];
__device__ __half g_woT[DMODEL * DMODEL];
__device__ __half g_w1T[(size_t)DFF * DMODEL];
__device__ __half g_w2T[(size_t)DMODEL * DFF];

// ---------------------------------------------------------------------------
// PTX helpers
// ---------------------------------------------------------------------------
__device__ __forceinline__ uint32_t smem_u32(const void* p) {
    return (uint32_t)__cvta_generic_to_shared(p);
}
__device__ __forceinline__ void cp16(uint32_t s, const void* g) {
    asm volatile("cp.async.cg.shared.global [%0], [%1], 16;" :: "r"(s), "l"(g));
}
__device__ __forceinline__ void cp_commit() {
    asm volatile("cp.async.commit_group;");
}
__device__ __forceinline__ void cp_wait0() {
    asm volatile("cp.async.wait_group 0;");
}
__device__ __forceinline__ uint32_t ldsu32(const __half* p) {
    return *reinterpret_cast<const uint32_t*>(p);
}
__device__ __forceinline__ uint32_t pack2(float lo, float hi) {
    __half2 h = __floats2half2_rn(lo, hi);
    return *reinterpret_cast<uint32_t*>(&h);
}
// fp16 mma, fp32 accumulate: D[16x8] += A[16x16] @ B[16x8]
__device__ __forceinline__ void mma_f16(float* c, const uint32_t* a, const uint32_t* b) {
    asm volatile(
        "mma.sync.aligned.m16n8k16.row.col.f32.f16.f16.f32 "
        "{%0,%1,%2,%3}, {%4,%5,%6,%7}, {%8,%9}, {%0,%1,%2,%3};"
        : "+f"(c[0]), "+f"(c[1]), "+f"(c[2]), "+f"(c[3])
        : "r"(a[0]), "r"(a[1]), "r"(a[2]), "r"(a[3]), "r"(b[0]), "r"(b[1]));
}

// ---------------------------------------------------------------------------
// FP16 tensor-core GEMM: C[M,N] = A[M,K](half) @ BT[N,K](half)^T + bias.
// BM=128, BN=256, BK=32, 8 warps, warp tile 64x64 (MT=4, NT=8).
// QKV mode: grid.z selects BT/C/bias; RoPE in epilogue for z<2; q scaled 1/8.
// OH: write half C; OF: write float C.
// ---------------------------------------------------------------------------
#define GM_STR    40                     // smem row stride (halves)
#define GM_A_ELE  (128 * GM_STR)         // 5120 halves
#define GM_B_ELE  (256 * GM_STR)         // 10240 halves
#define GM_STAGE  (GM_A_ELE + GM_B_ELE)
#define GM_SMEM_BYTES (2 * GM_STAGE * 2) // 61440

template<bool QKV, bool GELU, bool OH, bool OF>
__global__ __launch_bounds__(256)
void hgemm(int M, int N, int K,
           const __half* __restrict__ A,
           const __half* __restrict__ BT0, const __half* __restrict__ BT1,
           const __half* __restrict__ BT2,
           __half* __restrict__ Ch0, __half* __restrict__ Ch1,
           __half* __restrict__ Ch2,
           float* __restrict__ Cf,
           int ldc,
           const float* __restrict__ bias0, const float* __restrict__ bias1,
           const float* __restrict__ bias2,
           const float* __restrict__ tau)
{
    extern __shared__ __half hsm[];
    __half* As[2] = { hsm, hsm + GM_STAGE };
    __half* Bs[2] = { hsm + GM_A_ELE, hsm + GM_STAGE + GM_A_ELE };

    const __half* BT   = BT0;
    __half*       Ch   = Ch0;
    const float*  bias = bias0;
    bool rope = false;
    float oscale = 1.0f;
    if (QKV) {
        int z = blockIdx.z;
        if (z == 1)      { BT = BT1; Ch = Ch1; bias = bias1; }
        else if (z == 2) { BT = BT2; Ch = Ch2; bias = bias2; }
        rope = (z < 2);
        if (z == 0) oscale = 0.125f;   // fold 1/sqrt(64) into q
    }

    const int tid  = threadIdx.x;
    const int lane = tid & 31;
    const int warp = tid >> 5;
    const int grp  = lane >> 2;
    const int tig  = lane & 3;
    const int wm0  = (warp >> 2) * 64;
    const int wn0  = (warp & 3) * 64;

    const int m0 = blockIdx.y * 128;
    const int n0 = blockIdx.x * 256;

    float acc[4][8][4];
#pragma unroll
    for (int mi = 0; mi < 4; mi++)
#pragma unroll
        for (int ni = 0; ni < 8; ni++)
#pragma unroll
            for (int e = 0; e < 4; e++) acc[mi][ni][e] = 0.0f;

    auto load_stage = [&](int k0, int buf) {
        // A: 128 rows x 32 halves = 512 x 16B, 2/thread
#pragma unroll
        for (int l = 0; l < 2; l++) {
            int c = tid + l * 256;
            int m = c >> 2, ch = c & 3;
            cp16(smem_u32(&As[buf][m * GM_STR + ch * 8]),
                 A + (size_t)(m0 + m) * K + k0 + ch * 8);
        }
        // B: 256 rows x 32 halves = 1024 x 16B, 4/thread
#pragma unroll
        for (int l = 0; l < 4; l++) {
            int c = tid + l * 256;
            int n = c >> 2, ch = c & 3;
            cp16(smem_u32(&Bs[buf][n * GM_STR + ch * 8]),
                 BT + (size_t)(n0 + n) * K + k0 + ch * 8);
        }
        cp_commit();
    };

    auto compute_stage = [&](int buf) {
        const __half* as = As[buf];
        const __half* bs = Bs[buf];
#pragma unroll
        for (int kk = 0; kk < 32; kk += 16) {
            uint32_t af[4][4], bf[8][2];
#pragma unroll
            for (int mi = 0; mi < 4; mi++) {
                int r = wm0 + mi * 16 + grp;
                af[mi][0] = ldsu32(&as[(r    ) * GM_STR + kk + tig * 2    ]);
                af[mi][1] = ldsu32(&as[(r + 8) * GM_STR + kk + tig * 2    ]);
                af[mi][2] = ldsu32(&as[(r    ) * GM_STR + kk + tig * 2 + 8]);
                af[mi][3] = ldsu32(&as[(r + 8) * GM_STR + kk + tig * 2 + 8]);
            }
#pragma unroll
            for (int ni = 0; ni < 8; ni++) {
                int n = wn0 + ni * 8 + grp;
                bf[ni][0] = ldsu32(&bs[n * GM_STR + kk + tig * 2    ]);
                bf[ni][1] = ldsu32(&bs[n * GM_STR + kk + tig * 2 + 8]);
            }
#pragma unroll
            for (int mi = 0; mi < 4; mi++)
#pragma unroll
                for (int ni = 0; ni < 8; ni++)
                    mma_f16(acc[mi][ni], af[mi], bf[ni]);
        }
    };

    const int S = K / 32;
    load_stage(0, 0);
    for (int s = 0; s < S; s++) {
        cp_wait0();
        __syncthreads();
        if (s + 1 < S) load_stage((s + 1) * 32, (s + 1) & 1);
        compute_stage(s & 1);
        __syncthreads();
    }

    // ---- epilogue ----
#pragma unroll
    for (int mi = 0; mi < 4; mi++) {
#pragma unroll
        for (int h = 0; h < 2; h++) {
            int row = m0 + wm0 + mi * 16 + grp + h * 8;
            float t = 0.0f;
            if (QKV) t = tau[row];
#pragma unroll
            for (int ni = 0; ni < 8; ni++) {
                int gcol = n0 + wn0 + ni * 8 + 2 * tig;
                float v0 = acc[mi][ni][h * 2 + 0];
                float v1 = acc[mi][ni][h * 2 + 1];
                if (bias) { v0 += bias[gcol]; v1 += bias[gcol + 1]; }
                if (GELU) {
                    v0 = 0.5f * v0 * (1.0f + erff(v0 * 0.7071067811865475f));
                    v1 = 0.5f * v1 * (1.0f + erff(v1 * 0.7071067811865475f));
                }
                if (QKV && rope) {
                    int j = (gcol & 63) >> 1;
                    float inv = __expf(-0.28782313662425572f * (float)j);
                    float sn, cs;
                    sincosf(t * inv, &sn, &cs);
                    float r0 = v0 * cs - v1 * sn;
                    float r1 = v1 * cs + v0 * sn;
                    v0 = r0 * oscale; v1 = r1 * oscale;
                }
                if (OH) {
                    __half2 hv = __floats2half2_rn(v0, v1);
                    *(__half2*)(Ch + (size_t)row * ldc + gcol) = hv;
                }
                if (OF) {
                    *(float2*)(Cf + (size_t)row * ldc + gcol) = make_float2(v0, v1);
                }
            }
        }
    }
}

// ---------------------------------------------------------------------------
// Weight transpose + half: out[c][r] = half(in[r][c]). block (32,8).
// ---------------------------------------------------------------------------
__global__ void trh_kernel(const float* __restrict__ in, __half* __restrict__ out,
                           int R, int C)
{
    __shared__ float t[32][33];
    int c0 = blockIdx.x * 32, r0 = blockIdx.y * 32;
    int x = threadIdx.x, y = threadIdx.y;
#pragma unroll
    for (int i = 0; i < 4; i++) {
        int r = y * 4 + i;
        t[r][x] = in[(size_t)(r0 + r) * C + c0 + x];
    }
    __syncthreads();
#pragma unroll
    for (int i = 0; i < 4; i++) {
        int r = y * 4 + i;
        out[(size_t)(c0 + r) * R + r0 + x] = __float2half_rn(t[x][r]);
    }
}

// float -> half elementwise (n multiple of 4)
__global__ void f2h_kernel(const float4* __restrict__ in,
                           __half2* __restrict__ out, int n4)
{
    int i = blockIdx.x * 256 + threadIdx.x;
    if (i < n4) {
        float4 v = in[i];
        out[2 * i]     = __floats2half2_rn(v.x, v.y);
        out[2 * i + 1] = __floats2half2_rn(v.z, v.w);
    }
}

// ---------------------------------------------------------------------------
// FP16 flash attention: ctx = softmax(q_scaled K^T) V per (b,h).
// 128 q-rows/block, 8 warps (16 rows each). KV tiles of 128 keys.
// P kept in registers (S-accum layout == PV A-fragment layout).
// ---------------------------------------------------------------------------
#define FK_STR   72                       // K/Q smem row stride (halves)
#define FV_STR   136                      // Vt smem row stride (halves)
#define FK_BUF   (128 * FK_STR)           // 9216 halves
#define FA_SMEM_BYTES ((2 * FK_BUF + 64 * FV_STR) * 2)   // 54272

__global__ __launch_bounds__(256)
void flash_kernel(const __half* __restrict__ q, const __half* __restrict__ k,
                  const __half* __restrict__ v, __half* __restrict__ ctx)
{
    extern __shared__ __half fsm[];
    __half* Ks = fsm;                    // [2][128][72]
    __half* Vt = fsm + 2 * FK_BUF;       // [64][136]

    const int tid  = threadIdx.x;
    const int lane = tid & 31;
    const int warp = tid >> 5;
    const int grp  = lane >> 2;
    const int tig  = lane & 3;

    const int m0 = blockIdx.x * 128;
    const int bh = blockIdx.y;
    const int b  = bh >> 4;
    const int h  = bh & 15;

    const __half* qb = q + ((size_t)b * SEQ) * DMODEL + h * HEADDIM;
    const __half* kb = k + ((size_t)b * SEQ) * DMODEL + h * HEADDIM;
    const __half* vb = v + ((size_t)b * SEQ) * DMODEL + h * HEADDIM;

    // ---- stage Q tile through Ks buffer 0; extract A-fragments ----
#pragma unroll
    for (int l = 0; l < 4; l++) {
        int c = tid + l * 256;
        int r = c >> 3, ch = c & 7;
        cp16(smem_u32(&Ks[r * FK_STR + ch * 8]),
             qb + (size_t)(m0 + r) * DMODEL + ch * 8);
    }
    cp_commit(); cp_wait0(); __syncthreads();

    uint32_t aq[4][4];
    {
        const __half* qs = Ks + (warp * 16) * FK_STR;
#pragma unroll
        for (int kc = 0; kc < 4; kc++) {
            aq[kc][0] = ldsu32(&qs[(grp    ) * FK_STR + kc * 16 + tig * 2    ]);
            aq[kc][1] = ldsu32(&qs[(grp + 8) * FK_STR + kc * 16 + tig * 2    ]);
            aq[kc][2] = ldsu32(&qs[(grp    ) * FK_STR + kc * 16 + tig * 2 + 8]);
            aq[kc][3] = ldsu32(&qs[(grp + 8) * FK_STR + kc * 16 + tig * 2 + 8]);
        }
    }
    __syncthreads();   // done reading Q before K preload overwrites

    float o[8][4];
#pragma unroll
    for (int ni = 0; ni < 8; ni++)
#pragma unroll
        for (int e = 0; e < 4; e++) o[ni][e] = 0.0f;
    float mrun0 = -1e30f, mrun1 = -1e30f, lrun0 = 0.0f, lrun1 = 0.0f;

    // preload K tile 0
#pragma unroll
    for (int l = 0; l < 4; l++) {
        int c = tid + l * 256;
        int r = c >> 3, ch = c & 7;
        cp16(smem_u32(&Ks[r * FK_STR + ch * 8]),
             kb + (size_t)r * DMODEL + ch * 8);
    }
    cp_commit();

    const int NTILE = SEQ / 128;  // 16
    for (int t = 0; t < NTILE; t++) {
        // V loads for this tile (half2, coalesced)
        __half2 vr2[16];
#pragma unroll
        for (int i = 0; i < 16; i++) {
            int c = tid + i * 256;
            int d2 = c & 31, kk = c >> 5;
            vr2[i] = *(const __half2*)(vb + (size_t)(t * 128 + kk) * DMODEL + d2 * 2);
        }

        cp_wait0();
        __syncthreads();   // K tile t ready; Vt from prev tile consumed

        if (t + 1 < NTILE) {
            __half* kd = Ks + ((t + 1) & 1) * FK_BUF;
#pragma unroll
            for (int l = 0; l < 4; l++) {
                int c = tid + l * 256;
                int r = c >> 3, ch = c & 7;
                cp16(smem_u32(&kd[r * FK_STR + ch * 8]),
                     kb + (size_t)((t + 1) * 128 + r) * DMODEL + ch * 8);
            }
            cp_commit();
        }

        // ---- S = Q @ K^T (q pre-scaled by 1/8) ----
        const __half* kcur = Ks + (t & 1) * FK_BUF;
        float sacc[16][4];
#pragma unroll
        for (int ni = 0; ni < 16; ni++)
#pragma unroll
            for (int e = 0; e < 4; e++) sacc[ni][e] = 0.0f;

#pragma unroll
        for (int ni = 0; ni < 16; ni++) {
            const __half* kr = kcur + (ni * 8 + grp) * FK_STR;
#pragma unroll
            for (int kc = 0; kc < 4; kc++) {
                uint32_t bf[2];
                bf[0] = ldsu32(&kr[kc * 16 + tig * 2    ]);
                bf[1] = ldsu32(&kr[kc * 16 + tig * 2 + 8]);
                mma_f16(sacc[ni], aq[kc], bf);
            }
        }

        // ---- online softmax ----
        float tmax0 = -1e30f, tmax1 = -1e30f;
#pragma unroll
        for (int ni = 0; ni < 16; ni++) {
            tmax0 = fmaxf(tmax0, fmaxf(sacc[ni][0], sacc[ni][1]));
            tmax1 = fmaxf(tmax1, fmaxf(sacc[ni][2], sacc[ni][3]));
        }
        tmax0 = fmaxf(tmax0, __shfl_xor_sync(0xffffffffu, tmax0, 1));
        tmax0 = fmaxf(tmax0, __shfl_xor_sync(0xffffffffu, tmax0, 2));
        tmax1 = fmaxf(tmax1, __shfl_xor_sync(0xffffffffu, tmax1, 1));
        tmax1 = fmaxf(tmax1, __shfl_xor_sync(0xffffffffu, tmax1, 2));

        float nm0 = fmaxf(mrun0, tmax0);
        float nm1 = fmaxf(mrun1, tmax1);
        float sc0 = __expf(mrun0 - nm0);
        float sc1 = __expf(mrun1 - nm1);
        mrun0 = nm0; mrun1 = nm1;

        float sum0 = 0.0f, sum1 = 0.0f;
#pragma unroll
        for (int ni = 0; ni < 16; ni++) {
            sacc[ni][0] = __expf(sacc[ni][0] - nm0);
            sacc[ni][1] = __expf(sacc[ni][1] - nm0);
            sacc[ni][2] = __expf(sacc[ni][2] - nm1);
            sacc[ni][3] = __expf(sacc[ni][3] - nm1);
            sum0 += sacc[ni][0] + sacc[ni][1];
            sum1 += sacc[ni][2] + sacc[ni][3];
        }
        sum0 += __shfl_xor_sync(0xffffffffu, sum0, 1);
        sum0 += __shfl_xor_sync(0xffffffffu, sum0, 2);
        sum1 += __shfl_xor_sync(0xffffffffu, sum1, 1);
        sum1 += __shfl_xor_sync(0xffffffffu, sum1, 2);
        lrun0 = lrun0 * sc0 + sum0;
        lrun1 = lrun1 * sc1 + sum1;

#pragma unroll
        for (int ni = 0; ni < 8; ni++) {
            o[ni][0] *= sc0; o[ni][1] *= sc0;
            o[ni][2] *= sc1; o[ni][3] *= sc1;
        }

        // ---- pack P into A-fragments (pure register shuffle-free reuse) ----
        uint32_t pA[8][4];
#pragma unroll
        for (int kc = 0; kc < 8; kc++) {
            pA[kc][0] = pack2(sacc[2 * kc    ][0], sacc[2 * kc    ][1]);
            pA[kc][1] = pack2(sacc[2 * kc    ][2], sacc[2 * kc    ][3]);
            pA[kc][2] = pack2(sacc[2 * kc + 1][0], sacc[2 * kc + 1][1]);
            pA[kc][3] = pack2(sacc[2 * kc + 1][2], sacc[2 * kc + 1][3]);
        }

        // ---- store V transposed into Vt ----
#pragma unroll
        for (int i = 0; i < 16; i++) {
            int c = tid + i * 256;
            int d2 = c & 31, kk = c >> 5;
            Vt[(d2 * 2    ) * FV_STR + kk] = __low2half(vr2[i]);
            Vt[(d2 * 2 + 1) * FV_STR + kk] = __high2half(vr2[i]);
        }
        __syncthreads();

        // ---- O += P @ V ----
#pragma unroll
        for (int kc = 0; kc < 8; kc++) {
#pragma unroll
            for (int ni = 0; ni < 8; ni++) {
                const __half* vrow = Vt + (ni * 8 + grp) * FV_STR;
                uint32_t bb[2];
                bb[0] = ldsu32(&vrow[kc * 16 + tig * 2    ]);
                bb[1] = ldsu32(&vrow[kc * 16 + tig * 2 + 8]);
                mma_f16(o[ni], pA[kc], bb);
            }
        }
    }

    // ---- normalize, write ctx (half) ----
    float inv0 = 1.0f / lrun0;
    float inv1 = 1.0f / lrun1;
    int r0 = m0 + warp * 16 + grp;
    __half* cb = ctx + ((size_t)b * SEQ) * DMODEL + h * HEADDIM;
#pragma unroll
    for (int ni = 0; ni < 8; ni++) {
        int col = ni * 8 + 2 * tig;
        *(__half2*)(cb + (size_t)(r0    ) * DMODEL + col) =
            __floats2half2_rn(o[ni][0] * inv0, o[ni][1] * inv0);
        *(__half2*)(cb + (size_t)(r0 + 8) * DMODEL + col) =
            __floats2half2_rn(o[ni][2] * inv1, o[ni][3] * inv1);
    }
}

// ---------------------------------------------------------------------------
// Fused residual + LayerNorm; writes fp32 out and (optionally) half outh.
// ---------------------------------------------------------------------------
__global__ __launch_bounds__(256)
void ln_kernel(const float* __restrict__ a, const float* __restrict__ b,
               const float* __restrict__ g, const float* __restrict__ be,
               float* __restrict__ out, __half* __restrict__ outh)
{
    const int D = DMODEL;
    size_t row = blockIdx.x;
    const float* pa = a + row * D;
    const float* pb = b + row * D;
    int tid = threadIdx.x;
    __shared__ float red[256];

    float x[4];
    float s = 0.0f;
#pragma unroll
    for (int i = 0; i < 4; i++) {
        int c = tid + i * 256;
        x[i] = pa[c] + pb[c];
        s += x[i];
    }
    red[tid] = s;
    __syncthreads();
    for (int t = 128; t > 0; t >>= 1) {
        if (tid < t) red[tid] += red[tid + t];
        __syncthreads();
    }
    float mu = red[0] * (1.0f / D);
    __syncthreads();

    float v = 0.0f;
#pragma unroll
    for (int i = 0; i < 4; i++) {
        float d = x[i] - mu;
        v += d * d;
    }
    red[tid] = v;
    __syncthreads();
    for (int t = 128; t > 0; t >>= 1) {
        if (tid < t) red[tid] += red[tid + t];
        __syncthreads();
    }
    float var = red[0] * (1.0f / D);
    float r = rsqrtf(var + 1e-5f);
#pragma unroll
    for (int i = 0; i < 4; i++) {
        int c = tid + i * 256;
        float y = (x[i] - mu) * r * g[c] + be[c];
        out[row * D + c] = y;
        if (outh) outh[row * D + c] = __float2half_rn(y);
    }
}

// ---------------------------------------------------------------------------
// Host-side launch
// ---------------------------------------------------------------------------
static void* symptr_v(const void* sym)
{
    void* p = nullptr;
    cudaGetSymbolAddress(&p, sym);
    return p;
}

extern "C" void kernel_launch(void* const* d_in, const int* in_sizes, int n_in,
                              void* d_out, int out_size)
{
    const float* src = (const float*)d_in[0];
    const float* tau = (const float*)d_in[1];
    const float* Wq  = (const float*)d_in[2];
    const float* bq  = (const float*)d_in[3];
    const float* Wk  = (const float*)d_in[4];
    const float* bk  = (const float*)d_in[5];
    const float* Wv  = (const float*)d_in[6];
    const float* bv  = (const float*)d_in[7];
    const float* Wo  = (const float*)d_in[8];
    const float* bo  = (const float*)d_in[9];
    const float* W1  = (const float*)d_in[10];
    const float* b1  = (const float*)d_in[11];
    const float* W2  = (const float*)d_in[12];
    const float* b2  = (const float*)d_in[13];
    const float* g1  = (const float*)d_in[14];
    const float* be1 = (const float*)d_in[15];
    const float* g2  = (const float*)d_in[16];
    const float* be2 = (const float*)d_in[17];
    float* out = (float*)d_out;

    __half* srch = (__half*)symptr_v(g_srch);
    __half* qh   = (__half*)symptr_v(g_qh);
    __half* kh   = (__half*)symptr_v(g_kh);
    __half* vh   = (__half*)symptr_v(g_vh);
    __half* ctxh = (__half*)symptr_v(g_ctxh);
    __half* h1h  = (__half*)symptr_v(g_h1h);
    __half* f1h  = (__half*)symptr_v(g_f1h);
    float*  ao   = (float*)symptr_v(g_ao);
    float*  h1f  = (float*)symptr_v(g_h1f);
    float*  f2   = (float*)symptr_v(g_f2);
    __half* wqT  = (__half*)symptr_v(g_wqT);
    __half* wkT  = (__half*)symptr_v(g_wkT);
    __half* wvT  = (__half*)symptr_v(g_wvT);
    __half* woT  = (__half*)symptr_v(g_woT);
    __half* w1T  = (__half*)symptr_v(g_w1T);
    __half* w2T  = (__half*)symptr_v(g_w2T);

    cudaFuncSetAttribute(flash_kernel,
                         cudaFuncAttributeMaxDynamicSharedMemorySize, FA_SMEM_BYTES);
    cudaFuncSetAttribute(hgemm<true,  false, true,  false>,
                         cudaFuncAttributeMaxDynamicSharedMemorySize, GM_SMEM_BYTES);
    cudaFuncSetAttribute(hgemm<false, false, false, true>,
                         cudaFuncAttributeMaxDynamicSharedMemorySize, GM_SMEM_BYTES);
    cudaFuncSetAttribute(hgemm<false, true,  true,  false>,
                         cudaFuncAttributeMaxDynamicSharedMemorySize, GM_SMEM_BYTES);

    // ---- prep: transpose weights to half [N][K]; convert src to half ----
    dim3 trb(32, 8);
    trh_kernel<<<dim3(DMODEL / 32, DMODEL / 32), trb>>>(Wq, wqT, DMODEL, DMODEL);
    trh_kernel<<<dim3(DMODEL / 32, DMODEL / 32), trb>>>(Wk, wkT, DMODEL, DMODEL);
    trh_kernel<<<dim3(DMODEL / 32, DMODEL / 32), trb>>>(Wv, wvT, DMODEL, DMODEL);
    trh_kernel<<<dim3(DMODEL / 32, DMODEL / 32), trb>>>(Wo, woT, DMODEL, DMODEL);
    trh_kernel<<<dim3(DFF / 32, DMODEL / 32), trb>>>(W1, w1T, DMODEL, DFF);
    trh_kernel<<<dim3(DMODEL / 32, DFF / 32), trb>>>(W2, w2T, DFF, DMODEL);
    {
        int n4 = TOKENS * DMODEL / 4;
        f2h_kernel<<<(n4 + 255) / 256, 256>>>((const float4*)src, (__half2*)srch, n4);
    }

    // ---- QKV (+RoPE, q pre-scaled) ----
    hgemm<true, false, true, false>
        <<<dim3(DMODEL / 256, TOKENS / 128, 3), 256, GM_SMEM_BYTES>>>(
        TOKENS, DMODEL, DMODEL, srch, wqT, wkT, wvT,
        qh, kh, vh, nullptr, DMODEL, bq, bk, bv, tau);

    // ---- flash attention -> ctx (half) ----
    flash_kernel<<<dim3(SEQ / 128, BATCH * NHEADS), 256, FA_SMEM_BYTES>>>(
        qh, kh, vh, ctxh);

    // ---- output projection -> ao (fp32) ----
    hgemm<false, false, false, true>
        <<<dim3(DMODEL / 256, TOKENS / 128, 1), 256, GM_SMEM_BYTES>>>(
        TOKENS, DMODEL, DMODEL, ctxh, woT, nullptr, nullptr,
        nullptr, nullptr, nullptr, ao, DMODEL, bo, nullptr, nullptr, nullptr);

    // ---- LN1 -> h1 (fp32 + half) ----
    ln_kernel<<<TOKENS, 256>>>(src, ao, g1, be1, h1f, h1h);

    // ---- FFN1 (GELU) -> f1 (half) ----
    hgemm<false, true, true, false>
        <<<dim3(DFF / 256, TOKENS / 128, 1), 256, GM_SMEM_BYTES>>>(
        TOKENS, DFF, DMODEL, h1h, w1T, nullptr, nullptr,
        f1h, nullptr, nullptr, nullptr, DFF, b1, nullptr, nullptr, nullptr);

    // ---- FFN2 -> f2 (fp32) ----
    hgemm<false, false, false, true>
        <<<dim3(DMODEL / 256, TOKENS / 128, 1), 256, GM_SMEM_BYTES>>>(
        TOKENS, DMODEL, DFF, f1h, w2T, nullptr, nullptr,
        nullptr, nullptr, nullptr, f2, DMODEL, b2, nullptr, nullptr, nullptr);

    // ---- LN2 -> out ----
    ln_kernel<<<TOKENS, 256>>>(h1f, f2, g2, be2, out, nullptr);

    (void)in_sizes; (void)n_in; (void)out_size;
}

// round 7
// speedup vs baseline: 5.8529x; 1.1822x over previous
#include <cuda_runtime.h>
#include <cuda_fp16.h>
#include <math.h>
#include <cstdint>

// ---------------------------------------------------------------------------
// Problem constants
// ---------------------------------------------------------------------------
#define BATCH   2
#define SEQ     2048
#define DMODEL  1024
#define NHEADS  16
#define HEADDIM 64
#define DFF     4096
#define TOKENS  (BATCH * SEQ)          // 4096

// ---------------------------------------------------------------------------
// Scratch (static device allocations)
// ---------------------------------------------------------------------------
__device__ __half g_srch[TOKENS * DMODEL];
__device__ __half g_qh  [TOKENS * DMODEL];
__device__ __half g_kh  [TOKENS * DMODEL];
__device__ __half g_vh  [TOKENS * DMODEL];
__device__ __half g_ctxh[TOKENS * DMODEL];
__device__ __half g_h1h [TOKENS * DMODEL];
__device__ __half g_f1h [(size_t)TOKENS * DFF];
__device__ float  g_ao  [TOKENS * DMODEL];
__device__ float  g_h1f [TOKENS * DMODEL];
__device__ float  g_f2  [TOKENS * DMODEL];
// half weights, natural [K][N] layout
__device__ __half g_wqH[DMODEL * DMODEL];
__device__ __half g_wkH[DMODEL * DMODEL];
__device__ __half g_wvH[DMODEL * DMODEL];
__device__ __half g_woH[DMODEL * DMODEL];
__device__ __half g_w1H[(size_t)DMODEL * DFF];
__device__ __half g_w2H[(size_t)DFF * DMODEL];

// ---------------------------------------------------------------------------
// PTX helpers
// ---------------------------------------------------------------------------
__device__ __forceinline__ uint32_t smem_u32(const void* p) {
    return (uint32_t)__cvta_generic_to_shared(p);
}
__device__ __forceinline__ void cp16(uint32_t s, const void* g) {
    asm volatile("cp.async.cg.shared.global [%0], [%1], 16;" :: "r"(s), "l"(g));
}
__device__ __forceinline__ void cp_commit() {
    asm volatile("cp.async.commit_group;");
}
template<int N>
__device__ __forceinline__ void cp_wait() {
    asm volatile("cp.async.wait_group %0;" :: "n"(N));
}
__device__ __forceinline__ uint32_t ldsu32(const __half* p) {
    return *reinterpret_cast<const uint32_t*>(p);
}
__device__ __forceinline__ uint32_t pack2(float lo, float hi) {
    __half2 h = __floats2half2_rn(lo, hi);
    return *reinterpret_cast<uint32_t*>(&h);
}
__device__ __forceinline__ void ldsm4(uint32_t addr, uint32_t* r) {
    asm volatile("ldmatrix.sync.aligned.m8n8.x4.shared.b16 {%0,%1,%2,%3}, [%4];"
        : "=r"(r[0]), "=r"(r[1]), "=r"(r[2]), "=r"(r[3]) : "r"(addr));
}
__device__ __forceinline__ void ldsm4t(uint32_t addr, uint32_t* r) {
    asm volatile("ldmatrix.sync.aligned.m8n8.x4.trans.shared.b16 {%0,%1,%2,%3}, [%4];"
        : "=r"(r[0]), "=r"(r[1]), "=r"(r[2]), "=r"(r[3]) : "r"(addr));
}
// fp16 mma, fp32 accumulate
__device__ __forceinline__ void mma_f16(float* c, const uint32_t* a, const uint32_t* b) {
    asm volatile(
        "mma.sync.aligned.m16n8k16.row.col.f32.f16.f16.f32 "
        "{%0,%1,%2,%3}, {%4,%5,%6,%7}, {%8,%9}, {%0,%1,%2,%3};"
        : "+f"(c[0]), "+f"(c[1]), "+f"(c[2]), "+f"(c[3])
        : "r"(a[0]), "r"(a[1]), "r"(a[2]), "r"(a[3]), "r"(b[0]), "r"(b[1]));
}

// ---------------------------------------------------------------------------
// FP16 GEMM: C[M,N] = A[M,K](half) @ W[K,N](half) + bias.
// BM=128, BN=256, BK=32, 8 warps (warp tile 64x64). 4-stage cp.async,
// one sync/stage. A frags: ldmatrix; B frags: ldmatrix.trans (W natural).
// QKV: grid.z selects W/C/bias, RoPE for z<2, q scaled 1/8.
// ---------------------------------------------------------------------------
#define GM_ASTR 40                       // A smem row stride (halves)
#define GM_BSTR 264                      // B smem row stride (halves)
#define GM_AH   (128 * GM_ASTR)          // 5120 halves
#define GM_BH   (32 * GM_BSTR)           // 8448 halves
#define GM_STG  (GM_AH + GM_BH)          // 13568 halves / stage
#define GM_SMEM_BYTES (4 * GM_STG * 2)   // 108544

template<bool QKV, bool GELU, bool OH, bool OF>
__global__ __launch_bounds__(256)
void hgemm(int M, int N, int K,
           const __half* __restrict__ A,
           const __half* __restrict__ W0, const __half* __restrict__ W1_,
           const __half* __restrict__ W2_,
           __half* __restrict__ Ch0, __half* __restrict__ Ch1,
           __half* __restrict__ Ch2,
           float* __restrict__ Cf,
           int ldc,
           const float* __restrict__ bias0, const float* __restrict__ bias1,
           const float* __restrict__ bias2,
           const float* __restrict__ tau)
{
    extern __shared__ __half hsm[];

    const __half* W    = W0;
    __half*       Ch   = Ch0;
    const float*  bias = bias0;
    bool rope = false;
    float oscale = 1.0f;
    if (QKV) {
        int z = blockIdx.z;
        if (z == 1)      { W = W1_; Ch = Ch1; bias = bias1; }
        else if (z == 2) { W = W2_; Ch = Ch2; bias = bias2; }
        rope = (z < 2);
        if (z == 0) oscale = 0.125f;
    }

    const int tid  = threadIdx.x;
    const int lane = tid & 31;
    const int warp = tid >> 5;
    const int grp  = lane >> 2;
    const int tig  = lane & 3;
    const int wm0  = (warp >> 2) * 64;
    const int wn0  = (warp & 3) * 64;
    const int m0 = blockIdx.y * 128;
    const int n0 = blockIdx.x * 256;

    const uint32_t sbase = smem_u32(hsm);
    // per-lane ldmatrix offsets (bytes within a stage's A / B tile)
    const uint32_t aOff = ((wm0 + (lane & 15)) * GM_ASTR + (lane >> 4) * 8) * 2;
    const int g8 = lane >> 3, r8 = lane & 7;
    const uint32_t bOff = (((g8 & 1) * 8 + r8) * GM_BSTR + wn0 + (g8 >> 1) * 8) * 2;

    float acc[4][8][4];
#pragma unroll
    for (int mi = 0; mi < 4; mi++)
#pragma unroll
        for (int ni = 0; ni < 8; ni++)
#pragma unroll
            for (int e = 0; e < 4; e++) acc[mi][ni][e] = 0.0f;

    auto load_stage = [&](int s) {
        uint32_t ab = sbase + (s & 3) * GM_STG * 2;
        uint32_t bb = ab + GM_AH * 2;
        int k0 = s * 32;
        // A: 128 rows x 32 halves = 512 chunks, 2/thread
#pragma unroll
        for (int l = 0; l < 2; l++) {
            int c = tid + l * 256;
            int m = c >> 2, ch = c & 3;
            cp16(ab + (m * GM_ASTR + ch * 8) * 2,
                 A + (size_t)(m0 + m) * K + k0 + ch * 8);
        }
        // B (W rows k): 32 rows x 256 halves = 1024 chunks, 4/thread
#pragma unroll
        for (int l = 0; l < 4; l++) {
            int c = tid + l * 256;
            int kk = c >> 5, nq = c & 31;
            cp16(bb + (kk * GM_BSTR + nq * 8) * 2,
                 W + (size_t)(k0 + kk) * N + n0 + nq * 8);
        }
        cp_commit();
    };

    auto compute_stage = [&](int s) {
        uint32_t ab = sbase + (s & 3) * GM_STG * 2;
        uint32_t bb = ab + GM_AH * 2;
#pragma unroll
        for (int kk = 0; kk < 32; kk += 16) {
            uint32_t af[4][4], bf[8][2];
#pragma unroll
            for (int mi = 0; mi < 4; mi++)
                ldsm4(ab + aOff + (mi * 16 * GM_ASTR + kk) * 2, af[mi]);
#pragma unroll
            for (int nip = 0; nip < 4; nip++)
                ldsm4t(bb + bOff + (kk * GM_BSTR + nip * 16) * 2, &bf[2 * nip][0]);
#pragma unroll
            for (int mi = 0; mi < 4; mi++)
#pragma unroll
                for (int ni = 0; ni < 8; ni++)
                    mma_f16(acc[mi][ni], af[mi], bf[ni]);
        }
    };

    const int S = K / 32;
    load_stage(0); load_stage(1); load_stage(2);
    for (int s = 0; s < S; s++) {
        int pend = S - 1 - s;
        if (pend >= 2)      cp_wait<2>();
        else if (pend == 1) cp_wait<1>();
        else                cp_wait<0>();
        __syncthreads();
        if (s + 3 < S) load_stage(s + 3);
        compute_stage(s);
    }

    // ---- epilogue ----
#pragma unroll
    for (int mi = 0; mi < 4; mi++) {
#pragma unroll
        for (int h = 0; h < 2; h++) {
            int row = m0 + wm0 + mi * 16 + grp + h * 8;
            float t = 0.0f;
            if (QKV) t = tau[row];
#pragma unroll
            for (int ni = 0; ni < 8; ni++) {
                int gcol = n0 + wn0 + ni * 8 + 2 * tig;
                float v0 = acc[mi][ni][h * 2 + 0];
                float v1 = acc[mi][ni][h * 2 + 1];
                if (bias) { v0 += bias[gcol]; v1 += bias[gcol + 1]; }
                if (GELU) {
                    v0 = 0.5f * v0 * (1.0f + erff(v0 * 0.7071067811865475f));
                    v1 = 0.5f * v1 * (1.0f + erff(v1 * 0.7071067811865475f));
                }
                if (QKV && rope) {
                    int j = (gcol & 63) >> 1;
                    float inv = __expf(-0.28782313662425572f * (float)j);
                    float sn, cs;
                    sincosf(t * inv, &sn, &cs);
                    float r0 = v0 * cs - v1 * sn;
                    float r1 = v1 * cs + v0 * sn;
                    v0 = r0 * oscale; v1 = r1 * oscale;
                }
                if (OH) {
                    *(__half2*)(Ch + (size_t)row * ldc + gcol) =
                        __floats2half2_rn(v0, v1);
                }
                if (OF) {
                    *(float2*)(Cf + (size_t)row * ldc + gcol) = make_float2(v0, v1);
                }
            }
        }
    }
}

// ---------------------------------------------------------------------------
// float -> half streaming convert (n multiple of 4)
// ---------------------------------------------------------------------------
__global__ void f2h_kernel(const float4* __restrict__ in,
                           __half2* __restrict__ out, int n4)
{
    int i = blockIdx.x * 256 + threadIdx.x;
    if (i < n4) {
        float4 v = in[i];
        out[2 * i]     = __floats2half2_rn(v.x, v.y);
        out[2 * i + 1] = __floats2half2_rn(v.z, v.w);
    }
}

// ---------------------------------------------------------------------------
// FP16 flash attention with ldmatrix + cp.async K/V double buffers.
// 128 q-rows/block, 8 warps. KV tiles of 128 keys.
// ---------------------------------------------------------------------------
#define FK_STR  72                        // row stride (halves) for K/V/Q tiles
#define FT_H    (128 * FK_STR)            // 9216 halves per tile buffer
#define FA_SMEM_BYTES (4 * FT_H * 2)      // 73728: Ks[2], Vs[2]

__global__ __launch_bounds__(256)
void flash_kernel(const __half* __restrict__ q, const __half* __restrict__ k,
                  const __half* __restrict__ v, __half* __restrict__ ctx)
{
    extern __shared__ __half fsm[];
    const uint32_t sbase = smem_u32(fsm);
    // layout (halves): Ks0 @0, Ks1 @FT_H, Vs0 @2*FT_H, Vs1 @3*FT_H

    const int tid  = threadIdx.x;
    const int lane = tid & 31;
    const int warp = tid >> 5;
    const int grp  = lane >> 2;
    const int tig  = lane & 3;
    const int g8 = lane >> 3, r8 = lane & 7;

    const int m0 = blockIdx.x * 128;
    const int bh = blockIdx.y;
    const int b  = bh >> 4;
    const int h  = bh & 15;

    const __half* qb = q + ((size_t)b * SEQ) * DMODEL + h * HEADDIM;
    const __half* kb = k + ((size_t)b * SEQ) * DMODEL + h * HEADDIM;
    const __half* vb = v + ((size_t)b * SEQ) * DMODEL + h * HEADDIM;

    // per-lane ldmatrix offsets (bytes within a tile buffer)
    const uint32_t qOff = ((warp * 16 + (lane & 15)) * FK_STR + (lane >> 4) * 8) * 2;
    const uint32_t kOff = ((r8 + (g8 >> 1) * 8) * FK_STR + (g8 & 1) * 8) * 2;
    const uint32_t vOff = ((r8 + (g8 & 1) * 8) * FK_STR + (g8 >> 1) * 8) * 2;

    // ---- stage Q tile into Ks0, extract A-fragments ----
#pragma unroll
    for (int l = 0; l < 4; l++) {
        int c = tid + l * 256;
        int r = c >> 3, ch = c & 7;
        cp16(sbase + (r * FK_STR + ch * 8) * 2,
             qb + (size_t)(m0 + r) * DMODEL + ch * 8);
    }
    cp_commit(); cp_wait<0>(); __syncthreads();

    uint32_t aq[4][4];
#pragma unroll
    for (int kc = 0; kc < 4; kc++)
        ldsm4(sbase + qOff + kc * 32, aq[kc]);
    __syncthreads();   // all warps done with Ks0 before K preload

    float o[8][4];
#pragma unroll
    for (int ni = 0; ni < 8; ni++)
#pragma unroll
        for (int e = 0; e < 4; e++) o[ni][e] = 0.0f;
    float mrun0 = -1e30f, mrun1 = -1e30f, lrun0 = 0.0f, lrun1 = 0.0f;

    auto load_kv = [&](int t) {
        uint32_t kd = sbase + (t & 1) * FT_H * 2;
        uint32_t vd = sbase + (2 + (t & 1)) * FT_H * 2;
#pragma unroll
        for (int l = 0; l < 4; l++) {
            int c = tid + l * 256;
            int r = c >> 3, ch = c & 7;
            uint32_t so = (r * FK_STR + ch * 8) * 2;
            size_t  go = (size_t)(t * 128 + r) * DMODEL + ch * 8;
            cp16(kd + so, kb + go);
            cp16(vd + so, vb + go);
        }
        cp_commit();
    };

    load_kv(0);

    const int NTILE = SEQ / 128;  // 16
    for (int t = 0; t < NTILE; t++) {
        cp_wait<0>();
        __syncthreads();                       // tile t visible; t-1 consumed
        if (t + 1 < NTILE) load_kv(t + 1);

        uint32_t kbuf = sbase + (t & 1) * FT_H * 2;
        uint32_t vbuf = sbase + (2 + (t & 1)) * FT_H * 2;

        // ---- S = Q @ K^T (q pre-scaled 1/8) ----
        float sacc[16][4];
#pragma unroll
        for (int ni = 0; ni < 16; ni++)
#pragma unroll
            for (int e = 0; e < 4; e++) sacc[ni][e] = 0.0f;

#pragma unroll
        for (int kc = 0; kc < 4; kc++) {
#pragma unroll
            for (int nip = 0; nip < 8; nip++) {
                uint32_t bf[4];
                ldsm4(kbuf + kOff + (nip * 16 * FK_STR + kc * 16) * 2, bf);
                mma_f16(sacc[2 * nip    ], aq[kc], &bf[0]);
                mma_f16(sacc[2 * nip + 1], aq[kc], &bf[2]);
            }
        }

        // ---- online softmax ----
        float tmax0 = -1e30f, tmax1 = -1e30f;
#pragma unroll
        for (int ni = 0; ni < 16; ni++) {
            tmax0 = fmaxf(tmax0, fmaxf(sacc[ni][0], sacc[ni][1]));
            tmax1 = fmaxf(tmax1, fmaxf(sacc[ni][2], sacc[ni][3]));
        }
        tmax0 = fmaxf(tmax0, __shfl_xor_sync(0xffffffffu, tmax0, 1));
        tmax0 = fmaxf(tmax0, __shfl_xor_sync(0xffffffffu, tmax0, 2));
        tmax1 = fmaxf(tmax1, __shfl_xor_sync(0xffffffffu, tmax1, 1));
        tmax1 = fmaxf(tmax1, __shfl_xor_sync(0xffffffffu, tmax1, 2));

        float nm0 = fmaxf(mrun0, tmax0);
        float nm1 = fmaxf(mrun1, tmax1);
        float sc0 = __expf(mrun0 - nm0);
        float sc1 = __expf(mrun1 - nm1);
        mrun0 = nm0; mrun1 = nm1;

        float sum0 = 0.0f, sum1 = 0.0f;
#pragma unroll
        for (int ni = 0; ni < 16; ni++) {
            sacc[ni][0] = __expf(sacc[ni][0] - nm0);
            sacc[ni][1] = __expf(sacc[ni][1] - nm0);
            sacc[ni][2] = __expf(sacc[ni][2] - nm1);
            sacc[ni][3] = __expf(sacc[ni][3] - nm1);
            sum0 += sacc[ni][0] + sacc[ni][1];
            sum1 += sacc[ni][2] + sacc[ni][3];
        }
        sum0 += __shfl_xor_sync(0xffffffffu, sum0, 1);
        sum0 += __shfl_xor_sync(0xffffffffu, sum0, 2);
        sum1 += __shfl_xor_sync(0xffffffffu, sum1, 1);
        sum1 += __shfl_xor_sync(0xffffffffu, sum1, 2);
        lrun0 = lrun0 * sc0 + sum0;
        lrun1 = lrun1 * sc1 + sum1;

#pragma unroll
        for (int ni = 0; ni < 8; ni++) {
            o[ni][0] *= sc0; o[ni][1] *= sc0;
            o[ni][2] *= sc1; o[ni][3] *= sc1;
        }

        // ---- pack P into A-fragments (registers only) ----
        uint32_t pA[8][4];
#pragma unroll
        for (int kc = 0; kc < 8; kc++) {
            pA[kc][0] = pack2(sacc[2 * kc    ][0], sacc[2 * kc    ][1]);
            pA[kc][1] = pack2(sacc[2 * kc    ][2], sacc[2 * kc    ][3]);
            pA[kc][2] = pack2(sacc[2 * kc + 1][0], sacc[2 * kc + 1][1]);
            pA[kc][3] = pack2(sacc[2 * kc + 1][2], sacc[2 * kc + 1][3]);
        }

        // ---- O += P @ V (V natural [key][d], trans ldmatrix) ----
#pragma unroll
        for (int kc = 0; kc < 8; kc++) {
#pragma unroll
            for (int nip = 0; nip < 4; nip++) {
                uint32_t bb[4];
                ldsm4t(vbuf + vOff + (kc * 16 * FK_STR + nip * 16) * 2, bb);
                mma_f16(o[2 * nip    ], pA[kc], &bb[0]);
                mma_f16(o[2 * nip + 1], pA[kc], &bb[2]);
            }
        }
    }

    // ---- normalize, write ctx (half) ----
    float inv0 = 1.0f / lrun0;
    float inv1 = 1.0f / lrun1;
    int r0 = m0 + warp * 16 + grp;
    __half* cb = ctx + ((size_t)b * SEQ) * DMODEL + h * HEADDIM;
#pragma unroll
    for (int ni = 0; ni < 8; ni++) {
        int col = ni * 8 + 2 * tig;
        *(__half2*)(cb + (size_t)(r0    ) * DMODEL + col) =
            __floats2half2_rn(o[ni][0] * inv0, o[ni][1] * inv0);
        *(__half2*)(cb + (size_t)(r0 + 8) * DMODEL + col) =
            __floats2half2_rn(o[ni][2] * inv1, o[ni][3] * inv1);
    }
}

// ---------------------------------------------------------------------------
// Fused residual + LayerNorm; fp32 out + optional half out.
// ---------------------------------------------------------------------------
__global__ __launch_bounds__(256)
void ln_kernel(const float* __restrict__ a, const float* __restrict__ b,
               const float* __restrict__ g, const float* __restrict__ be,
               float* __restrict__ out, __half* __restrict__ outh)
{
    const int D = DMODEL;
    size_t row = blockIdx.x;
    const float* pa = a + row * D;
    const float* pb = b + row * D;
    int tid = threadIdx.x;
    __shared__ float red[256];

    float x[4];
    float s = 0.0f;
#pragma unroll
    for (int i = 0; i < 4; i++) {
        int c = tid + i * 256;
        x[i] = pa[c] + pb[c];
        s += x[i];
    }
    red[tid] = s;
    __syncthreads();
    for (int t = 128; t > 0; t >>= 1) {
        if (tid < t) red[tid] += red[tid + t];
        __syncthreads();
    }
    float mu = red[0] * (1.0f / D);
    __syncthreads();

    float v = 0.0f;
#pragma unroll
    for (int i = 0; i < 4; i++) {
        float d = x[i] - mu;
        v += d * d;
    }
    red[tid] = v;
    __syncthreads();
    for (int t = 128; t > 0; t >>= 1) {
        if (tid < t) red[tid] += red[tid + t];
        __syncthreads();
    }
    float var = red[0] * (1.0f / D);
    float r = rsqrtf(var + 1e-5f);
#pragma unroll
    for (int i = 0; i < 4; i++) {
        int c = tid + i * 256;
        float y = (x[i] - mu) * r * g[c] + be[c];
        out[row * D + c] = y;
        if (outh) outh[row * D + c] = __float2half_rn(y);
    }
}

// ---------------------------------------------------------------------------
// Host-side launch
// ---------------------------------------------------------------------------
static void* symptr_v(const void* sym)
{
    void* p = nullptr;
    cudaGetSymbolAddress(&p, sym);
    return p;
}

extern "C" void kernel_launch(void* const* d_in, const int* in_sizes, int n_in,
                              void* d_out, int out_size)
{
    const float* src = (const float*)d_in[0];
    const float* tau = (const float*)d_in[1];
    const float* Wq  = (const float*)d_in[2];
    const float* bq  = (const float*)d_in[3];
    const float* Wk  = (const float*)d_in[4];
    const float* bk  = (const float*)d_in[5];
    const float* Wv  = (const float*)d_in[6];
    const float* bv  = (const float*)d_in[7];
    const float* Wo  = (const float*)d_in[8];
    const float* bo  = (const float*)d_in[9];
    const float* W1  = (const float*)d_in[10];
    const float* b1  = (const float*)d_in[11];
    const float* W2  = (const float*)d_in[12];
    const float* b2  = (const float*)d_in[13];
    const float* g1  = (const float*)d_in[14];
    const float* be1 = (const float*)d_in[15];
    const float* g2  = (const float*)d_in[16];
    const float* be2 = (const float*)d_in[17];
    float* out = (float*)d_out;

    __half* srch = (__half*)symptr_v(g_srch);
    __half* qh   = (__half*)symptr_v(g_qh);
    __half* kh   = (__half*)symptr_v(g_kh);
    __half* vh   = (__half*)symptr_v(g_vh);
    __half* ctxh = (__half*)symptr_v(g_ctxh);
    __half* h1h  = (__half*)symptr_v(g_h1h);
    __half* f1h  = (__half*)symptr_v(g_f1h);
    float*  ao   = (float*)symptr_v(g_ao);
    float*  h1f  = (float*)symptr_v(g_h1f);
    float*  f2   = (float*)symptr_v(g_f2);
    __half* wqH  = (__half*)symptr_v(g_wqH);
    __half* wkH  = (__half*)symptr_v(g_wkH);
    __half* wvH  = (__half*)symptr_v(g_wvH);
    __half* woH  = (__half*)symptr_v(g_woH);
    __half* w1H  = (__half*)symptr_v(g_w1H);
    __half* w2H  = (__half*)symptr_v(g_w2H);

    cudaFuncSetAttribute(flash_kernel,
                         cudaFuncAttributeMaxDynamicSharedMemorySize, FA_SMEM_BYTES);
    cudaFuncSetAttribute(hgemm<true,  false, true,  false>,
                         cudaFuncAttributeMaxDynamicSharedMemorySize, GM_SMEM_BYTES);
    cudaFuncSetAttribute(hgemm<false, false, false, true>,
                         cudaFuncAttributeMaxDynamicSharedMemorySize, GM_SMEM_BYTES);
    cudaFuncSetAttribute(hgemm<false, true,  true,  false>,
                         cudaFuncAttributeMaxDynamicSharedMemorySize, GM_SMEM_BYTES);

    // ---- prep: streaming f2h of weights (natural layout) and src ----
    {
        int nW = DMODEL * DMODEL / 4;               // 262144
        f2h_kernel<<<(nW + 255) / 256, 256>>>((const float4*)Wq, (__half2*)wqH, nW);
        f2h_kernel<<<(nW + 255) / 256, 256>>>((const float4*)Wk, (__half2*)wkH, nW);
        f2h_kernel<<<(nW + 255) / 256, 256>>>((const float4*)Wv, (__half2*)wvH, nW);
        f2h_kernel<<<(nW + 255) / 256, 256>>>((const float4*)Wo, (__half2*)woH, nW);
        int nF = DMODEL * DFF / 4;                  // 1048576
        f2h_kernel<<<(nF + 255) / 256, 256>>>((const float4*)W1, (__half2*)w1H, nF);
        f2h_kernel<<<(nF + 255) / 256, 256>>>((const float4*)W2, (__half2*)w2H, nF);
        int nS = TOKENS * DMODEL / 4;
        f2h_kernel<<<(nS + 255) / 256, 256>>>((const float4*)src, (__half2*)srch, nS);
    }

    // ---- QKV (+RoPE, q pre-scaled) ----
    hgemm<true, false, true, false>
        <<<dim3(DMODEL / 256, TOKENS / 128, 3), 256, GM_SMEM_BYTES>>>(
        TOKENS, DMODEL, DMODEL, srch, wqH, wkH, wvH,
        qh, kh, vh, nullptr, DMODEL, bq, bk, bv, tau);

    // ---- flash attention -> ctx (half) ----
    flash_kernel<<<dim3(SEQ / 128, BATCH * NHEADS), 256, FA_SMEM_BYTES>>>(
        qh, kh, vh, ctxh);

    // ---- output projection -> ao (fp32) ----
    hgemm<false, false, false, true>
        <<<dim3(DMODEL / 256, TOKENS / 128, 1), 256, GM_SMEM_BYTES>>>(
        TOKENS, DMODEL, DMODEL, ctxh, woH, nullptr, nullptr,
        nullptr, nullptr, nullptr, ao, DMODEL, bo, nullptr, nullptr, nullptr);

    // ---- LN1 -> h1 (fp32 + half) ----
    ln_kernel<<<TOKENS, 256>>>(src, ao, g1, be1, h1f, h1h);

    // ---- FFN1 (GELU) -> f1 (half) ----
    hgemm<false, true, true, false>
        <<<dim3(DFF / 256, TOKENS / 128, 1), 256, GM_SMEM_BYTES>>>(
        TOKENS, DFF, DMODEL, h1h, w1H, nullptr, nullptr,
        f1h, nullptr, nullptr, nullptr, DFF, b1, nullptr, nullptr, nullptr);

    // ---- FFN2 -> f2 (fp32) ----
    hgemm<false, false, false, true>
        <<<dim3(DMODEL / 256, TOKENS / 128, 1), 256, GM_SMEM_BYTES>>>(
        TOKENS, DMODEL, DFF, f1h, w2H, nullptr, nullptr,
        nullptr, nullptr, nullptr, f2, DMODEL, b2, nullptr, nullptr, nullptr);

    // ---- LN2 -> out ----
    ln_kernel<<<TOKENS, 256>>>(h1f, f2, g2, be2, out, nullptr);

    (void)in_sizes; (void)n_in; (void)out_size;
}

// round 8
// speedup vs baseline: 6.8167x; 1.1647x over previous
#include <cuda_runtime.h>
#include <cuda_fp16.h>
#include <math.h>
#include <cstdint>

// ---------------------------------------------------------------------------
// Problem constants
// ---------------------------------------------------------------------------
#define BATCH   2
#define SEQ     2048
#define DMODEL  1024
#define NHEADS  16
#define HEADDIM 64
#define DFF     4096
#define TOKENS  (BATCH * SEQ)          // 4096

// ---------------------------------------------------------------------------
// Scratch (static device allocations)
// ---------------------------------------------------------------------------
__device__ __half g_srch[TOKENS * DMODEL];
__device__ __half g_qh  [TOKENS * DMODEL];
__device__ __half g_kh  [TOKENS * DMODEL];
__device__ __half g_vh  [TOKENS * DMODEL];
__device__ __half g_ctxh[TOKENS * DMODEL];
__device__ __half g_h1h [TOKENS * DMODEL];
__device__ __half g_f1h [(size_t)TOKENS * DFF];
__device__ float  g_ao  [TOKENS * DMODEL];
__device__ float  g_h1f [TOKENS * DMODEL];
__device__ float  g_f2  [TOKENS * DMODEL];
// half weights, natural [K][N] layout
__device__ __half g_wqH[DMODEL * DMODEL];
__device__ __half g_wkH[DMODEL * DMODEL];
__device__ __half g_wvH[DMODEL * DMODEL];
__device__ __half g_woH[DMODEL * DMODEL];
__device__ __half g_w1H[(size_t)DMODEL * DFF];
__device__ __half g_w2H[(size_t)DFF * DMODEL];

// ---------------------------------------------------------------------------
// PTX helpers
// ---------------------------------------------------------------------------
__device__ __forceinline__ uint32_t smem_u32(const void* p) {
    return (uint32_t)__cvta_generic_to_shared(p);
}
__device__ __forceinline__ void cp16(uint32_t s, const void* g) {
    asm volatile("cp.async.cg.shared.global [%0], [%1], 16;" :: "r"(s), "l"(g));
}
__device__ __forceinline__ void cp_commit() {
    asm volatile("cp.async.commit_group;");
}
template<int N>
__device__ __forceinline__ void cp_wait() {
    asm volatile("cp.async.wait_group %0;" :: "n"(N));
}
__device__ __forceinline__ uint32_t pack2(float lo, float hi) {
    __half2 h = __floats2half2_rn(lo, hi);
    return *reinterpret_cast<uint32_t*>(&h);
}
__device__ __forceinline__ void ldsm4(uint32_t addr, uint32_t* r) {
    asm volatile("ldmatrix.sync.aligned.m8n8.x4.shared.b16 {%0,%1,%2,%3}, [%4];"
        : "=r"(r[0]), "=r"(r[1]), "=r"(r[2]), "=r"(r[3]) : "r"(addr));
}
__device__ __forceinline__ void ldsm4t(uint32_t addr, uint32_t* r) {
    asm volatile("ldmatrix.sync.aligned.m8n8.x4.trans.shared.b16 {%0,%1,%2,%3}, [%4];"
        : "=r"(r[0]), "=r"(r[1]), "=r"(r[2]), "=r"(r[3]) : "r"(addr));
}
__device__ __forceinline__ void mma_f16(float* c, const uint32_t* a, const uint32_t* b) {
    asm volatile(
        "mma.sync.aligned.m16n8k16.row.col.f32.f16.f16.f32 "
        "{%0,%1,%2,%3}, {%4,%5,%6,%7}, {%8,%9}, {%0,%1,%2,%3};"
        : "+f"(c[0]), "+f"(c[1]), "+f"(c[2]), "+f"(c[3])
        : "r"(a[0]), "r"(a[1]), "r"(a[2]), "r"(a[3]), "r"(b[0]), "r"(b[1]));
}

// ---------------------------------------------------------------------------
// FP16 GEMM: C[M,N] = A[M,K](half) @ W[K,N](half) + bias.
// BM=128, BN=128, BK=32, 8 warps (warp tile 64x32), 2 CTAs/SM.
// 4-stage cp.async, one sync/stage. A: ldmatrix; B: ldmatrix.trans.
// QKV: grid.z selects W/C/bias, RoPE for z<2, q scaled 1/8.
// ---------------------------------------------------------------------------
#define GM_ASTR 40                       // A smem row stride (halves)
#define GM_BSTR 136                      // B smem row stride (halves)
#define GM_AH   (128 * GM_ASTR)          // 5120 halves
#define GM_BH   (32 * GM_BSTR)           // 4352 halves
#define GM_STG  (GM_AH + GM_BH)          // 9472 halves / stage
#define GM_SMEM_BYTES (4 * GM_STG * 2)   // 75776

template<bool QKV, bool GELU, bool OH, bool OF>
__global__ __launch_bounds__(256, 2)
void hgemm(int M, int N, int K,
           const __half* __restrict__ A,
           const __half* __restrict__ W0, const __half* __restrict__ W1_,
           const __half* __restrict__ W2_,
           __half* __restrict__ Ch0, __half* __restrict__ Ch1,
           __half* __restrict__ Ch2,
           float* __restrict__ Cf,
           int ldc,
           const float* __restrict__ bias0, const float* __restrict__ bias1,
           const float* __restrict__ bias2,
           const float* __restrict__ tau)
{
    extern __shared__ __half hsm[];

    const __half* W    = W0;
    __half*       Ch   = Ch0;
    const float*  bias = bias0;
    bool rope = false;
    float oscale = 1.0f;
    if (QKV) {
        int z = blockIdx.z;
        if (z == 1)      { W = W1_; Ch = Ch1; bias = bias1; }
        else if (z == 2) { W = W2_; Ch = Ch2; bias = bias2; }
        rope = (z < 2);
        if (z == 0) oscale = 0.125f;
    }

    const int tid  = threadIdx.x;
    const int lane = tid & 31;
    const int warp = tid >> 5;
    const int grp  = lane >> 2;
    const int tig  = lane & 3;
    const int wm0  = (warp >> 2) * 64;    // 0 or 64
    const int wn0  = (warp & 3) * 32;     // 0,32,64,96
    const int m0 = blockIdx.y * 128;
    const int n0 = blockIdx.x * 128;

    const uint32_t sbase = smem_u32(hsm);
    const uint32_t aOff = ((wm0 + (lane & 15)) * GM_ASTR + (lane >> 4) * 8) * 2;
    const int g8 = lane >> 3, r8 = lane & 7;
    const uint32_t bOff = (((g8 & 1) * 8 + r8) * GM_BSTR + wn0 + (g8 >> 1) * 8) * 2;

    float acc[4][4][4];
#pragma unroll
    for (int mi = 0; mi < 4; mi++)
#pragma unroll
        for (int ni = 0; ni < 4; ni++)
#pragma unroll
            for (int e = 0; e < 4; e++) acc[mi][ni][e] = 0.0f;

    auto load_stage = [&](int s) {
        uint32_t ab = sbase + (s & 3) * GM_STG * 2;
        uint32_t bb = ab + GM_AH * 2;
        int k0 = s * 32;
        // A: 128 rows x 32 halves = 512 chunks, 2/thread
#pragma unroll
        for (int l = 0; l < 2; l++) {
            int c = tid + l * 256;
            int m = c >> 2, ch = c & 3;
            cp16(ab + (m * GM_ASTR + ch * 8) * 2,
                 A + (size_t)(m0 + m) * K + k0 + ch * 8);
        }
        // B: 32 rows x 128 halves = 512 chunks, 2/thread
#pragma unroll
        for (int l = 0; l < 2; l++) {
            int c = tid + l * 256;
            int kk = c >> 4, nq = c & 15;
            cp16(bb + (kk * GM_BSTR + nq * 8) * 2,
                 W + (size_t)(k0 + kk) * N + n0 + nq * 8);
        }
        cp_commit();
    };

    auto compute_stage = [&](int s) {
        uint32_t ab = sbase + (s & 3) * GM_STG * 2;
        uint32_t bb = ab + GM_AH * 2;
#pragma unroll
        for (int kk = 0; kk < 32; kk += 16) {
            uint32_t af[4][4], bf[4][2];
#pragma unroll
            for (int mi = 0; mi < 4; mi++)
                ldsm4(ab + aOff + (mi * 16 * GM_ASTR + kk) * 2, af[mi]);
#pragma unroll
            for (int nip = 0; nip < 2; nip++)
                ldsm4t(bb + bOff + (kk * GM_BSTR + nip * 16) * 2, &bf[2 * nip][0]);
#pragma unroll
            for (int mi = 0; mi < 4; mi++)
#pragma unroll
                for (int ni = 0; ni < 4; ni++)
                    mma_f16(acc[mi][ni], af[mi], bf[ni]);
        }
    };

    const int S = K / 32;
    load_stage(0); load_stage(1); load_stage(2);
    for (int s = 0; s < S; s++) {
        int pend = S - 1 - s;
        if (pend >= 2)      cp_wait<2>();
        else if (pend == 1) cp_wait<1>();
        else                cp_wait<0>();
        __syncthreads();
        if (s + 3 < S) load_stage(s + 3);
        compute_stage(s);
    }

    // ---- epilogue ----
#pragma unroll
    for (int mi = 0; mi < 4; mi++) {
#pragma unroll
        for (int h = 0; h < 2; h++) {
            int row = m0 + wm0 + mi * 16 + grp + h * 8;
            float t = 0.0f;
            if (QKV) t = tau[row];
#pragma unroll
            for (int ni = 0; ni < 4; ni++) {
                int gcol = n0 + wn0 + ni * 8 + 2 * tig;
                float v0 = acc[mi][ni][h * 2 + 0];
                float v1 = acc[mi][ni][h * 2 + 1];
                if (bias) { v0 += bias[gcol]; v1 += bias[gcol + 1]; }
                if (GELU) {
                    v0 = 0.5f * v0 * (1.0f + erff(v0 * 0.7071067811865475f));
                    v1 = 0.5f * v1 * (1.0f + erff(v1 * 0.7071067811865475f));
                }
                if (QKV && rope) {
                    int j = (gcol & 63) >> 1;
                    float inv = __expf(-0.28782313662425572f * (float)j);
                    float sn, cs;
                    sincosf(t * inv, &sn, &cs);
                    float r0 = v0 * cs - v1 * sn;
                    float r1 = v1 * cs + v0 * sn;
                    v0 = r0 * oscale; v1 = r1 * oscale;
                }
                if (OH) {
                    *(__half2*)(Ch + (size_t)row * ldc + gcol) =
                        __floats2half2_rn(v0, v1);
                }
                if (OF) {
                    *(float2*)(Cf + (size_t)row * ldc + gcol) = make_float2(v0, v1);
                }
            }
        }
    }
}

// ---------------------------------------------------------------------------
// Fused float->half conversion of all 7 buffers in one launch.
// ---------------------------------------------------------------------------
struct F2HJob {
    const float4* in[7];
    __half2*      out[7];
    int           end[7];   // cumulative end offsets (in float4 units)
};

__global__ __launch_bounds__(256)
void f2h_all_kernel(F2HJob job)
{
    int i = blockIdx.x * 256 + threadIdx.x;
    int seg = 0, base = 0;
#pragma unroll
    for (int s = 0; s < 7; s++) {
        if (i >= job.end[s]) { seg = s + 1; base = job.end[s]; }
    }
    if (seg >= 7) return;
    int off = i - base;
    float4 v = job.in[seg][off];
    job.out[seg][2 * off]     = __floats2half2_rn(v.x, v.y);
    job.out[seg][2 * off + 1] = __floats2half2_rn(v.z, v.w);
}

// ---------------------------------------------------------------------------
// FP16 flash attention with ldmatrix + cp.async K/V double buffers.
// ---------------------------------------------------------------------------
#define FK_STR  72
#define FT_H    (128 * FK_STR)
#define FA_SMEM_BYTES (4 * FT_H * 2)      // 73728

__global__ __launch_bounds__(256)
void flash_kernel(const __half* __restrict__ q, const __half* __restrict__ k,
                  const __half* __restrict__ v, __half* __restrict__ ctx)
{
    extern __shared__ __half fsm[];
    const uint32_t sbase = smem_u32(fsm);

    const int tid  = threadIdx.x;
    const int lane = tid & 31;
    const int warp = tid >> 5;
    const int grp  = lane >> 2;
    const int tig  = lane & 3;
    const int g8 = lane >> 3, r8 = lane & 7;

    const int m0 = blockIdx.x * 128;
    const int bh = blockIdx.y;
    const int b  = bh >> 4;
    const int h  = bh & 15;

    const __half* qb = q + ((size_t)b * SEQ) * DMODEL + h * HEADDIM;
    const __half* kb = k + ((size_t)b * SEQ) * DMODEL + h * HEADDIM;
    const __half* vb = v + ((size_t)b * SEQ) * DMODEL + h * HEADDIM;

    const uint32_t qOff = ((warp * 16 + (lane & 15)) * FK_STR + (lane >> 4) * 8) * 2;
    const uint32_t kOff = ((r8 + (g8 >> 1) * 8) * FK_STR + (g8 & 1) * 8) * 2;
    const uint32_t vOff = ((r8 + (g8 & 1) * 8) * FK_STR + (g8 >> 1) * 8) * 2;

#pragma unroll
    for (int l = 0; l < 4; l++) {
        int c = tid + l * 256;
        int r = c >> 3, ch = c & 7;
        cp16(sbase + (r * FK_STR + ch * 8) * 2,
             qb + (size_t)(m0 + r) * DMODEL + ch * 8);
    }
    cp_commit(); cp_wait<0>(); __syncthreads();

    uint32_t aq[4][4];
#pragma unroll
    for (int kc = 0; kc < 4; kc++)
        ldsm4(sbase + qOff + kc * 32, aq[kc]);
    __syncthreads();

    float o[8][4];
#pragma unroll
    for (int ni = 0; ni < 8; ni++)
#pragma unroll
        for (int e = 0; e < 4; e++) o[ni][e] = 0.0f;
    float mrun0 = -1e30f, mrun1 = -1e30f, lrun0 = 0.0f, lrun1 = 0.0f;

    auto load_kv = [&](int t) {
        uint32_t kd = sbase + (t & 1) * FT_H * 2;
        uint32_t vd = sbase + (2 + (t & 1)) * FT_H * 2;
#pragma unroll
        for (int l = 0; l < 4; l++) {
            int c = tid + l * 256;
            int r = c >> 3, ch = c & 7;
            uint32_t so = (r * FK_STR + ch * 8) * 2;
            size_t  go = (size_t)(t * 128 + r) * DMODEL + ch * 8;
            cp16(kd + so, kb + go);
            cp16(vd + so, vb + go);
        }
        cp_commit();
    };

    load_kv(0);

    const int NTILE = SEQ / 128;
    for (int t = 0; t < NTILE; t++) {
        cp_wait<0>();
        __syncthreads();
        if (t + 1 < NTILE) load_kv(t + 1);

        uint32_t kbuf = sbase + (t & 1) * FT_H * 2;
        uint32_t vbuf = sbase + (2 + (t & 1)) * FT_H * 2;

        float sacc[16][4];
#pragma unroll
        for (int ni = 0; ni < 16; ni++)
#pragma unroll
            for (int e = 0; e < 4; e++) sacc[ni][e] = 0.0f;

#pragma unroll
        for (int kc = 0; kc < 4; kc++) {
#pragma unroll
            for (int nip = 0; nip < 8; nip++) {
                uint32_t bf[4];
                ldsm4(kbuf + kOff + (nip * 16 * FK_STR + kc * 16) * 2, bf);
                mma_f16(sacc[2 * nip    ], aq[kc], &bf[0]);
                mma_f16(sacc[2 * nip + 1], aq[kc], &bf[2]);
            }
        }

        float tmax0 = -1e30f, tmax1 = -1e30f;
#pragma unroll
        for (int ni = 0; ni < 16; ni++) {
            tmax0 = fmaxf(tmax0, fmaxf(sacc[ni][0], sacc[ni][1]));
            tmax1 = fmaxf(tmax1, fmaxf(sacc[ni][2], sacc[ni][3]));
        }
        tmax0 = fmaxf(tmax0, __shfl_xor_sync(0xffffffffu, tmax0, 1));
        tmax0 = fmaxf(tmax0, __shfl_xor_sync(0xffffffffu, tmax0, 2));
        tmax1 = fmaxf(tmax1, __shfl_xor_sync(0xffffffffu, tmax1, 1));
        tmax1 = fmaxf(tmax1, __shfl_xor_sync(0xffffffffu, tmax1, 2));

        float nm0 = fmaxf(mrun0, tmax0);
        float nm1 = fmaxf(mrun1, tmax1);
        float sc0 = __expf(mrun0 - nm0);
        float sc1 = __expf(mrun1 - nm1);
        mrun0 = nm0; mrun1 = nm1;

        float sum0 = 0.0f, sum1 = 0.0f;
#pragma unroll
        for (int ni = 0; ni < 16; ni++) {
            sacc[ni][0] = __expf(sacc[ni][0] - nm0);
            sacc[ni][1] = __expf(sacc[ni][1] - nm0);
            sacc[ni][2] = __expf(sacc[ni][2] - nm1);
            sacc[ni][3] = __expf(sacc[ni][3] - nm1);
            sum0 += sacc[ni][0] + sacc[ni][1];
            sum1 += sacc[ni][2] + sacc[ni][3];
        }
        sum0 += __shfl_xor_sync(0xffffffffu, sum0, 1);
        sum0 += __shfl_xor_sync(0xffffffffu, sum0, 2);
        sum1 += __shfl_xor_sync(0xffffffffu, sum1, 1);
        sum1 += __shfl_xor_sync(0xffffffffu, sum1, 2);
        lrun0 = lrun0 * sc0 + sum0;
        lrun1 = lrun1 * sc1 + sum1;

#pragma unroll
        for (int ni = 0; ni < 8; ni++) {
            o[ni][0] *= sc0; o[ni][1] *= sc0;
            o[ni][2] *= sc1; o[ni][3] *= sc1;
        }

        uint32_t pA[8][4];
#pragma unroll
        for (int kc = 0; kc < 8; kc++) {
            pA[kc][0] = pack2(sacc[2 * kc    ][0], sacc[2 * kc    ][1]);
            pA[kc][1] = pack2(sacc[2 * kc    ][2], sacc[2 * kc    ][3]);
            pA[kc][2] = pack2(sacc[2 * kc + 1][0], sacc[2 * kc + 1][1]);
            pA[kc][3] = pack2(sacc[2 * kc + 1][2], sacc[2 * kc + 1][3]);
        }

#pragma unroll
        for (int kc = 0; kc < 8; kc++) {
#pragma unroll
            for (int nip = 0; nip < 4; nip++) {
                uint32_t bb[4];
                ldsm4t(vbuf + vOff + (kc * 16 * FK_STR + nip * 16) * 2, bb);
                mma_f16(o[2 * nip    ], pA[kc], &bb[0]);
                mma_f16(o[2 * nip + 1], pA[kc], &bb[2]);
            }
        }
    }

    float inv0 = 1.0f / lrun0;
    float inv1 = 1.0f / lrun1;
    int r0 = m0 + warp * 16 + grp;
    __half* cb = ctx + ((size_t)b * SEQ) * DMODEL + h * HEADDIM;
#pragma unroll
    for (int ni = 0; ni < 8; ni++) {
        int col = ni * 8 + 2 * tig;
        *(__half2*)(cb + (size_t)(r0    ) * DMODEL + col) =
            __floats2half2_rn(o[ni][0] * inv0, o[ni][1] * inv0);
        *(__half2*)(cb + (size_t)(r0 + 8) * DMODEL + col) =
            __floats2half2_rn(o[ni][2] * inv1, o[ni][3] * inv1);
    }
}

// ---------------------------------------------------------------------------
// Fused residual + LayerNorm; fp32 out + optional half out.
// ---------------------------------------------------------------------------
__global__ __launch_bounds__(256)
void ln_kernel(const float* __restrict__ a, const float* __restrict__ b,
               const float* __restrict__ g, const float* __restrict__ be,
               float* __restrict__ out, __half* __restrict__ outh)
{
    const int D = DMODEL;
    size_t row = blockIdx.x;
    const float* pa = a + row * D;
    const float* pb = b + row * D;
    int tid = threadIdx.x;
    __shared__ float red[256];

    float x[4];
    float s = 0.0f;
#pragma unroll
    for (int i = 0; i < 4; i++) {
        int c = tid + i * 256;
        x[i] = pa[c] + pb[c];
        s += x[i];
    }
    red[tid] = s;
    __syncthreads();
    for (int t = 128; t > 0; t >>= 1) {
        if (tid < t) red[tid] += red[tid + t];
        __syncthreads();
    }
    float mu = red[0] * (1.0f / D);
    __syncthreads();

    float v = 0.0f;
#pragma unroll
    for (int i = 0; i < 4; i++) {
        float d = x[i] - mu;
        v += d * d;
    }
    red[tid] = v;
    __syncthreads();
    for (int t = 128; t > 0; t >>= 1) {
        if (tid < t) red[tid] += red[tid + t];
        __syncthreads();
    }
    float var = red[0] * (1.0f / D);
    float r = rsqrtf(var + 1e-5f);
#pragma unroll
    for (int i = 0; i < 4; i++) {
        int c = tid + i * 256;
        float y = (x[i] - mu) * r * g[c] + be[c];
        out[row * D + c] = y;
        if (outh) outh[row * D + c] = __float2half_rn(y);
    }
}

// ---------------------------------------------------------------------------
// Host-side launch
// ---------------------------------------------------------------------------
static void* symptr_v(const void* sym)
{
    void* p = nullptr;
    cudaGetSymbolAddress(&p, sym);
    return p;
}

extern "C" void kernel_launch(void* const* d_in, const int* in_sizes, int n_in,
                              void* d_out, int out_size)
{
    const float* src = (const float*)d_in[0];
    const float* tau = (const float*)d_in[1];
    const float* Wq  = (const float*)d_in[2];
    const float* bq  = (const float*)d_in[3];
    const float* Wk  = (const float*)d_in[4];
    const float* bk  = (const float*)d_in[5];
    const float* Wv  = (const float*)d_in[6];
    const float* bv  = (const float*)d_in[7];
    const float* Wo  = (const float*)d_in[8];
    const float* bo  = (const float*)d_in[9];
    const float* W1  = (const float*)d_in[10];
    const float* b1  = (const float*)d_in[11];
    const float* W2  = (const float*)d_in[12];
    const float* b2  = (const float*)d_in[13];
    const float* g1  = (const float*)d_in[14];
    const float* be1 = (const float*)d_in[15];
    const float* g2  = (const float*)d_in[16];
    const float* be2 = (const float*)d_in[17];
    float* out = (float*)d_out;

    __half* srch = (__half*)symptr_v(g_srch);
    __half* qh   = (__half*)symptr_v(g_qh);
    __half* kh   = (__half*)symptr_v(g_kh);
    __half* vh   = (__half*)symptr_v(g_vh);
    __half* ctxh = (__half*)symptr_v(g_ctxh);
    __half* h1h  = (__half*)symptr_v(g_h1h);
    __half* f1h  = (__half*)symptr_v(g_f1h);
    float*  ao   = (float*)symptr_v(g_ao);
    float*  h1f  = (float*)symptr_v(g_h1f);
    float*  f2   = (float*)symptr_v(g_f2);
    __half* wqH  = (__half*)symptr_v(g_wqH);
    __half* wkH  = (__half*)symptr_v(g_wkH);
    __half* wvH  = (__half*)symptr_v(g_wvH);
    __half* woH  = (__half*)symptr_v(g_woH);
    __half* w1H  = (__half*)symptr_v(g_w1H);
    __half* w2H  = (__half*)symptr_v(g_w2H);

    cudaFuncSetAttribute(flash_kernel,
                         cudaFuncAttributeMaxDynamicSharedMemorySize, FA_SMEM_BYTES);
    cudaFuncSetAttribute(hgemm<true,  false, true,  false>,
                         cudaFuncAttributeMaxDynamicSharedMemorySize, GM_SMEM_BYTES);
    cudaFuncSetAttribute(hgemm<false, false, false, true>,
                         cudaFuncAttributeMaxDynamicSharedMemorySize, GM_SMEM_BYTES);
    cudaFuncSetAttribute(hgemm<false, true,  true,  false>,
                         cudaFuncAttributeMaxDynamicSharedMemorySize, GM_SMEM_BYTES);

    // ---- prep: single fused f2h of all weights + src ----
    {
        const int nW = DMODEL * DMODEL / 4;        // 262144
        const int nF = DMODEL * DFF / 4;           // 1048576
        const int nS = TOKENS * DMODEL / 4;        // 1048576
        F2HJob job;
        job.in[0] = (const float4*)Wq;  job.out[0] = (__half2*)wqH;
        job.in[1] = (const float4*)Wk;  job.out[1] = (__half2*)wkH;
        job.in[2] = (const float4*)Wv;  job.out[2] = (__half2*)wvH;
        job.in[3] = (const float4*)Wo;  job.out[3] = (__half2*)woH;
        job.in[4] = (const float4*)W1;  job.out[4] = (__half2*)w1H;
        job.in[5] = (const float4*)W2;  job.out[5] = (__half2*)w2H;
        job.in[6] = (const float4*)src; job.out[6] = (__half2*)srch;
        int acc = 0;
        int sizes[7] = { nW, nW, nW, nW, nF, nF, nS };
        for (int s = 0; s < 7; s++) { acc += sizes[s]; job.end[s] = acc; }
        f2h_all_kernel<<<(acc + 255) / 256, 256>>>(job);
    }

    // ---- QKV (+RoPE, q pre-scaled) ----
    hgemm<true, false, true, false>
        <<<dim3(DMODEL / 128, TOKENS / 128, 3), 256, GM_SMEM_BYTES>>>(
        TOKENS, DMODEL, DMODEL, srch, wqH, wkH, wvH,
        qh, kh, vh, nullptr, DMODEL, bq, bk, bv, tau);

    // ---- flash attention -> ctx (half) ----
    flash_kernel<<<dim3(SEQ / 128, BATCH * NHEADS), 256, FA_SMEM_BYTES>>>(
        qh, kh, vh, ctxh);

    // ---- output projection -> ao (fp32) ----
    hgemm<false, false, false, true>
        <<<dim3(DMODEL / 128, TOKENS / 128, 1), 256, GM_SMEM_BYTES>>>(
        TOKENS, DMODEL, DMODEL, ctxh, woH, nullptr, nullptr,
        nullptr, nullptr, nullptr, ao, DMODEL, bo, nullptr, nullptr, nullptr);

    // ---- LN1 -> h1 (fp32 + half) ----
    ln_kernel<<<TOKENS, 256>>>(src, ao, g1, be1, h1f, h1h);

    // ---- FFN1 (GELU) -> f1 (half) ----
    hgemm<false, true, true, false>
        <<<dim3(DFF / 128, TOKENS / 128, 1), 256, GM_SMEM_BYTES>>>(
        TOKENS, DFF, DMODEL, h1h, w1H, nullptr, nullptr,
        f1h, nullptr, nullptr, nullptr, DFF, b1, nullptr, nullptr, nullptr);

    // ---- FFN2 -> f2 (fp32) ----
    hgemm<false, false, false, true>
        <<<dim3(DMODEL / 128, TOKENS / 128, 1), 256, GM_SMEM_BYTES>>>(
        TOKENS, DMODEL, DFF, f1h, w2H, nullptr, nullptr,
        nullptr, nullptr, nullptr, f2, DMODEL, b2, nullptr, nullptr, nullptr);

    // ---- LN2 -> out ----
    ln_kernel<<<TOKENS, 256>>>(h1f, f2, g2, be2, out, nullptr);

    (void)in_sizes; (void)n_in; (void)out_size;
}

// round 9
// speedup vs baseline: 7.0557x; 1.0351x over previous
#include <cuda_runtime.h>
#include <cuda_fp16.h>
#include <math.h>
#include <cstdint>

// ---------------------------------------------------------------------------
// Problem constants
// ---------------------------------------------------------------------------
#define BATCH   2
#define SEQ     2048
#define DMODEL  1024
#define NHEADS  16
#define HEADDIM 64
#define DFF     4096
#define TOKENS  (BATCH * SEQ)          // 4096

// ---------------------------------------------------------------------------
// Scratch (static device allocations)
// ---------------------------------------------------------------------------
__device__ __half g_srch[TOKENS * DMODEL];
__device__ __half g_qh  [TOKENS * DMODEL];
__device__ __half g_kh  [TOKENS * DMODEL];
__device__ __half g_vh  [TOKENS * DMODEL];
__device__ __half g_ctxh[TOKENS * DMODEL];
__device__ __half g_h1h [TOKENS * DMODEL];
__device__ __half g_f1h [(size_t)TOKENS * DFF];
__device__ float  g_ao  [TOKENS * DMODEL];
__device__ float  g_h1f [TOKENS * DMODEL];
__device__ float  g_f2  [TOKENS * DMODEL];
// half weights, natural [K][N] layout
__device__ __half g_wqH[DMODEL * DMODEL];
__device__ __half g_wkH[DMODEL * DMODEL];
__device__ __half g_wvH[DMODEL * DMODEL];
__device__ __half g_woH[DMODEL * DMODEL];
__device__ __half g_w1H[(size_t)DMODEL * DFF];
__device__ __half g_w2H[(size_t)DFF * DMODEL];

// ---------------------------------------------------------------------------
// PTX helpers
// ---------------------------------------------------------------------------
__device__ __forceinline__ uint32_t smem_u32(const void* p) {
    return (uint32_t)__cvta_generic_to_shared(p);
}
__device__ __forceinline__ void cp16(uint32_t s, const void* g) {
    asm volatile("cp.async.cg.shared.global [%0], [%1], 16;" :: "r"(s), "l"(g));
}
__device__ __forceinline__ void cp_commit() {
    asm volatile("cp.async.commit_group;");
}
template<int N>
__device__ __forceinline__ void cp_wait() {
    asm volatile("cp.async.wait_group %0;" :: "n"(N));
}
__device__ __forceinline__ uint32_t pack2(float lo, float hi) {
    __half2 h = __floats2half2_rn(lo, hi);
    return *reinterpret_cast<uint32_t*>(&h);
}
__device__ __forceinline__ void ldsm4(uint32_t addr, uint32_t* r) {
    asm volatile("ldmatrix.sync.aligned.m8n8.x4.shared.b16 {%0,%1,%2,%3}, [%4];"
        : "=r"(r[0]), "=r"(r[1]), "=r"(r[2]), "=r"(r[3]) : "r"(addr));
}
__device__ __forceinline__ void ldsm4t(uint32_t addr, uint32_t* r) {
    asm volatile("ldmatrix.sync.aligned.m8n8.x4.trans.shared.b16 {%0,%1,%2,%3}, [%4];"
        : "=r"(r[0]), "=r"(r[1]), "=r"(r[2]), "=r"(r[3]) : "r"(addr));
}
__device__ __forceinline__ void mma_f16(float* c, const uint32_t* a, const uint32_t* b) {
    asm volatile(
        "mma.sync.aligned.m16n8k16.row.col.f32.f16.f16.f32 "
        "{%0,%1,%2,%3}, {%4,%5,%6,%7}, {%8,%9}, {%0,%1,%2,%3};"
        : "+f"(c[0]), "+f"(c[1]), "+f"(c[2]), "+f"(c[3])
        : "r"(a[0]), "r"(a[1]), "r"(a[2]), "r"(a[3]), "r"(b[0]), "r"(b[1]));
}

// ---------------------------------------------------------------------------
// FP16 GEMM: C[M,N] = A[M,K](half) @ W[K,N](half) + bias.
// BM=128, BN=128, BK=32, 8 warps (warp tile 64x32), 2 CTAs/SM.
// 4-stage cp.async ring; register-level fragment double buffering so every
// mma block's operands are loaded one half-stage ahead (LDSM latency hidden).
// ---------------------------------------------------------------------------
#define GM_ASTR 40                       // A smem row stride (halves)
#define GM_BSTR 136                      // B smem row stride (halves)
#define GM_AH   (128 * GM_ASTR)          // 5120 halves
#define GM_BH   (32 * GM_BSTR)           // 4352 halves
#define GM_STG  (GM_AH + GM_BH)          // 9472 halves / stage
#define GM_SMEM_BYTES (4 * GM_STG * 2)   // 75776

template<bool QKV, bool GELU, bool OH, bool OF>
__global__ __launch_bounds__(256, 2)
void hgemm(int M, int N, int K,
           const __half* __restrict__ A,
           const __half* __restrict__ W0, const __half* __restrict__ W1_,
           const __half* __restrict__ W2_,
           __half* __restrict__ Ch0, __half* __restrict__ Ch1,
           __half* __restrict__ Ch2,
           float* __restrict__ Cf,
           int ldc,
           const float* __restrict__ bias0, const float* __restrict__ bias1,
           const float* __restrict__ bias2,
           const float* __restrict__ tau)
{
    extern __shared__ __half hsm[];

    const __half* W    = W0;
    __half*       Ch   = Ch0;
    const float*  bias = bias0;
    bool rope = false;
    float oscale = 1.0f;
    if (QKV) {
        int z = blockIdx.z;
        if (z == 1)      { W = W1_; Ch = Ch1; bias = bias1; }
        else if (z == 2) { W = W2_; Ch = Ch2; bias = bias2; }
        rope = (z < 2);
        if (z == 0) oscale = 0.125f;
    }

    const int tid  = threadIdx.x;
    const int lane = tid & 31;
    const int warp = tid >> 5;
    const int grp  = lane >> 2;
    const int tig  = lane & 3;
    const int wm0  = (warp >> 2) * 64;    // 0 or 64
    const int wn0  = (warp & 3) * 32;     // 0,32,64,96
    const int m0 = blockIdx.y * 128;
    const int n0 = blockIdx.x * 128;

    const uint32_t sbase = smem_u32(hsm);
    const uint32_t aOff = ((wm0 + (lane & 15)) * GM_ASTR + (lane >> 4) * 8) * 2;
    const int g8 = lane >> 3, r8 = lane & 7;
    const uint32_t bOff = (((g8 & 1) * 8 + r8) * GM_BSTR + wn0 + (g8 >> 1) * 8) * 2;

    float acc[4][4][4];
#pragma unroll
    for (int mi = 0; mi < 4; mi++)
#pragma unroll
        for (int ni = 0; ni < 4; ni++)
#pragma unroll
            for (int e = 0; e < 4; e++) acc[mi][ni][e] = 0.0f;

    auto load_stage = [&](int s) {
        uint32_t ab = sbase + (s & 3) * GM_STG * 2;
        uint32_t bb = ab + GM_AH * 2;
        int k0 = s * 32;
#pragma unroll
        for (int l = 0; l < 2; l++) {
            int c = tid + l * 256;
            int m = c >> 2, ch = c & 3;
            cp16(ab + (m * GM_ASTR + ch * 8) * 2,
                 A + (size_t)(m0 + m) * K + k0 + ch * 8);
        }
#pragma unroll
        for (int l = 0; l < 2; l++) {
            int c = tid + l * 256;
            int kk = c >> 4, nq = c & 15;
            cp16(bb + (kk * GM_BSTR + nq * 8) * 2,
                 W + (size_t)(k0 + kk) * N + n0 + nq * 8);
        }
        cp_commit();
    };

    // register fragment double-buffer: p=0 holds kk=0 frags, p=1 holds kk=16
    uint32_t af[2][4][4], bf[2][4][2];

    auto load_frags = [&](int s, int kk, int p) {
        uint32_t ab = sbase + (s & 3) * GM_STG * 2;
        uint32_t bb = ab + GM_AH * 2;
#pragma unroll
        for (int mi = 0; mi < 4; mi++)
            ldsm4(ab + aOff + (mi * 16 * GM_ASTR + kk) * 2, af[p][mi]);
#pragma unroll
        for (int nip = 0; nip < 2; nip++)
            ldsm4t(bb + bOff + (kk * GM_BSTR + nip * 16) * 2, &bf[p][2 * nip][0]);
    };

    auto do_mma = [&](int p) {
#pragma unroll
        for (int mi = 0; mi < 4; mi++)
#pragma unroll
            for (int ni = 0; ni < 4; ni++)
                mma_f16(acc[mi][ni], af[p][mi], bf[p][ni]);
    };

    const int S = K / 32;
    load_stage(0); load_stage(1); load_stage(2);
    cp_wait<2>();          // stage 0 complete
    __syncthreads();
    load_frags(0, 0, 0);

    for (int s = 0; s < S; s++) {
        load_frags(s, 16, 1);         // prefetch kk=16 frags (stage s resident)
        do_mma(0);                    // kk=0 mma (operands prefetched earlier)
        // make stage s+1 visible to ALL threads: per-thread wait, then barrier.
        int rem = S - 2 - s;          // committed stages beyond s+1
        if (rem >= 2)      cp_wait<2>();
        else if (rem == 1) cp_wait<1>();
        else               cp_wait<0>();
        __syncthreads();              // also protects ring-buffer reuse below
        if (s + 3 < S) load_stage(s + 3);
        if (s + 1 < S) load_frags(s + 1, 0, 0);   // prefetch next stage kk=0
        do_mma(1);                    // kk=16 mma
    }

    // ---- epilogue ----
#pragma unroll
    for (int mi = 0; mi < 4; mi++) {
#pragma unroll
        for (int h = 0; h < 2; h++) {
            int row = m0 + wm0 + mi * 16 + grp + h * 8;
            float t = 0.0f;
            if (QKV) t = tau[row];
#pragma unroll
            for (int ni = 0; ni < 4; ni++) {
                int gcol = n0 + wn0 + ni * 8 + 2 * tig;
                float v0 = acc[mi][ni][h * 2 + 0];
                float v1 = acc[mi][ni][h * 2 + 1];
                if (bias) { v0 += bias[gcol]; v1 += bias[gcol + 1]; }
                if (GELU) {
                    v0 = 0.5f * v0 * (1.0f + erff(v0 * 0.7071067811865475f));
                    v1 = 0.5f * v1 * (1.0f + erff(v1 * 0.7071067811865475f));
                }
                if (QKV && rope) {
                    int j = (gcol & 63) >> 1;
                    float inv = __expf(-0.28782313662425572f * (float)j);
                    float sn, cs;
                    sincosf(t * inv, &sn, &cs);
                    float r0 = v0 * cs - v1 * sn;
                    float r1 = v1 * cs + v0 * sn;
                    v0 = r0 * oscale; v1 = r1 * oscale;
                }
                if (OH) {
                    *(__half2*)(Ch + (size_t)row * ldc + gcol) =
                        __floats2half2_rn(v0, v1);
                }
                if (OF) {
                    *(float2*)(Cf + (size_t)row * ldc + gcol) = make_float2(v0, v1);
                }
            }
        }
    }
}

// ---------------------------------------------------------------------------
// Fused float->half conversion of all 7 buffers in one launch.
// ---------------------------------------------------------------------------
struct F2HJob {
    const float4* in[7];
    __half2*      out[7];
    int           end[7];   // cumulative end offsets (in float4 units)
};

__global__ __launch_bounds__(256)
void f2h_all_kernel(F2HJob job)
{
    int i = blockIdx.x * 256 + threadIdx.x;
    int seg = 0, base = 0;
#pragma unroll
    for (int s = 0; s < 7; s++) {
        if (i >= job.end[s]) { seg = s + 1; base = job.end[s]; }
    }
    if (seg >= 7) return;
    int off = i - base;
    float4 v = job.in[seg][off];
    job.out[seg][2 * off]     = __floats2half2_rn(v.x, v.y);
    job.out[seg][2 * off + 1] = __floats2half2_rn(v.z, v.w);
}

// ---------------------------------------------------------------------------
// FP16 flash attention with ldmatrix + cp.async K/V double buffers.
// S-loop and PV-loop use register double-buffered B fragments.
// ---------------------------------------------------------------------------
#define FK_STR  72
#define FT_H    (128 * FK_STR)
#define FA_SMEM_BYTES (4 * FT_H * 2)      // 73728

__global__ __launch_bounds__(256)
void flash_kernel(const __half* __restrict__ q, const __half* __restrict__ k,
                  const __half* __restrict__ v, __half* __restrict__ ctx)
{
    extern __shared__ __half fsm[];
    const uint32_t sbase = smem_u32(fsm);

    const int tid  = threadIdx.x;
    const int lane = tid & 31;
    const int warp = tid >> 5;
    const int grp  = lane >> 2;
    const int tig  = lane & 3;
    const int g8 = lane >> 3, r8 = lane & 7;

    const int m0 = blockIdx.x * 128;
    const int bh = blockIdx.y;
    const int b  = bh >> 4;
    const int h  = bh & 15;

    const __half* qb = q + ((size_t)b * SEQ) * DMODEL + h * HEADDIM;
    const __half* kb = k + ((size_t)b * SEQ) * DMODEL + h * HEADDIM;
    const __half* vb = v + ((size_t)b * SEQ) * DMODEL + h * HEADDIM;

    const uint32_t qOff = ((warp * 16 + (lane & 15)) * FK_STR + (lane >> 4) * 8) * 2;
    const uint32_t kOff = ((r8 + (g8 >> 1) * 8) * FK_STR + (g8 & 1) * 8) * 2;
    const uint32_t vOff = ((r8 + (g8 & 1) * 8) * FK_STR + (g8 >> 1) * 8) * 2;

#pragma unroll
    for (int l = 0; l < 4; l++) {
        int c = tid + l * 256;
        int r = c >> 3, ch = c & 7;
        cp16(sbase + (r * FK_STR + ch * 8) * 2,
             qb + (size_t)(m0 + r) * DMODEL + ch * 8);
    }
    cp_commit(); cp_wait<0>(); __syncthreads();

    uint32_t aq[4][4];
#pragma unroll
    for (int kc = 0; kc < 4; kc++)
        ldsm4(sbase + qOff + kc * 32, aq[kc]);
    __syncthreads();

    float o[8][4];
#pragma unroll
    for (int ni = 0; ni < 8; ni++)
#pragma unroll
        for (int e = 0; e < 4; e++) o[ni][e] = 0.0f;
    float mrun0 = -1e30f, mrun1 = -1e30f, lrun0 = 0.0f, lrun1 = 0.0f;

    auto load_kv = [&](int t) {
        uint32_t kd = sbase + (t & 1) * FT_H * 2;
        uint32_t vd = sbase + (2 + (t & 1)) * FT_H * 2;
#pragma unroll
        for (int l = 0; l < 4; l++) {
            int c = tid + l * 256;
            int r = c >> 3, ch = c & 7;
            uint32_t so = (r * FK_STR + ch * 8) * 2;
            size_t  go = (size_t)(t * 128 + r) * DMODEL + ch * 8;
            cp16(kd + so, kb + go);
            cp16(vd + so, vb + go);
        }
        cp_commit();
    };

    load_kv(0);

    const int NTILE = SEQ / 128;
    for (int t = 0; t < NTILE; t++) {
        cp_wait<0>();
        __syncthreads();
        if (t + 1 < NTILE) load_kv(t + 1);

        uint32_t kbuf = sbase + (t & 1) * FT_H * 2;
        uint32_t vbuf = sbase + (2 + (t & 1)) * FT_H * 2;

        float sacc[16][4];
#pragma unroll
        for (int ni = 0; ni < 16; ni++)
#pragma unroll
            for (int e = 0; e < 4; e++) sacc[ni][e] = 0.0f;

        // ---- S = Q @ K^T, pipelined (it = kc*8 + nip) ----
        {
            uint32_t bf2[2][4];
            ldsm4(kbuf + kOff, bf2[0]);
#pragma unroll
            for (int it = 0; it < 32; it++) {
                if (it + 1 < 32) {
                    int kc2 = (it + 1) >> 3, nip2 = (it + 1) & 7;
                    ldsm4(kbuf + kOff + (nip2 * 16 * FK_STR + kc2 * 16) * 2,
                          bf2[(it + 1) & 1]);
                }
                int kc = it >> 3, nip = it & 7;
                mma_f16(sacc[2 * nip    ], aq[kc], &bf2[it & 1][0]);
                mma_f16(sacc[2 * nip + 1], aq[kc], &bf2[it & 1][2]);
            }
        }

        float tmax0 = -1e30f, tmax1 = -1e30f;
#pragma unroll
        for (int ni = 0; ni < 16; ni++) {
            tmax0 = fmaxf(tmax0, fmaxf(sacc[ni][0], sacc[ni][1]));
            tmax1 = fmaxf(tmax1, fmaxf(sacc[ni][2], sacc[ni][3]));
        }
        tmax0 = fmaxf(tmax0, __shfl_xor_sync(0xffffffffu, tmax0, 1));
        tmax0 = fmaxf(tmax0, __shfl_xor_sync(0xffffffffu, tmax0, 2));
        tmax1 = fmaxf(tmax1, __shfl_xor_sync(0xffffffffu, tmax1, 1));
        tmax1 = fmaxf(tmax1, __shfl_xor_sync(0xffffffffu, tmax1, 2));

        float nm0 = fmaxf(mrun0, tmax0);
        float nm1 = fmaxf(mrun1, tmax1);
        float sc0 = __expf(mrun0 - nm0);
        float sc1 = __expf(mrun1 - nm1);
        mrun0 = nm0; mrun1 = nm1;

        float sum0 = 0.0f, sum1 = 0.0f;
#pragma unroll
        for (int ni = 0; ni < 16; ni++) {
            sacc[ni][0] = __expf(sacc[ni][0] - nm0);
            sacc[ni][1] = __expf(sacc[ni][1] - nm0);
            sacc[ni][2] = __expf(sacc[ni][2] - nm1);
            sacc[ni][3] = __expf(sacc[ni][3] - nm1);
            sum0 += sacc[ni][0] + sacc[ni][1];
            sum1 += sacc[ni][2] + sacc[ni][3];
        }
        sum0 += __shfl_xor_sync(0xffffffffu, sum0, 1);
        sum0 += __shfl_xor_sync(0xffffffffu, sum0, 2);
        sum1 += __shfl_xor_sync(0xffffffffu, sum1, 1);
        sum1 += __shfl_xor_sync(0xffffffffu, sum1, 2);
        lrun0 = lrun0 * sc0 + sum0;
        lrun1 = lrun1 * sc1 + sum1;

#pragma unroll
        for (int ni = 0; ni < 8; ni++) {
            o[ni][0] *= sc0; o[ni][1] *= sc0;
            o[ni][2] *= sc1; o[ni][3] *= sc1;
        }

        uint32_t pA[8][4];
#pragma unroll
        for (int kc = 0; kc < 8; kc++) {
            pA[kc][0] = pack2(sacc[2 * kc    ][0], sacc[2 * kc    ][1]);
            pA[kc][1] = pack2(sacc[2 * kc    ][2], sacc[2 * kc    ][3]);
            pA[kc][2] = pack2(sacc[2 * kc + 1][0], sacc[2 * kc + 1][1]);
            pA[kc][3] = pack2(sacc[2 * kc + 1][2], sacc[2 * kc + 1][3]);
        }

        // ---- O += P @ V, pipelined (it = kc*4 + nip) ----
        {
            uint32_t bb2[2][4];
            ldsm4t(vbuf + vOff, bb2[0]);
#pragma unroll
            for (int it = 0; it < 32; it++) {
                if (it + 1 < 32) {
                    int kc2 = (it + 1) >> 2, nip2 = (it + 1) & 3;
                    ldsm4t(vbuf + vOff + (kc2 * 16 * FK_STR + nip2 * 16) * 2,
                           bb2[(it + 1) & 1]);
                }
                int kc = it >> 2, nip = it & 3;
                mma_f16(o[2 * nip    ], pA[kc], &bb2[it & 1][0]);
                mma_f16(o[2 * nip + 1], pA[kc], &bb2[it & 1][2]);
            }
        }
    }

    float inv0 = 1.0f / lrun0;
    float inv1 = 1.0f / lrun1;
    int r0 = m0 + warp * 16 + grp;
    __half* cb = ctx + ((size_t)b * SEQ) * DMODEL + h * HEADDIM;
#pragma unroll
    for (int ni = 0; ni < 8; ni++) {
        int col = ni * 8 + 2 * tig;
        *(__half2*)(cb + (size_t)(r0    ) * DMODEL + col) =
            __floats2half2_rn(o[ni][0] * inv0, o[ni][1] * inv0);
        *(__half2*)(cb + (size_t)(r0 + 8) * DMODEL + col) =
            __floats2half2_rn(o[ni][2] * inv1, o[ni][3] * inv1);
    }
}

// ---------------------------------------------------------------------------
// Fused residual + LayerNorm; fp32 out + optional half out.
// ---------------------------------------------------------------------------
__global__ __launch_bounds__(256)
void ln_kernel(const float* __restrict__ a, const float* __restrict__ b,
               const float* __restrict__ g, const float* __restrict__ be,
               float* __restrict__ out, __half* __restrict__ outh)
{
    const int D = DMODEL;
    size_t row = blockIdx.x;
    const float* pa = a + row * D;
    const float* pb = b + row * D;
    int tid = threadIdx.x;
    __shared__ float red[256];

    float x[4];
    float s = 0.0f;
#pragma unroll
    for (int i = 0; i < 4; i++) {
        int c = tid + i * 256;
        x[i] = pa[c] + pb[c];
        s += x[i];
    }
    red[tid] = s;
    __syncthreads();
    for (int t = 128; t > 0; t >>= 1) {
        if (tid < t) red[tid] += red[tid + t];
        __syncthreads();
    }
    float mu = red[0] * (1.0f / D);
    __syncthreads();

    float v = 0.0f;
#pragma unroll
    for (int i = 0; i < 4; i++) {
        float d = x[i] - mu;
        v += d * d;
    }
    red[tid] = v;
    __syncthreads();
    for (int t = 128; t > 0; t >>= 1) {
        if (tid < t) red[tid] += red[tid + t];
        __syncthreads();
    }
    float var = red[0] * (1.0f / D);
    float r = rsqrtf(var + 1e-5f);
#pragma unroll
    for (int i = 0; i < 4; i++) {
        int c = tid + i * 256;
        float y = (x[i] - mu) * r * g[c] + be[c];
        out[row * D + c] = y;
        if (outh) outh[row * D + c] = __float2half_rn(y);
    }
}

// ---------------------------------------------------------------------------
// Host-side launch
// ---------------------------------------------------------------------------
static void* symptr_v(const void* sym)
{
    void* p = nullptr;
    cudaGetSymbolAddress(&p, sym);
    return p;
}

extern "C" void kernel_launch(void* const* d_in, const int* in_sizes, int n_in,
                              void* d_out, int out_size)
{
    const float* src = (const float*)d_in[0];
    const float* tau = (const float*)d_in[1];
    const float* Wq  = (const float*)d_in[2];
    const float* bq  = (const float*)d_in[3];
    const float* Wk  = (const float*)d_in[4];
    const float* bk  = (const float*)d_in[5];
    const float* Wv  = (const float*)d_in[6];
    const float* bv  = (const float*)d_in[7];
    const float* Wo  = (const float*)d_in[8];
    const float* bo  = (const float*)d_in[9];
    const float* W1  = (const float*)d_in[10];
    const float* b1  = (const float*)d_in[11];
    const float* W2  = (const float*)d_in[12];
    const float* b2  = (const float*)d_in[13];
    const float* g1  = (const float*)d_in[14];
    const float* be1 = (const float*)d_in[15];
    const float* g2  = (const float*)d_in[16];
    const float* be2 = (const float*)d_in[17];
    float* out = (float*)d_out;

    __half* srch = (__half*)symptr_v(g_srch);
    __half* qh   = (__half*)symptr_v(g_qh);
    __half* kh   = (__half*)symptr_v(g_kh);
    __half* vh   = (__half*)symptr_v(g_vh);
    __half* ctxh = (__half*)symptr_v(g_ctxh);
    __half* h1h  = (__half*)symptr_v(g_h1h);
    __half* f1h  = (__half*)symptr_v(g_f1h);
    float*  ao   = (float*)symptr_v(g_ao);
    float*  h1f  = (float*)symptr_v(g_h1f);
    float*  f2   = (float*)symptr_v(g_f2);
    __half* wqH  = (__half*)symptr_v(g_wqH);
    __half* wkH  = (__half*)symptr_v(g_wkH);
    __half* wvH  = (__half*)symptr_v(g_wvH);
    __half* woH  = (__half*)symptr_v(g_woH);
    __half* w1H  = (__half*)symptr_v(g_w1H);
    __half* w2H  = (__half*)symptr_v(g_w2H);

    cudaFuncSetAttribute(flash_kernel,
                         cudaFuncAttributeMaxDynamicSharedMemorySize, FA_SMEM_BYTES);
    cudaFuncSetAttribute(hgemm<true,  false, true,  false>,
                         cudaFuncAttributeMaxDynamicSharedMemorySize, GM_SMEM_BYTES);
    cudaFuncSetAttribute(hgemm<false, false, false, true>,
                         cudaFuncAttributeMaxDynamicSharedMemorySize, GM_SMEM_BYTES);
    cudaFuncSetAttribute(hgemm<false, true,  true,  false>,
                         cudaFuncAttributeMaxDynamicSharedMemorySize, GM_SMEM_BYTES);

    // ---- prep: single fused f2h of all weights + src ----
    {
        const int nW = DMODEL * DMODEL / 4;        // 262144
        const int nF = DMODEL * DFF / 4;           // 1048576
        const int nS = TOKENS * DMODEL / 4;        // 1048576
        F2HJob job;
        job.in[0] = (const float4*)Wq;  job.out[0] = (__half2*)wqH;
        job.in[1] = (const float4*)Wk;  job.out[1] = (__half2*)wkH;
        job.in[2] = (const float4*)Wv;  job.out[2] = (__half2*)wvH;
        job.in[3] = (const float4*)Wo;  job.out[3] = (__half2*)woH;
        job.in[4] = (const float4*)W1;  job.out[4] = (__half2*)w1H;
        job.in[5] = (const float4*)W2;  job.out[5] = (__half2*)w2H;
        job.in[6] = (const float4*)src; job.out[6] = (__half2*)srch;
        int acc = 0;
        int sizes[7] = { nW, nW, nW, nW, nF, nF, nS };
        for (int s = 0; s < 7; s++) { acc += sizes[s]; job.end[s] = acc; }
        f2h_all_kernel<<<(acc + 255) / 256, 256>>>(job);
    }

    // ---- QKV (+RoPE, q pre-scaled) ----
    hgemm<true, false, true, false>
        <<<dim3(DMODEL / 128, TOKENS / 128, 3), 256, GM_SMEM_BYTES>>>(
        TOKENS, DMODEL, DMODEL, srch, wqH, wkH, wvH,
        qh, kh, vh, nullptr, DMODEL, bq, bk, bv, tau);

    // ---- flash attention -> ctx (half) ----
    flash_kernel<<<dim3(SEQ / 128, BATCH * NHEADS), 256, FA_SMEM_BYTES>>>(
        qh, kh, vh, ctxh);

    // ---- output projection -> ao (fp32) ----
    hgemm<false, false, false, true>
        <<<dim3(DMODEL / 128, TOKENS / 128, 1), 256, GM_SMEM_BYTES>>>(
        TOKENS, DMODEL, DMODEL, ctxh, woH, nullptr, nullptr,
        nullptr, nullptr, nullptr, ao, DMODEL, bo, nullptr, nullptr, nullptr);

    // ---- LN1 -> h1 (fp32 + half) ----
    ln_kernel<<<TOKENS, 256>>>(src, ao, g1, be1, h1f, h1h);

    // ---- FFN1 (GELU) -> f1 (half) ----
    hgemm<false, true, true, false>
        <<<dim3(DFF / 128, TOKENS / 128, 1), 256, GM_SMEM_BYTES>>>(
        TOKENS, DFF, DMODEL, h1h, w1H, nullptr, nullptr,
        f1h, nullptr, nullptr, nullptr, DFF, b1, nullptr, nullptr, nullptr);

    // ---- FFN2 -> f2 (fp32) ----
    hgemm<false, false, false, true>
        <<<dim3(DMODEL / 128, TOKENS / 128, 1), 256, GM_SMEM_BYTES>>>(
        TOKENS, DMODEL, DFF, f1h, w2H, nullptr, nullptr,
        nullptr, nullptr, nullptr, f2, DMODEL, b2, nullptr, nullptr, nullptr);

    // ---- LN2 -> out ----
    ln_kernel<<<TOKENS, 256>>>(h1f, f2, g2, be2, out, nullptr);

    (void)in_sizes; (void)n_in; (void)out_size;
}

// round 10
// speedup vs baseline: 7.1307x; 1.0106x over previous
#include <cuda_runtime.h>
#include <cuda_fp16.h>
#include <math.h>
#include <cstdint>

// ---------------------------------------------------------------------------
// Problem constants
// ---------------------------------------------------------------------------
#define BATCH   2
#define SEQ     2048
#define DMODEL  1024
#define NHEADS  16
#define HEADDIM 64
#define DFF     4096
#define TOKENS  (BATCH * SEQ)          // 4096

// ---------------------------------------------------------------------------
// Scratch (static device allocations)
// ---------------------------------------------------------------------------
__device__ __half g_srch[TOKENS * DMODEL];
__device__ __half g_qh  [TOKENS * DMODEL];
__device__ __half g_kh  [TOKENS * DMODEL];
__device__ __half g_vh  [TOKENS * DMODEL];
__device__ __half g_ctxh[TOKENS * DMODEL];
__device__ __half g_h1h [TOKENS * DMODEL];
__device__ __half g_f1h [(size_t)TOKENS * DFF];
__device__ float  g_ao  [TOKENS * DMODEL];
__device__ float  g_h1f [TOKENS * DMODEL];
__device__ float  g_f2  [TOKENS * DMODEL];
// half weights, natural [K][N] layout
__device__ __half g_wqH[DMODEL * DMODEL];
__device__ __half g_wkH[DMODEL * DMODEL];
__device__ __half g_wvH[DMODEL * DMODEL];
__device__ __half g_woH[DMODEL * DMODEL];
__device__ __half g_w1H[(size_t)DMODEL * DFF];
__device__ __half g_w2H[(size_t)DFF * DMODEL];

// ---------------------------------------------------------------------------
// PTX helpers
// ---------------------------------------------------------------------------
__device__ __forceinline__ uint32_t smem_u32(const void* p) {
    return (uint32_t)__cvta_generic_to_shared(p);
}
__device__ __forceinline__ void cp16(uint32_t s, const void* g) {
    asm volatile("cp.async.cg.shared.global [%0], [%1], 16;" :: "r"(s), "l"(g));
}
__device__ __forceinline__ void cp_commit() {
    asm volatile("cp.async.commit_group;");
}
template<int N>
__device__ __forceinline__ void cp_wait() {
    asm volatile("cp.async.wait_group %0;" :: "n"(N));
}
__device__ __forceinline__ uint32_t pack2(float lo, float hi) {
    __half2 h = __floats2half2_rn(lo, hi);
    return *reinterpret_cast<uint32_t*>(&h);
}
__device__ __forceinline__ void ldsm4(uint32_t addr, uint32_t* r) {
    asm volatile("ldmatrix.sync.aligned.m8n8.x4.shared.b16 {%0,%1,%2,%3}, [%4];"
        : "=r"(r[0]), "=r"(r[1]), "=r"(r[2]), "=r"(r[3]) : "r"(addr));
}
__device__ __forceinline__ void ldsm4t(uint32_t addr, uint32_t* r) {
    asm volatile("ldmatrix.sync.aligned.m8n8.x4.trans.shared.b16 {%0,%1,%2,%3}, [%4];"
        : "=r"(r[0]), "=r"(r[1]), "=r"(r[2]), "=r"(r[3]) : "r"(addr));
}
__device__ __forceinline__ void mma_f16(float* c, const uint32_t* a, const uint32_t* b) {
    asm volatile(
        "mma.sync.aligned.m16n8k16.row.col.f32.f16.f16.f32 "
        "{%0,%1,%2,%3}, {%4,%5,%6,%7}, {%8,%9}, {%0,%1,%2,%3};"
        : "+f"(c[0]), "+f"(c[1]), "+f"(c[2]), "+f"(c[3])
        : "r"(a[0]), "r"(a[1]), "r"(a[2]), "r"(a[3]), "r"(b[0]), "r"(b[1]));
}

// ---------------------------------------------------------------------------
// FP16 GEMM: C[M,N] = A[M,K](half) @ W[K,N](half) + bias.
// BM=128, BN=128, BK=32, 8 warps (warp tile 64x32), 2 CTAs/SM.
// 4-stage cp.async ring; LDSM for the NEXT half-stage is interleaved
// instruction-by-instruction into the current half-stage's 16 MMAs
// (asm volatile order is preserved -> smem and tensor pipes overlap).
// ---------------------------------------------------------------------------
#define GM_ASTR 40                       // A smem row stride (halves)
#define GM_BSTR 136                      // B smem row stride (halves)
#define GM_AH   (128 * GM_ASTR)          // 5120 halves
#define GM_BH   (32 * GM_BSTR)           // 4352 halves
#define GM_STG  (GM_AH + GM_BH)          // 9472 halves / stage
#define GM_SMEM_BYTES (4 * GM_STG * 2)   // 75776

template<bool QKV, bool GELU, bool OH, bool OF>
__global__ __launch_bounds__(256, 2)
void hgemm(int M, int N, int K,
           const __half* __restrict__ A,
           const __half* __restrict__ W0, const __half* __restrict__ W1_,
           const __half* __restrict__ W2_,
           __half* __restrict__ Ch0, __half* __restrict__ Ch1,
           __half* __restrict__ Ch2,
           float* __restrict__ Cf,
           int ldc,
           const float* __restrict__ bias0, const float* __restrict__ bias1,
           const float* __restrict__ bias2,
           const float* __restrict__ tau)
{
    extern __shared__ __half hsm[];

    const __half* W    = W0;
    __half*       Ch   = Ch0;
    const float*  bias = bias0;
    bool rope = false;
    float oscale = 1.0f;
    if (QKV) {
        int z = blockIdx.z;
        if (z == 1)      { W = W1_; Ch = Ch1; bias = bias1; }
        else if (z == 2) { W = W2_; Ch = Ch2; bias = bias2; }
        rope = (z < 2);
        if (z == 0) oscale = 0.125f;
    }

    const int tid  = threadIdx.x;
    const int lane = tid & 31;
    const int warp = tid >> 5;
    const int grp  = lane >> 2;
    const int tig  = lane & 3;
    const int wm0  = (warp >> 2) * 64;    // 0 or 64
    const int wn0  = (warp & 3) * 32;     // 0,32,64,96
    const int m0 = blockIdx.y * 128;
    const int n0 = blockIdx.x * 128;

    const uint32_t sbase = smem_u32(hsm);
    const uint32_t aOff = ((wm0 + (lane & 15)) * GM_ASTR + (lane >> 4) * 8) * 2;
    const int g8 = lane >> 3, r8 = lane & 7;
    const uint32_t bOff = (((g8 & 1) * 8 + r8) * GM_BSTR + wn0 + (g8 >> 1) * 8) * 2;

    float acc[4][4][4];
#pragma unroll
    for (int mi = 0; mi < 4; mi++)
#pragma unroll
        for (int ni = 0; ni < 4; ni++)
#pragma unroll
            for (int e = 0; e < 4; e++) acc[mi][ni][e] = 0.0f;

    auto load_stage = [&](int s) {
        uint32_t ab = sbase + (s & 3) * GM_STG * 2;
        uint32_t bb = ab + GM_AH * 2;
        int k0 = s * 32;
#pragma unroll
        for (int l = 0; l < 2; l++) {
            int c = tid + l * 256;
            int m = c >> 2, ch = c & 3;
            cp16(ab + (m * GM_ASTR + ch * 8) * 2,
                 A + (size_t)(m0 + m) * K + k0 + ch * 8);
        }
#pragma unroll
        for (int l = 0; l < 2; l++) {
            int c = tid + l * 256;
            int kk = c >> 4, nq = c & 15;
            cp16(bb + (kk * GM_BSTR + nq * 8) * 2,
                 W + (size_t)(k0 + kk) * N + n0 + nq * 8);
        }
        cp_commit();
    };

    // register fragment double-buffer
    uint32_t af[2][4][4], bf[2][4][2];

    auto load_frags = [&](int s, int kk, int p) {
        uint32_t ab = sbase + (s & 3) * GM_STG * 2;
        uint32_t bb = ab + GM_AH * 2;
#pragma unroll
        for (int mi = 0; mi < 4; mi++)
            ldsm4(ab + aOff + (mi * 16 * GM_ASTR + kk) * 2, af[p][mi]);
#pragma unroll
        for (int nip = 0; nip < 2; nip++)
            ldsm4t(bb + bOff + (kk * GM_BSTR + nip * 16) * 2, &bf[p][2 * nip][0]);
    };

    // 16 MMAs on buffer p; interleave the 6 LDSMs for (s_ld, kk_ld) -> buffer q.
    auto mma_block = [&](int p, int q, int s_ld, int kk_ld) {
        uint32_t ab = sbase + (s_ld & 3) * GM_STG * 2;
        uint32_t bb = ab + GM_AH * 2;
        mma_f16(acc[0][0], af[p][0], bf[p][0]);
        mma_f16(acc[0][1], af[p][0], bf[p][1]);
        ldsm4(ab + aOff + (0 * 16 * GM_ASTR + kk_ld) * 2, af[q][0]);
        mma_f16(acc[0][2], af[p][0], bf[p][2]);
        mma_f16(acc[0][3], af[p][0], bf[p][3]);
        ldsm4(ab + aOff + (1 * 16 * GM_ASTR + kk_ld) * 2, af[q][1]);
        mma_f16(acc[1][0], af[p][1], bf[p][0]);
        mma_f16(acc[1][1], af[p][1], bf[p][1]);
        ldsm4(ab + aOff + (2 * 16 * GM_ASTR + kk_ld) * 2, af[q][2]);
        mma_f16(acc[1][2], af[p][1], bf[p][2]);
        mma_f16(acc[1][3], af[p][1], bf[p][3]);
        ldsm4(ab + aOff + (3 * 16 * GM_ASTR + kk_ld) * 2, af[q][3]);
        mma_f16(acc[2][0], af[p][2], bf[p][0]);
        mma_f16(acc[2][1], af[p][2], bf[p][1]);
        ldsm4t(bb + bOff + (kk_ld * GM_BSTR + 0) * 2, &bf[q][0][0]);
        mma_f16(acc[2][2], af[p][2], bf[p][2]);
        mma_f16(acc[2][3], af[p][2], bf[p][3]);
        ldsm4t(bb + bOff + (kk_ld * GM_BSTR + 16) * 2, &bf[q][2][0]);
        mma_f16(acc[3][0], af[p][3], bf[p][0]);
        mma_f16(acc[3][1], af[p][3], bf[p][1]);
        mma_f16(acc[3][2], af[p][3], bf[p][2]);
        mma_f16(acc[3][3], af[p][3], bf[p][3]);
    };

    const int S = K / 32;
    load_stage(0); load_stage(1); load_stage(2);
    cp_wait<2>();          // stage 0 complete
    __syncthreads();
    load_frags(0, 0, 0);

    for (int s = 0; s < S; s++) {
        // phase A: compute kk=0 frags (p0), prefetch kk=16 of stage s -> p1
        mma_block(0, 1, s, 16);
        // stage s+1 visibility + ring-slot reuse barrier
        int rem = S - 2 - s;
        if (rem >= 2)      cp_wait<2>();
        else if (rem == 1) cp_wait<1>();
        else               cp_wait<0>();
        __syncthreads();
        if (s + 3 < S) load_stage(s + 3);
        // phase B: compute kk=16 frags (p1), prefetch kk=0 of stage s+1 -> p0
        // (for s == S-1 this reads stale ring data that is never consumed)
        mma_block(1, 0, s + 1, 0);
    }

    // ---- epilogue ----
#pragma unroll
    for (int mi = 0; mi < 4; mi++) {
#pragma unroll
        for (int h = 0; h < 2; h++) {
            int row = m0 + wm0 + mi * 16 + grp + h * 8;
            float t = 0.0f;
            if (QKV) t = tau[row];
#pragma unroll
            for (int ni = 0; ni < 4; ni++) {
                int gcol = n0 + wn0 + ni * 8 + 2 * tig;
                float v0 = acc[mi][ni][h * 2 + 0];
                float v1 = acc[mi][ni][h * 2 + 1];
                if (bias) { v0 += bias[gcol]; v1 += bias[gcol + 1]; }
                if (GELU) {
                    v0 = 0.5f * v0 * (1.0f + erff(v0 * 0.7071067811865475f));
                    v1 = 0.5f * v1 * (1.0f + erff(v1 * 0.7071067811865475f));
                }
                if (QKV && rope) {
                    int j = (gcol & 63) >> 1;
                    float inv = __expf(-0.28782313662425572f * (float)j);
                    float sn, cs;
                    sincosf(t * inv, &sn, &cs);
                    float r0 = v0 * cs - v1 * sn;
                    float r1 = v1 * cs + v0 * sn;
                    v0 = r0 * oscale; v1 = r1 * oscale;
                }
                if (OH) {
                    *(__half2*)(Ch + (size_t)row * ldc + gcol) =
                        __floats2half2_rn(v0, v1);
                }
                if (OF) {
                    *(float2*)(Cf + (size_t)row * ldc + gcol) = make_float2(v0, v1);
                }
            }
        }
    }
}

// ---------------------------------------------------------------------------
// Fused float->half conversion of all 7 buffers in one launch.
// ---------------------------------------------------------------------------
struct F2HJob {
    const float4* in[7];
    __half2*      out[7];
    int           end[7];   // cumulative end offsets (in float4 units)
};

__global__ __launch_bounds__(256)
void f2h_all_kernel(F2HJob job)
{
    int i = blockIdx.x * 256 + threadIdx.x;
    int seg = 0, base = 0;
#pragma unroll
    for (int s = 0; s < 7; s++) {
        if (i >= job.end[s]) { seg = s + 1; base = job.end[s]; }
    }
    if (seg >= 7) return;
    int off = i - base;
    float4 v = job.in[seg][off];
    job.out[seg][2 * off]     = __floats2half2_rn(v.x, v.y);
    job.out[seg][2 * off + 1] = __floats2half2_rn(v.z, v.w);
}

// ---------------------------------------------------------------------------
// FP16 flash attention with ldmatrix + cp.async K/V double buffers.
// ---------------------------------------------------------------------------
#define FK_STR  72
#define FT_H    (128 * FK_STR)
#define FA_SMEM_BYTES (4 * FT_H * 2)      // 73728

__global__ __launch_bounds__(256)
void flash_kernel(const __half* __restrict__ q, const __half* __restrict__ k,
                  const __half* __restrict__ v, __half* __restrict__ ctx)
{
    extern __shared__ __half fsm[];
    const uint32_t sbase = smem_u32(fsm);

    const int tid  = threadIdx.x;
    const int lane = tid & 31;
    const int warp = tid >> 5;
    const int grp  = lane >> 2;
    const int tig  = lane & 3;
    const int g8 = lane >> 3, r8 = lane & 7;

    const int m0 = blockIdx.x * 128;
    const int bh = blockIdx.y;
    const int b  = bh >> 4;
    const int h  = bh & 15;

    const __half* qb = q + ((size_t)b * SEQ) * DMODEL + h * HEADDIM;
    const __half* kb = k + ((size_t)b * SEQ) * DMODEL + h * HEADDIM;
    const __half* vb = v + ((size_t)b * SEQ) * DMODEL + h * HEADDIM;

    const uint32_t qOff = ((warp * 16 + (lane & 15)) * FK_STR + (lane >> 4) * 8) * 2;
    const uint32_t kOff = ((r8 + (g8 >> 1) * 8) * FK_STR + (g8 & 1) * 8) * 2;
    const uint32_t vOff = ((r8 + (g8 & 1) * 8) * FK_STR + (g8 >> 1) * 8) * 2;

#pragma unroll
    for (int l = 0; l < 4; l++) {
        int c = tid + l * 256;
        int r = c >> 3, ch = c & 7;
        cp16(sbase + (r * FK_STR + ch * 8) * 2,
             qb + (size_t)(m0 + r) * DMODEL + ch * 8);
    }
    cp_commit(); cp_wait<0>(); __syncthreads();

    uint32_t aq[4][4];
#pragma unroll
    for (int kc = 0; kc < 4; kc++)
        ldsm4(sbase + qOff + kc * 32, aq[kc]);
    __syncthreads();

    float o[8][4];
#pragma unroll
    for (int ni = 0; ni < 8; ni++)
#pragma unroll
        for (int e = 0; e < 4; e++) o[ni][e] = 0.0f;
    float mrun0 = -1e30f, mrun1 = -1e30f, lrun0 = 0.0f, lrun1 = 0.0f;

    auto load_kv = [&](int t) {
        uint32_t kd = sbase + (t & 1) * FT_H * 2;
        uint32_t vd = sbase + (2 + (t & 1)) * FT_H * 2;
#pragma unroll
        for (int l = 0; l < 4; l++) {
            int c = tid + l * 256;
            int r = c >> 3, ch = c & 7;
            uint32_t so = (r * FK_STR + ch * 8) * 2;
            size_t  go = (size_t)(t * 128 + r) * DMODEL + ch * 8;
            cp16(kd + so, kb + go);
            cp16(vd + so, vb + go);
        }
        cp_commit();
    };

    load_kv(0);

    const int NTILE = SEQ / 128;
    for (int t = 0; t < NTILE; t++) {
        cp_wait<0>();
        __syncthreads();
        if (t + 1 < NTILE) load_kv(t + 1);

        uint32_t kbuf = sbase + (t & 1) * FT_H * 2;
        uint32_t vbuf = sbase + (2 + (t & 1)) * FT_H * 2;

        float sacc[16][4];
#pragma unroll
        for (int ni = 0; ni < 16; ni++)
#pragma unroll
            for (int e = 0; e < 4; e++) sacc[ni][e] = 0.0f;

        // ---- S = Q @ K^T, pipelined (it = kc*8 + nip) ----
        {
            uint32_t bf2[2][4];
            ldsm4(kbuf + kOff, bf2[0]);
#pragma unroll
            for (int it = 0; it < 32; it++) {
                if (it + 1 < 32) {
                    int kc2 = (it + 1) >> 3, nip2 = (it + 1) & 7;
                    ldsm4(kbuf + kOff + (nip2 * 16 * FK_STR + kc2 * 16) * 2,
                          bf2[(it + 1) & 1]);
                }
                int kc = it >> 3, nip = it & 7;
                mma_f16(sacc[2 * nip    ], aq[kc], &bf2[it & 1][0]);
                mma_f16(sacc[2 * nip + 1], aq[kc], &bf2[it & 1][2]);
            }
        }

        float tmax0 = -1e30f, tmax1 = -1e30f;
#pragma unroll
        for (int ni = 0; ni < 16; ni++) {
            tmax0 = fmaxf(tmax0, fmaxf(sacc[ni][0], sacc[ni][1]));
            tmax1 = fmaxf(tmax1, fmaxf(sacc[ni][2], sacc[ni][3]));
        }
        tmax0 = fmaxf(tmax0, __shfl_xor_sync(0xffffffffu, tmax0, 1));
        tmax0 = fmaxf(tmax0, __shfl_xor_sync(0xffffffffu, tmax0, 2));
        tmax1 = fmaxf(tmax1, __shfl_xor_sync(0xffffffffu, tmax1, 1));
        tmax1 = fmaxf(tmax1, __shfl_xor_sync(0xffffffffu, tmax1, 2));

        float nm0 = fmaxf(mrun0, tmax0);
        float nm1 = fmaxf(mrun1, tmax1);
        float sc0 = __expf(mrun0 - nm0);
        float sc1 = __expf(mrun1 - nm1);
        mrun0 = nm0; mrun1 = nm1;

        float sum0 = 0.0f, sum1 = 0.0f;
#pragma unroll
        for (int ni = 0; ni < 16; ni++) {
            sacc[ni][0] = __expf(sacc[ni][0] - nm0);
            sacc[ni][1] = __expf(sacc[ni][1] - nm0);
            sacc[ni][2] = __expf(sacc[ni][2] - nm1);
            sacc[ni][3] = __expf(sacc[ni][3] - nm1);
            sum0 += sacc[ni][0] + sacc[ni][1];
            sum1 += sacc[ni][2] + sacc[ni][3];
        }
        sum0 += __shfl_xor_sync(0xffffffffu, sum0, 1);
        sum0 += __shfl_xor_sync(0xffffffffu, sum0, 2);
        sum1 += __shfl_xor_sync(0xffffffffu, sum1, 1);
        sum1 += __shfl_xor_sync(0xffffffffu, sum1, 2);
        lrun0 = lrun0 * sc0 + sum0;
        lrun1 = lrun1 * sc1 + sum1;

#pragma unroll
        for (int ni = 0; ni < 8; ni++) {
            o[ni][0] *= sc0; o[ni][1] *= sc0;
            o[ni][2] *= sc1; o[ni][3] *= sc1;
        }

        uint32_t pA[8][4];
#pragma unroll
        for (int kc = 0; kc < 8; kc++) {
            pA[kc][0] = pack2(sacc[2 * kc    ][0], sacc[2 * kc    ][1]);
            pA[kc][1] = pack2(sacc[2 * kc    ][2], sacc[2 * kc    ][3]);
            pA[kc][2] = pack2(sacc[2 * kc + 1][0], sacc[2 * kc + 1][1]);
            pA[kc][3] = pack2(sacc[2 * kc + 1][2], sacc[2 * kc + 1][3]);
        }

        // ---- O += P @ V, pipelined (it = kc*4 + nip) ----
        {
            uint32_t bb2[2][4];
            ldsm4t(vbuf + vOff, bb2[0]);
#pragma unroll
            for (int it = 0; it < 32; it++) {
                if (it + 1 < 32) {
                    int kc2 = (it + 1) >> 2, nip2 = (it + 1) & 3;
                    ldsm4t(vbuf + vOff + (kc2 * 16 * FK_STR + nip2 * 16) * 2,
                           bb2[(it + 1) & 1]);
                }
                int kc = it >> 2, nip = it & 3;
                mma_f16(o[2 * nip    ], pA[kc], &bb2[it & 1][0]);
                mma_f16(o[2 * nip + 1], pA[kc], &bb2[it & 1][2]);
            }
        }
    }

    float inv0 = 1.0f / lrun0;
    float inv1 = 1.0f / lrun1;
    int r0 = m0 + warp * 16 + grp;
    __half* cb = ctx + ((size_t)b * SEQ) * DMODEL + h * HEADDIM;
#pragma unroll
    for (int ni = 0; ni < 8; ni++) {
        int col = ni * 8 + 2 * tig;
        *(__half2*)(cb + (size_t)(r0    ) * DMODEL + col) =
            __floats2half2_rn(o[ni][0] * inv0, o[ni][1] * inv0);
        *(__half2*)(cb + (size_t)(r0 + 8) * DMODEL + col) =
            __floats2half2_rn(o[ni][2] * inv1, o[ni][3] * inv1);
    }
}

// ---------------------------------------------------------------------------
// Fused residual + LayerNorm; fp32 out + optional half out.
// ---------------------------------------------------------------------------
__global__ __launch_bounds__(256)
void ln_kernel(const float* __restrict__ a, const float* __restrict__ b,
               const float* __restrict__ g, const float* __restrict__ be,
               float* __restrict__ out, __half* __restrict__ outh)
{
    const int D = DMODEL;
    size_t row = blockIdx.x;
    const float* pa = a + row * D;
    const float* pb = b + row * D;
    int tid = threadIdx.x;
    __shared__ float red[256];

    float x[4];
    float s = 0.0f;
#pragma unroll
    for (int i = 0; i < 4; i++) {
        int c = tid + i * 256;
        x[i] = pa[c] + pb[c];
        s += x[i];
    }
    red[tid] = s;
    __syncthreads();
    for (int t = 128; t > 0; t >>= 1) {
        if (tid < t) red[tid] += red[tid + t];
        __syncthreads();
    }
    float mu = red[0] * (1.0f / D);
    __syncthreads();

    float v = 0.0f;
#pragma unroll
    for (int i = 0; i < 4; i++) {
        float d = x[i] - mu;
        v += d * d;
    }
    red[tid] = v;
    __syncthreads();
    for (int t = 128; t > 0; t >>= 1) {
        if (tid < t) red[tid] += red[tid + t];
        __syncthreads();
    }
    float var = red[0] * (1.0f / D);
    float r = rsqrtf(var + 1e-5f);
#pragma unroll
    for (int i = 0; i < 4; i++) {
        int c = tid + i * 256;
        float y = (x[i] - mu) * r * g[c] + be[c];
        out[row * D + c] = y;
        if (outh) outh[row * D + c] = __float2half_rn(y);
    }
}

// ---------------------------------------------------------------------------
// Host-side launch
// ---------------------------------------------------------------------------
static void* symptr_v(const void* sym)
{
    void* p = nullptr;
    cudaGetSymbolAddress(&p, sym);
    return p;
}

extern "C" void kernel_launch(void* const* d_in, const int* in_sizes, int n_in,
                              void* d_out, int out_size)
{
    const float* src = (const float*)d_in[0];
    const float* tau = (const float*)d_in[1];
    const float* Wq  = (const float*)d_in[2];
    const float* bq  = (const float*)d_in[3];
    const float* Wk  = (const float*)d_in[4];
    const float* bk  = (const float*)d_in[5];
    const float* Wv  = (const float*)d_in[6];
    const float* bv  = (const float*)d_in[7];
    const float* Wo  = (const float*)d_in[8];
    const float* bo  = (const float*)d_in[9];
    const float* W1  = (const float*)d_in[10];
    const float* b1  = (const float*)d_in[11];
    const float* W2  = (const float*)d_in[12];
    const float* b2  = (const float*)d_in[13];
    const float* g1  = (const float*)d_in[14];
    const float* be1 = (const float*)d_in[15];
    const float* g2  = (const float*)d_in[16];
    const float* be2 = (const float*)d_in[17];
    float* out = (float*)d_out;

    __half* srch = (__half*)symptr_v(g_srch);
    __half* qh   = (__half*)symptr_v(g_qh);
    __half* kh   = (__half*)symptr_v(g_kh);
    __half* vh   = (__half*)symptr_v(g_vh);
    __half* ctxh = (__half*)symptr_v(g_ctxh);
    __half* h1h  = (__half*)symptr_v(g_h1h);
    __half* f1h  = (__half*)symptr_v(g_f1h);
    float*  ao   = (float*)symptr_v(g_ao);
    float*  h1f  = (float*)symptr_v(g_h1f);
    float*  f2   = (float*)symptr_v(g_f2);
    __half* wqH  = (__half*)symptr_v(g_wqH);
    __half* wkH  = (__half*)symptr_v(g_wkH);
    __half* wvH  = (__half*)symptr_v(g_wvH);
    __half* woH  = (__half*)symptr_v(g_woH);
    __half* w1H  = (__half*)symptr_v(g_w1H);
    __half* w2H  = (__half*)symptr_v(g_w2H);

    cudaFuncSetAttribute(flash_kernel,
                         cudaFuncAttributeMaxDynamicSharedMemorySize, FA_SMEM_BYTES);
    cudaFuncSetAttribute(hgemm<true,  false, true,  false>,
                         cudaFuncAttributeMaxDynamicSharedMemorySize, GM_SMEM_BYTES);
    cudaFuncSetAttribute(hgemm<false, false, false, true>,
                         cudaFuncAttributeMaxDynamicSharedMemorySize, GM_SMEM_BYTES);
    cudaFuncSetAttribute(hgemm<false, true,  true,  false>,
                         cudaFuncAttributeMaxDynamicSharedMemorySize, GM_SMEM_BYTES);

    // ---- prep: single fused f2h of all weights + src ----
    {
        const int nW = DMODEL * DMODEL / 4;        // 262144
        const int nF = DMODEL * DFF / 4;           // 1048576
        const int nS = TOKENS * DMODEL / 4;        // 1048576
        F2HJob job;
        job.in[0] = (const float4*)Wq;  job.out[0] = (__half2*)wqH;
        job.in[1] = (const float4*)Wk;  job.out[1] = (__half2*)wkH;
        job.in[2] = (const float4*)Wv;  job.out[2] = (__half2*)wvH;
        job.in[3] = (const float4*)Wo;  job.out[3] = (__half2*)woH;
        job.in[4] = (const float4*)W1;  job.out[4] = (__half2*)w1H;
        job.in[5] = (const float4*)W2;  job.out[5] = (__half2*)w2H;
        job.in[6] = (const float4*)src; job.out[6] = (__half2*)srch;
        int acc = 0;
        int sizes[7] = { nW, nW, nW, nW, nF, nF, nS };
        for (int s = 0; s < 7; s++) { acc += sizes[s]; job.end[s] = acc; }
        f2h_all_kernel<<<(acc + 255) / 256, 256>>>(job);
    }

    // ---- QKV (+RoPE, q pre-scaled) ----
    hgemm<true, false, true, false>
        <<<dim3(DMODEL / 128, TOKENS / 128, 3), 256, GM_SMEM_BYTES>>>(
        TOKENS, DMODEL, DMODEL, srch, wqH, wkH, wvH,
        qh, kh, vh, nullptr, DMODEL, bq, bk, bv, tau);

    // ---- flash attention -> ctx (half) ----
    flash_kernel<<<dim3(SEQ / 128, BATCH * NHEADS), 256, FA_SMEM_BYTES>>>(
        qh, kh, vh, ctxh);

    // ---- output projection -> ao (fp32) ----
    hgemm<false, false, false, true>
        <<<dim3(DMODEL / 128, TOKENS / 128, 1), 256, GM_SMEM_BYTES>>>(
        TOKENS, DMODEL, DMODEL, ctxh, woH, nullptr, nullptr,
        nullptr, nullptr, nullptr, ao, DMODEL, bo, nullptr, nullptr, nullptr);

    // ---- LN1 -> h1 (fp32 + half) ----
    ln_kernel<<<TOKENS, 256>>>(src, ao, g1, be1, h1f, h1h);

    // ---- FFN1 (GELU) -> f1 (half) ----
    hgemm<false, true, true, false>
        <<<dim3(DFF / 128, TOKENS / 128, 1), 256, GM_SMEM_BYTES>>>(
        TOKENS, DFF, DMODEL, h1h, w1H, nullptr, nullptr,
        f1h, nullptr, nullptr, nullptr, DFF, b1, nullptr, nullptr, nullptr);

    // ---- FFN2 -> f2 (fp32) ----
    hgemm<false, false, false, true>
        <<<dim3(DMODEL / 128, TOKENS / 128, 1), 256, GM_SMEM_BYTES>>>(
        TOKENS, DMODEL, DFF, f1h, w2H, nullptr, nullptr,
        nullptr, nullptr, nullptr, f2, DMODEL, b2, nullptr, nullptr, nullptr);

    // ---- LN2 -> out ----
    ln_kernel<<<TOKENS, 256>>>(h1f, f2, g2, be2, out, nullptr);

    (void)in_sizes; (void)n_in; (void)out_size;
}